// round 1
// baseline (speedup 1.0000x reference)
#include <cuda_runtime.h>
#include <math.h>

// ---------------- problem constants ----------------
namespace hk {
constexpr int B  = 2;
constexpr int S  = 2048;
constexpr int D  = 2048;
constexpr int H  = 16;
constexpr int HD = 128;
constexpr int F  = 8192;
constexpr int BS = B * S;                    // 4096 rows
constexpr size_t NBSD = (size_t)BS * D;      // 8,388,608
constexpr size_t NBSF = (size_t)BS * F;      // 33,554,432
}

// ---------------- scratch (static device globals; no allocs allowed) ----------------
__device__ float g_normed[hk::NBSD];
__device__ float g_y     [hk::NBSD];
__device__ float g_xb    [hk::NBSD];
__device__ float g_xc    [hk::NBSD];
__device__ float g_rlin  [hk::NBSD];
__device__ float g_ilin  [hk::NBSD];
__device__ float g_a     [hk::NBSD];
__device__ float g_bx    [hk::NBSD];
__device__ float g_lru   [hk::NBSD];
__device__ float g_resid [hk::NBSD];
__device__ float g_n2    [hk::NBSD];
__device__ float g_G     [hk::NBSF];
__device__ float g_U     [hk::NBSF];

// ---------------- helpers ----------------
__device__ __forceinline__ float gelu_tanh(float x) {
    // jax.nn.gelu default (approximate=True)
    float x3 = x * x * x;
    return 0.5f * x * (1.0f + tanhf(0.7978845608028654f * (x + 0.044715f * x3)));
}

// ---------------- generalized tiled fp32 GEMM ----------------
// C[M,N] = A[M,K] @ B[K,N]; row-major with explicit leading dims.
// Batched via blockIdx.z with element strides sA/sB/sC (aux uses sC).
// EPI: 0 = none, 1 = tanh-gelu, 2 = add aux (same layout as C).
template<int EPI>
__global__ void __launch_bounds__(256)
gemm_tpl(const float* __restrict__ A, const float* __restrict__ Bm,
         float* __restrict__ C, const float* __restrict__ aux,
         int M, int N, int K, int lda, int ldb, int ldc,
         long long sA, long long sB, long long sC)
{
    __shared__ float As[8][128];
    __shared__ float Bs[8][128];

    A  += (size_t)blockIdx.z * sA;
    Bm += (size_t)blockIdx.z * sB;
    C  += (size_t)blockIdx.z * sC;
    if (EPI == 2) aux += (size_t)blockIdx.z * sC;

    const int tid  = threadIdx.x;
    const int row0 = blockIdx.y * 128;
    const int col0 = blockIdx.x * 128;

    const int aRow = tid >> 1;          // 0..127
    const int aCol = (tid & 1) * 4;     // 0 or 4
    const int bRow = tid >> 5;          // 0..7
    const int bCol = (tid & 31) * 4;    // 0..124

    const int ty = tid >> 4;            // 0..15 -> row group
    const int tx = tid & 15;            // 0..15 -> col group

    float acc[8][8];
    #pragma unroll
    for (int i = 0; i < 8; i++)
        #pragma unroll
        for (int j = 0; j < 8; j++) acc[i][j] = 0.0f;

    for (int k0 = 0; k0 < K; k0 += 8) {
        float4 av = *reinterpret_cast<const float4*>(
            &A[(size_t)(row0 + aRow) * lda + (k0 + aCol)]);
        float4 bv = *reinterpret_cast<const float4*>(
            &Bm[(size_t)(k0 + bRow) * ldb + (col0 + bCol)]);
        As[aCol + 0][aRow] = av.x;
        As[aCol + 1][aRow] = av.y;
        As[aCol + 2][aRow] = av.z;
        As[aCol + 3][aRow] = av.w;
        *reinterpret_cast<float4*>(&Bs[bRow][bCol]) = bv;
        __syncthreads();

        #pragma unroll
        for (int k = 0; k < 8; k++) {
            float ra[8], rb[8];
            #pragma unroll
            for (int i = 0; i < 8; i++) ra[i] = As[k][ty * 8 + i];
            #pragma unroll
            for (int j = 0; j < 8; j++) rb[j] = Bs[k][tx * 8 + j];
            #pragma unroll
            for (int i = 0; i < 8; i++)
                #pragma unroll
                for (int j = 0; j < 8; j++)
                    acc[i][j] = fmaf(ra[i], rb[j], acc[i][j]);
        }
        __syncthreads();
    }

    #pragma unroll
    for (int i = 0; i < 8; i++) {
        int r = row0 + ty * 8 + i;
        #pragma unroll
        for (int j = 0; j < 8; j += 4) {
            int c = col0 + tx * 8 + j;
            float4 v;
            float* vp = &v.x;
            #pragma unroll
            for (int q = 0; q < 4; q++) {
                float t = acc[i][j + q];
                if (EPI == 1) t = gelu_tanh(t);
                if (EPI == 2) t += aux[(size_t)r * ldc + (c + q)];
                vp[q] = t;
            }
            *reinterpret_cast<float4*>(&C[(size_t)r * ldc + c]) = v;
        }
    }
}

// ---------------- rmsnorm (one block per row, D=2048) ----------------
__global__ void rmsnorm_kernel(const float* __restrict__ x,
                               const float* __restrict__ w,
                               float* __restrict__ out)
{
    using namespace hk;
    const int row = blockIdx.x;
    const float* xr = x + (size_t)row * D;
    float ss = 0.0f;
    for (int d = threadIdx.x; d < D; d += 256) { float v = xr[d]; ss += v * v; }

    __shared__ float red[8];
    #pragma unroll
    for (int o = 16; o > 0; o >>= 1) ss += __shfl_down_sync(0xffffffffu, ss, o);
    if ((threadIdx.x & 31) == 0) red[threadIdx.x >> 5] = ss;
    __syncthreads();
    if (threadIdx.x < 8) {
        float v = red[threadIdx.x];
        #pragma unroll
        for (int o = 4; o > 0; o >>= 1) v += __shfl_down_sync(0xffu, v, o);
        if (threadIdx.x == 0) red[0] = v;
    }
    __syncthreads();
    const float scale = rsqrtf(red[0] / (float)D + 1e-6f);
    float* orow = out + (size_t)row * D;
    for (int d = threadIdx.x; d < D; d += 256) orow[d] = xr[d] * scale * w[d];
}

// ---------------- causal depthwise conv, kernel 4 ----------------
__global__ void conv_kernel(const float* __restrict__ xb,
                            const float* __restrict__ cw,
                            const float* __restrict__ cb,
                            float* __restrict__ xc)
{
    using namespace hk;
    size_t idx = (size_t)blockIdx.x * blockDim.x + threadIdx.x;
    if (idx >= NBSD) return;
    int d = (int)(idx % D);
    int s = (int)((idx / D) % S);
    float acc = cb[d];
    #pragma unroll
    for (int k = 0; k < 4; k++) {
        int ss = s + k - 3;
        if (ss >= 0) acc = fmaf(cw[k * D + d], xb[idx + (size_t)(k - 3) * D], acc);
    }
    xc[idx] = acc;
}

// ---------------- RG-LRU gate pointwise ----------------
__global__ void gate_kernel(const float* __restrict__ rlin,
                            const float* __restrict__ ilin,
                            const float* __restrict__ xc,
                            const float* __restrict__ ab,   // agate_b flat [D]
                            const float* __restrict__ ib,   // igate_b flat [D]
                            const float* __restrict__ apar, // a_param [D]
                            float* __restrict__ ga, float* __restrict__ gb)
{
    using namespace hk;
    size_t idx = (size_t)blockIdx.x * blockDim.x + threadIdx.x;
    if (idx >= NBSD) return;
    int d = (int)(idx % D);
    float sp = log1pf(expf(-apar[d]));               // softplus(-a_param)
    float r  = 1.0f / (1.0f + expf(-(rlin[idx] + ab[d])));
    float ii = 1.0f / (1.0f + expf(-(ilin[idx] + ib[d])));
    float la = -8.0f * r * sp;                        // C_RGLRU = 8
    ga[idx]  = expf(la);
    float mult = sqrtf(fmaxf(1.0f - expf(2.0f * la), 0.0f));
    gb[idx]  = mult * ii * xc[idx];
}

// ---------------- linear scan h = a*h + b over S ----------------
__global__ void scan_kernel(const float* __restrict__ a,
                            const float* __restrict__ bx,
                            const float* __restrict__ h0,
                            float* __restrict__ lru,
                            float* __restrict__ hlast)
{
    using namespace hk;
    int ch = blockIdx.x * blockDim.x + threadIdx.x;   // 0 .. B*D-1
    if (ch >= B * D) return;
    int b = ch / D, d = ch % D;
    float h = h0[ch];
    size_t base = (size_t)b * S * D + d;
    for (int s = 0; s < S; s++) {
        size_t idx = base + (size_t)s * D;
        h = fmaf(a[idx], h, bx[idx]);
        lru[idx] = h;
    }
    if (hlast) hlast[ch] = h;
}

// ---------------- elementwise multiply (in place into dst) ----------------
__global__ void mul_kernel(float* __restrict__ dst, const float* __restrict__ src, size_t n)
{
    size_t idx = (size_t)blockIdx.x * blockDim.x + threadIdx.x;
    if (idx < n) dst[idx] *= src[idx];
}

// ---------------- launch ----------------
extern "C" void kernel_launch(void* const* d_in, const int* in_sizes, int n_in,
                              void* d_out, int out_size)
{
    using namespace hk;
    const float* x    = (const float*)d_in[0];
    const float* h0   = (const float*)d_in[1];
    const float* r1w  = (const float*)d_in[2];
    const float* r2w  = (const float*)d_in[3];
    const float* Wx   = (const float*)d_in[4];
    const float* Wy   = (const float*)d_in[5];
    const float* cw   = (const float*)d_in[6];
    const float* cb   = (const float*)d_in[7];
    const float* apar = (const float*)d_in[8];
    const float* igw  = (const float*)d_in[9];
    const float* igb  = (const float*)d_in[10];
    const float* agw  = (const float*)d_in[11];
    const float* agb  = (const float*)d_in[12];
    const float* Wout = (const float*)d_in[13];
    const float* Wg   = (const float*)d_in[14];
    const float* Wu   = (const float*)d_in[15];
    const float* Wd   = (const float*)d_in[16];
    float* out = (float*)d_out;

    float *normed, *y, *xb, *xc, *rlin, *ilin, *ga, *gb, *lru, *resid, *n2, *G, *U;
    cudaGetSymbolAddress((void**)&normed, g_normed);
    cudaGetSymbolAddress((void**)&y,      g_y);
    cudaGetSymbolAddress((void**)&xb,     g_xb);
    cudaGetSymbolAddress((void**)&xc,     g_xc);
    cudaGetSymbolAddress((void**)&rlin,   g_rlin);
    cudaGetSymbolAddress((void**)&ilin,   g_ilin);
    cudaGetSymbolAddress((void**)&ga,     g_a);
    cudaGetSymbolAddress((void**)&gb,     g_bx);
    cudaGetSymbolAddress((void**)&lru,    g_lru);
    cudaGetSymbolAddress((void**)&resid,  g_resid);
    cudaGetSymbolAddress((void**)&n2,     g_n2);
    cudaGetSymbolAddress((void**)&G,      g_G);
    cudaGetSymbolAddress((void**)&U,      g_U);

    const int EW = 256;
    const size_t nbsd_blocks = (NBSD + EW - 1) / EW;
    const size_t nbsf_blocks = (NBSF + EW - 1) / EW;

    // h_last goes after the main output if the harness flattened the tuple.
    float* hlast = (out_size >= (int)(NBSD + (size_t)B * D)) ? (out + NBSD) : nullptr;

    // 1) pre-norm
    rmsnorm_kernel<<<BS, 256>>>(x, r1w, normed);

    // 2) y = gelu(normed @ W_y) ; xb = normed @ W_x
    dim3 gDD(D / 128, BS / 128, 1);
    gemm_tpl<1><<<gDD, 256>>>(normed, Wy, y,  nullptr, BS, D, D, D, D, D, 0, 0, 0);
    gemm_tpl<0><<<gDD, 256>>>(normed, Wx, xb, nullptr, BS, D, D, D, D, D, 0, 0, 0);

    // 3) causal depthwise conv
    conv_kernel<<<(unsigned)nbsd_blocks, EW>>>(xb, cw, cb, xc);

    // 4) per-head gate GEMMs (batched over H via grid.z)
    dim3 gGate(HD / 128, BS / 128, H);
    gemm_tpl<0><<<gGate, 256>>>(xc, agw, rlin, nullptr, BS, HD, HD, D, HD, D,
                                HD, (long long)HD * HD, HD);
    gemm_tpl<0><<<gGate, 256>>>(xc, igw, ilin, nullptr, BS, HD, HD, D, HD, D,
                                HD, (long long)HD * HD, HD);

    // 5) gate pointwise -> a, bx
    gate_kernel<<<(unsigned)nbsd_blocks, EW>>>(rlin, ilin, xc, agb, igb, apar, ga, gb);

    // 6) linear recurrence
    scan_kernel<<<(B * D + 255) / 256, 256>>>(ga, gb, h0, lru, hlast);

    // 7) z = y * lru (in place into y)
    mul_kernel<<<(unsigned)nbsd_blocks, EW>>>(y, lru, NBSD);

    // 8) residual = z @ W_out + x
    gemm_tpl<2><<<gDD, 256>>>(y, Wout, resid, x, BS, D, D, D, D, D, 0, 0, 0);

    // 9) second norm
    rmsnorm_kernel<<<BS, 256>>>(resid, r2w, n2);

    // 10) MLP: G = gelu(n2 @ W_gate), U = n2 @ W_up, G *= U
    dim3 gDF(F / 128, BS / 128, 1);
    gemm_tpl<1><<<gDF, 256>>>(n2, Wg, G, nullptr, BS, F, D, D, F, F, 0, 0, 0);
    gemm_tpl<0><<<gDF, 256>>>(n2, Wu, U, nullptr, BS, F, D, D, F, F, 0, 0, 0);
    mul_kernel<<<(unsigned)nbsf_blocks, EW>>>(G, U, NBSF);

    // 11) out = G @ W_down + residual
    gemm_tpl<2><<<gDD, 256>>>(G, Wd, out, resid, BS, D, F, F, D, D, 0, 0, 0);
}

// round 3
// speedup vs baseline: 2.2966x; 2.2966x over previous
#include <cuda_runtime.h>
#include <cuda_bf16.h>
#include <math.h>
#include <stdint.h>

// ---------------- problem constants ----------------
namespace hk {
constexpr int B  = 2;
constexpr int S  = 2048;
constexpr int D  = 2048;
constexpr int H  = 16;
constexpr int HD = 128;
constexpr int F  = 8192;
constexpr int BS = B * S;                     // 4096 rows
constexpr size_t NBSD = (size_t)BS * D;       // 8,388,608
constexpr size_t NBSF = (size_t)BS * F;       // 33,554,432
constexpr size_t NDD  = (size_t)D * D;
constexpr size_t NDF  = (size_t)D * F;
}

// ---------------- scratch: fp32 intermediates ----------------
__device__ float g_y     [hk::NBSD];
__device__ float g_xb    [hk::NBSD];
__device__ float g_xc    [hk::NBSD];
__device__ float g_rlin  [hk::NBSD];
__device__ float g_ilin  [hk::NBSD];
__device__ float g_a     [hk::NBSD];
__device__ float g_bx    [hk::NBSD];
__device__ float g_lru   [hk::NBSD];
__device__ float g_resid [hk::NBSD];
__device__ float g_G     [hk::NBSF];
__device__ float g_U     [hk::NBSF];

// ---------------- scratch: bf16 hi/lo split activations ----------------
__device__ __nv_bfloat16 g_nH [hk::NBSD], g_nL [hk::NBSD];
__device__ __nv_bfloat16 g_zH [hk::NBSD], g_zL [hk::NBSD];
__device__ __nv_bfloat16 g_n2H[hk::NBSD], g_n2L[hk::NBSD];
__device__ __nv_bfloat16 g_guH[hk::NBSF], g_guL[hk::NBSF];

// ---------------- scratch: bf16 hi/lo split, transposed weights [N,K] ----------------
__device__ __nv_bfloat16 g_WyH[hk::NDD], g_WyL[hk::NDD];
__device__ __nv_bfloat16 g_WxH[hk::NDD], g_WxL[hk::NDD];
__device__ __nv_bfloat16 g_WoH[hk::NDD], g_WoL[hk::NDD];
__device__ __nv_bfloat16 g_WgH[hk::NDF], g_WgL[hk::NDF];
__device__ __nv_bfloat16 g_WuH[hk::NDF], g_WuL[hk::NDF];
__device__ __nv_bfloat16 g_WdH[hk::NDF], g_WdL[hk::NDF];

// ---------------- helpers ----------------
__device__ __forceinline__ float gelu_tanh(float x) {
    float x3 = x * x * x;
    return 0.5f * x * (1.0f + tanhf(0.7978845608028654f * (x + 0.044715f * x3)));
}

__device__ __forceinline__ uint32_t s2u(const void* p) {
    uint32_t a;
    asm("{ .reg .u64 t; cvta.to.shared.u64 t, %1; cvt.u32.u64 %0, t; }" : "=r"(a) : "l"(p));
    return a;
}

__device__ __forceinline__ void cpa16(uint32_t dst, const void* src) {
    asm volatile("cp.async.cg.shared.global [%0], [%1], 16;" :: "r"(dst), "l"(src));
}

__device__ __forceinline__ void ldmx4(uint32_t* r, uint32_t a) {
    asm volatile("ldmatrix.sync.aligned.m8n8.x4.shared.b16 {%0,%1,%2,%3}, [%4];"
                 : "=r"(r[0]), "=r"(r[1]), "=r"(r[2]), "=r"(r[3]) : "r"(a));
}

__device__ __forceinline__ void ldmx2(uint32_t* r, uint32_t a) {
    asm volatile("ldmatrix.sync.aligned.m8n8.x2.shared.b16 {%0,%1}, [%2];"
                 : "=r"(r[0]), "=r"(r[1]) : "r"(a));
}

__device__ __forceinline__ void mma16816(float* c, const uint32_t* a, const uint32_t* b) {
    asm volatile(
        "mma.sync.aligned.m16n8k16.row.col.f32.bf16.bf16.f32 "
        "{%0,%1,%2,%3}, {%4,%5,%6,%7}, {%8,%9}, {%0,%1,%2,%3};"
        : "+f"(c[0]), "+f"(c[1]), "+f"(c[2]), "+f"(c[3])
        : "r"(a[0]), "r"(a[1]), "r"(a[2]), "r"(a[3]), "r"(b[0]), "r"(b[1]));
}

__device__ __forceinline__ void split2(float v, __nv_bfloat16& h, __nv_bfloat16& l) {
    h = __float2bfloat16(v);
    l = __float2bfloat16(v - __bfloat162float(h));
}

// =====================================================================
// bf16x3 tensor-core GEMM via mma.sync (base sm_103-legal):
//   C[M,N](fp32) = (Ah+Al)[M,K] @ (Bh+Bl)[N,K]^T   (AlBl dropped)
// CTA tile 128x128, BK=32, 8 warps (2x4), 3-stage cp.async pipeline.
// Smem rows padded to 40 bf16 (80 B) -> conflict-free ldmatrix.
// EPI: 0 none, 1 tanh-gelu, 2 add aux.
// =====================================================================
constexpr int GM_LDK   = 40;                    // padded row length (bf16 elems)
constexpr int GM_MAT   = 128 * GM_LDK * 2;      // 10240 B per matrix tile
constexpr int GM_STAGE = 4 * GM_MAT;            // Ah, Al, Bh, Bl = 40960 B
constexpr int GM_SMEM  = 3 * GM_STAGE;          // 122880 B

template<int EPI>
__global__ void __launch_bounds__(256, 1)
gemm_mma(const __nv_bfloat16* __restrict__ Ah, const __nv_bfloat16* __restrict__ Al,
         const __nv_bfloat16* __restrict__ Bh, const __nv_bfloat16* __restrict__ Bl,
         float* __restrict__ C, const float* __restrict__ aux,
         int N, int K)
{
    extern __shared__ __align__(128) char smem[];
    const uint32_t sm0 = s2u(smem);

    const int tid  = threadIdx.x;
    const int lane = tid & 31;
    const int wid  = tid >> 5;
    const int wm   = wid >> 2;        // 0..1  -> 64-row slab
    const int wn   = wid & 3;         // 0..3  -> 32-col slab
    const int row0 = blockIdx.y * 128;
    const int col0 = blockIdx.x * 128;
    const int KB   = K >> 5;          // BK = 32

    // ldmatrix byte offsets within a matrix tile
    uint32_t aoff[4], boff[4];
    #pragma unroll
    for (int im = 0; im < 4; im++)
        aoff[im] = (uint32_t)(((wm * 64 + im * 16 + (lane & 15)) * GM_LDK
                               + (lane >> 4) * 8) * 2);
    #pragma unroll
    for (int in = 0; in < 4; in++)
        boff[in] = (uint32_t)(((wn * 32 + in * 8 + (lane & 7)) * GM_LDK
                               + ((lane >> 3) & 1) * 8) * 2);

    float acc[4][4][4];
    #pragma unroll
    for (int im = 0; im < 4; im++)
        #pragma unroll
        for (int in = 0; in < 4; in++)
            #pragma unroll
            for (int q = 0; q < 4; q++) acc[im][in][q] = 0.0f;

    auto load_stage = [&](int kb, int s) {
        const uint32_t sb = sm0 + (uint32_t)s * GM_STAGE;
        const size_t k0 = (size_t)kb * 32;
        #pragma unroll
        for (int i = 0; i < 2; i++) {
            int id = tid + i * 256;          // 0..511
            int r = id >> 2, c = id & 3;
            uint32_t so = (uint32_t)((r * GM_LDK + c * 8) * 2);
            size_t gA = (size_t)(row0 + r) * K + k0 + (size_t)c * 8;
            size_t gB = (size_t)(col0 + r) * K + k0 + (size_t)c * 8;
            cpa16(sb + so,                  Ah + gA);
            cpa16(sb + GM_MAT + so,         Al + gA);
            cpa16(sb + 2 * GM_MAT + so,     Bh + gB);
            cpa16(sb + 3 * GM_MAT + so,     Bl + gB);
        }
        asm volatile("cp.async.commit_group;" ::: "memory");
    };

    auto compute_stage = [&](int s) {
        const uint32_t sb = sm0 + (uint32_t)s * GM_STAGE;
        #pragma unroll
        for (int kk = 0; kk < 2; kk++) {
            uint32_t ahf[4][4], alf[4][4], bhf[4][2], blf[4][2];
            #pragma unroll
            for (int im = 0; im < 4; im++) {
                ldmx4(ahf[im], sb + aoff[im] + kk * 32);
                ldmx4(alf[im], sb + GM_MAT + aoff[im] + kk * 32);
            }
            #pragma unroll
            for (int in = 0; in < 4; in++) {
                ldmx2(bhf[in], sb + 2 * GM_MAT + boff[in] + kk * 32);
                ldmx2(blf[in], sb + 3 * GM_MAT + boff[in] + kk * 32);
            }
            #pragma unroll
            for (int im = 0; im < 4; im++)
                #pragma unroll
                for (int in = 0; in < 4; in++)
                    mma16816(acc[im][in], ahf[im], bhf[in]);
            #pragma unroll
            for (int im = 0; im < 4; im++)
                #pragma unroll
                for (int in = 0; in < 4; in++)
                    mma16816(acc[im][in], ahf[im], blf[in]);
            #pragma unroll
            for (int im = 0; im < 4; im++)
                #pragma unroll
                for (int in = 0; in < 4; in++)
                    mma16816(acc[im][in], alf[im], bhf[in]);
        }
    };

    load_stage(0, 0);
    load_stage(1, 1);
    for (int kb = 0; kb < KB; kb++) {
        if (kb + 2 < KB) {
            load_stage(kb + 2, (kb + 2) % 3);
            asm volatile("cp.async.wait_group 2;" ::: "memory");
        } else {
            asm volatile("cp.async.wait_group 0;" ::: "memory");
        }
        __syncthreads();
        compute_stage(kb % 3);
        __syncthreads();
    }

    // ---- epilogue ----
    const int gid = lane >> 2, t4 = lane & 3;
    #pragma unroll
    for (int im = 0; im < 4; im++) {
        #pragma unroll
        for (int in = 0; in < 4; in++) {
            int r = row0 + wm * 64 + im * 16 + gid;
            int c = col0 + wn * 32 + in * 8 + t4 * 2;
            #pragma unroll
            for (int half = 0; half < 2; half++) {
                int rr = r + half * 8;
                float v0 = acc[im][in][half * 2 + 0];
                float v1 = acc[im][in][half * 2 + 1];
                if (EPI == 1) { v0 = gelu_tanh(v0); v1 = gelu_tanh(v1); }
                if (EPI == 2) {
                    float2 a2 = *reinterpret_cast<const float2*>(
                        aux + (size_t)rr * N + c);
                    v0 += a2.x; v1 += a2.y;
                }
                float2 o; o.x = v0; o.y = v1;
                *reinterpret_cast<float2*>(C + (size_t)rr * N + c) = o;
            }
        }
    }
}

// =====================================================================
// transpose + hi/lo split: W[K,N] fp32 -> hi/lo[N,K] bf16
// =====================================================================
__global__ void trans_split(const float* __restrict__ W,
                            __nv_bfloat16* __restrict__ hi, __nv_bfloat16* __restrict__ lo,
                            int K, int N)
{
    __shared__ float t[32][33];
    int n0 = blockIdx.x * 32, k0 = blockIdx.y * 32;
    int tx = threadIdx.x, ty = threadIdx.y;   // 32 x 8
    #pragma unroll
    for (int i = 0; i < 32; i += 8)
        t[ty + i][tx] = W[(size_t)(k0 + ty + i) * N + (n0 + tx)];
    __syncthreads();
    #pragma unroll
    for (int i = 0; i < 32; i += 8) {
        float v = t[tx][ty + i];
        size_t o = (size_t)(n0 + ty + i) * K + (k0 + tx);
        __nv_bfloat16 h, l; split2(v, h, l);
        hi[o] = h; lo[o] = l;
    }
}

// ---------------- rmsnorm with hi/lo split output ----------------
__global__ void rmsnorm_split(const float* __restrict__ x, const float* __restrict__ w,
                              __nv_bfloat16* __restrict__ hi, __nv_bfloat16* __restrict__ lo)
{
    using namespace hk;
    const int row = blockIdx.x;
    const float* xr = x + (size_t)row * D;
    float ss = 0.0f;
    for (int d = threadIdx.x; d < D; d += 256) { float v = xr[d]; ss += v * v; }
    __shared__ float red[8];
    #pragma unroll
    for (int o = 16; o > 0; o >>= 1) ss += __shfl_down_sync(0xffffffffu, ss, o);
    if ((threadIdx.x & 31) == 0) red[threadIdx.x >> 5] = ss;
    __syncthreads();
    if (threadIdx.x < 8) {
        float v = red[threadIdx.x];
        #pragma unroll
        for (int o = 4; o > 0; o >>= 1) v += __shfl_down_sync(0xffu, v, o);
        if (threadIdx.x == 0) red[0] = v;
    }
    __syncthreads();
    const float scale = rsqrtf(red[0] / (float)D + 1e-6f);
    size_t base = (size_t)row * D;
    for (int d = threadIdx.x; d < D; d += 256) {
        float v = xr[d] * scale * w[d];
        __nv_bfloat16 h, l; split2(v, h, l);
        hi[base + d] = h; lo[base + d] = l;
    }
}

// ---------------- causal depthwise conv, kernel 4 ----------------
__global__ void conv_kernel(const float* __restrict__ xb, const float* __restrict__ cw,
                            const float* __restrict__ cb, float* __restrict__ xc)
{
    using namespace hk;
    size_t idx = (size_t)blockIdx.x * blockDim.x + threadIdx.x;
    if (idx >= NBSD) return;
    int d = (int)(idx % D);
    int s = (int)((idx / D) % S);
    float acc = cb[d];
    #pragma unroll
    for (int k = 0; k < 4; k++) {
        int ss = s + k - 3;
        if (ss >= 0) acc = fmaf(cw[k * D + d], xb[idx + (size_t)(k - 3) * D], acc);
    }
    xc[idx] = acc;
}

// ---------------- SIMT fp32 GEMM (gates only; small) ----------------
__global__ void __launch_bounds__(256)
gemm_tpl(const float* __restrict__ A, const float* __restrict__ Bm,
         float* __restrict__ C,
         int M, int N, int K, int lda, int ldb, int ldc,
         long long sA, long long sB, long long sC)
{
    __shared__ float As[8][128];
    __shared__ float Bs[8][128];
    A  += (size_t)blockIdx.z * sA;
    Bm += (size_t)blockIdx.z * sB;
    C  += (size_t)blockIdx.z * sC;
    const int tid  = threadIdx.x;
    const int row0 = blockIdx.y * 128;
    const int col0 = blockIdx.x * 128;
    const int aRow = tid >> 1, aCol = (tid & 1) * 4;
    const int bRow = tid >> 5, bCol = (tid & 31) * 4;
    const int ty = tid >> 4, tx = tid & 15;
    float acc[8][8];
    #pragma unroll
    for (int i = 0; i < 8; i++)
        #pragma unroll
        for (int j = 0; j < 8; j++) acc[i][j] = 0.0f;
    for (int k0 = 0; k0 < K; k0 += 8) {
        float4 av = *reinterpret_cast<const float4*>(&A[(size_t)(row0 + aRow) * lda + (k0 + aCol)]);
        float4 bv = *reinterpret_cast<const float4*>(&Bm[(size_t)(k0 + bRow) * ldb + (col0 + bCol)]);
        As[aCol + 0][aRow] = av.x; As[aCol + 1][aRow] = av.y;
        As[aCol + 2][aRow] = av.z; As[aCol + 3][aRow] = av.w;
        *reinterpret_cast<float4*>(&Bs[bRow][bCol]) = bv;
        __syncthreads();
        #pragma unroll
        for (int k = 0; k < 8; k++) {
            float ra[8], rb[8];
            #pragma unroll
            for (int i = 0; i < 8; i++) ra[i] = As[k][ty * 8 + i];
            #pragma unroll
            for (int j = 0; j < 8; j++) rb[j] = Bs[k][tx * 8 + j];
            #pragma unroll
            for (int i = 0; i < 8; i++)
                #pragma unroll
                for (int j = 0; j < 8; j++)
                    acc[i][j] = fmaf(ra[i], rb[j], acc[i][j]);
        }
        __syncthreads();
    }
    #pragma unroll
    for (int i = 0; i < 8; i++) {
        int r = row0 + ty * 8 + i;
        #pragma unroll
        for (int j = 0; j < 8; j += 4) {
            int c = col0 + tx * 8 + j;
            float4 v;
            v.x = acc[i][j]; v.y = acc[i][j + 1]; v.z = acc[i][j + 2]; v.w = acc[i][j + 3];
            *reinterpret_cast<float4*>(&C[(size_t)r * ldc + c]) = v;
        }
    }
}

// ---------------- RG-LRU gate pointwise ----------------
__global__ void gate_kernel(const float* __restrict__ rlin, const float* __restrict__ ilin,
                            const float* __restrict__ xc, const float* __restrict__ ab,
                            const float* __restrict__ ib, const float* __restrict__ apar,
                            float* __restrict__ ga, float* __restrict__ gb)
{
    using namespace hk;
    size_t idx = (size_t)blockIdx.x * blockDim.x + threadIdx.x;
    if (idx >= NBSD) return;
    int d = (int)(idx % D);
    float sp = log1pf(expf(-apar[d]));
    float r  = 1.0f / (1.0f + expf(-(rlin[idx] + ab[d])));
    float ii = 1.0f / (1.0f + expf(-(ilin[idx] + ib[d])));
    float la = -8.0f * r * sp;
    ga[idx]  = expf(la);
    float mult = sqrtf(fmaxf(1.0f - expf(2.0f * la), 0.0f));
    gb[idx]  = mult * ii * xc[idx];
}

// ---------------- linear scan ----------------
__global__ void scan_kernel(const float* __restrict__ a, const float* __restrict__ bx,
                            const float* __restrict__ h0, float* __restrict__ lru,
                            float* __restrict__ hlast)
{
    using namespace hk;
    int ch = blockIdx.x * blockDim.x + threadIdx.x;
    if (ch >= B * D) return;
    int b = ch / D, d = ch % D;
    float h = h0[ch];
    size_t base = (size_t)b * S * D + d;
    for (int s = 0; s < S; s++) {
        size_t idx = base + (size_t)s * D;
        h = fmaf(a[idx], h, bx[idx]);
        lru[idx] = h;
    }
    if (hlast) hlast[ch] = h;
}

// ---------------- elementwise multiply with hi/lo split output ----------------
__global__ void mul_split(const float* __restrict__ a, const float* __restrict__ b,
                          __nv_bfloat16* __restrict__ hi, __nv_bfloat16* __restrict__ lo,
                          size_t n)
{
    size_t idx = (size_t)blockIdx.x * blockDim.x + threadIdx.x;
    if (idx < n) {
        float v = a[idx] * b[idx];
        __nv_bfloat16 h, l; split2(v, h, l);
        hi[idx] = h; lo[idx] = l;
    }
}

// ---------------- launch ----------------
extern "C" void kernel_launch(void* const* d_in, const int* in_sizes, int n_in,
                              void* d_out, int out_size)
{
    using namespace hk;
    const float* x    = (const float*)d_in[0];
    const float* h0   = (const float*)d_in[1];
    const float* r1w  = (const float*)d_in[2];
    const float* r2w  = (const float*)d_in[3];
    const float* Wx   = (const float*)d_in[4];
    const float* Wy   = (const float*)d_in[5];
    const float* cw   = (const float*)d_in[6];
    const float* cb   = (const float*)d_in[7];
    const float* apar = (const float*)d_in[8];
    const float* igw  = (const float*)d_in[9];
    const float* igb  = (const float*)d_in[10];
    const float* agw  = (const float*)d_in[11];
    const float* agb  = (const float*)d_in[12];
    const float* Wout = (const float*)d_in[13];
    const float* Wg   = (const float*)d_in[14];
    const float* Wu   = (const float*)d_in[15];
    const float* Wd   = (const float*)d_in[16];
    float* out = (float*)d_out;

    float *y, *xb, *xc, *rlin, *ilin, *ga, *gb, *lru, *resid, *G, *U;
    cudaGetSymbolAddress((void**)&y,     g_y);
    cudaGetSymbolAddress((void**)&xb,    g_xb);
    cudaGetSymbolAddress((void**)&xc,    g_xc);
    cudaGetSymbolAddress((void**)&rlin,  g_rlin);
    cudaGetSymbolAddress((void**)&ilin,  g_ilin);
    cudaGetSymbolAddress((void**)&ga,    g_a);
    cudaGetSymbolAddress((void**)&gb,    g_bx);
    cudaGetSymbolAddress((void**)&lru,   g_lru);
    cudaGetSymbolAddress((void**)&resid, g_resid);
    cudaGetSymbolAddress((void**)&G,     g_G);
    cudaGetSymbolAddress((void**)&U,     g_U);

    __nv_bfloat16 *nH,*nL,*zH,*zL,*n2H,*n2L,*guH,*guL;
    __nv_bfloat16 *WyH,*WyL,*WxH,*WxL,*WoH,*WoL,*WgH,*WgL,*WuH,*WuL,*WdH,*WdL;
    cudaGetSymbolAddress((void**)&nH,  g_nH);  cudaGetSymbolAddress((void**)&nL,  g_nL);
    cudaGetSymbolAddress((void**)&zH,  g_zH);  cudaGetSymbolAddress((void**)&zL,  g_zL);
    cudaGetSymbolAddress((void**)&n2H, g_n2H); cudaGetSymbolAddress((void**)&n2L, g_n2L);
    cudaGetSymbolAddress((void**)&guH, g_guH); cudaGetSymbolAddress((void**)&guL, g_guL);
    cudaGetSymbolAddress((void**)&WyH, g_WyH); cudaGetSymbolAddress((void**)&WyL, g_WyL);
    cudaGetSymbolAddress((void**)&WxH, g_WxH); cudaGetSymbolAddress((void**)&WxL, g_WxL);
    cudaGetSymbolAddress((void**)&WoH, g_WoH); cudaGetSymbolAddress((void**)&WoL, g_WoL);
    cudaGetSymbolAddress((void**)&WgH, g_WgH); cudaGetSymbolAddress((void**)&WgL, g_WgL);
    cudaGetSymbolAddress((void**)&WuH, g_WuH); cudaGetSymbolAddress((void**)&WuL, g_WuL);
    cudaGetSymbolAddress((void**)&WdH, g_WdH); cudaGetSymbolAddress((void**)&WdL, g_WdL);

    cudaFuncSetAttribute(gemm_mma<0>, cudaFuncAttributeMaxDynamicSharedMemorySize, GM_SMEM);
    cudaFuncSetAttribute(gemm_mma<1>, cudaFuncAttributeMaxDynamicSharedMemorySize, GM_SMEM);
    cudaFuncSetAttribute(gemm_mma<2>, cudaFuncAttributeMaxDynamicSharedMemorySize, GM_SMEM);

    const int EW = 256;
    const size_t nbsd_blocks = (NBSD + EW - 1) / EW;
    const size_t nbsf_blocks = (NBSF + EW - 1) / EW;
    float* hlast = (out_size >= (int)(NBSD + (size_t)B * D)) ? (out + NBSD) : nullptr;

    // ---- weight transpose + split (every call; deterministic) ----
    dim3 tb(32, 8);
    trans_split<<<dim3(D / 32, D / 32), tb>>>(Wy,   WyH, WyL, D, D);
    trans_split<<<dim3(D / 32, D / 32), tb>>>(Wx,   WxH, WxL, D, D);
    trans_split<<<dim3(D / 32, D / 32), tb>>>(Wout, WoH, WoL, D, D);
    trans_split<<<dim3(F / 32, D / 32), tb>>>(Wg,   WgH, WgL, D, F);
    trans_split<<<dim3(F / 32, D / 32), tb>>>(Wu,   WuH, WuL, D, F);
    trans_split<<<dim3(D / 32, F / 32), tb>>>(Wd,   WdH, WdL, F, D);

    // ---- temporal pre-norm (split output) ----
    rmsnorm_split<<<BS, 256>>>(x, r1w, nH, nL);

    // ---- y = gelu(normed @ W_y); xb = normed @ W_x ----
    dim3 gDD(D / 128, BS / 128);
    gemm_mma<1><<<gDD, 256, GM_SMEM>>>(nH, nL, WyH, WyL, y,  nullptr, D, D);
    gemm_mma<0><<<gDD, 256, GM_SMEM>>>(nH, nL, WxH, WxL, xb, nullptr, D, D);

    // ---- causal conv ----
    conv_kernel<<<(unsigned)nbsd_blocks, EW>>>(xb, cw, cb, xc);

    // ---- gate GEMMs (SIMT fp32; tiny) ----
    dim3 gGate(HD / 128, BS / 128, H);
    gemm_tpl<<<gGate, 256>>>(xc, agw, rlin, BS, HD, HD, D, HD, D,
                             HD, (long long)HD * HD, HD);
    gemm_tpl<<<gGate, 256>>>(xc, igw, ilin, BS, HD, HD, D, HD, D,
                             HD, (long long)HD * HD, HD);

    // ---- gate pointwise -> a, bx ----
    gate_kernel<<<(unsigned)nbsd_blocks, EW>>>(rlin, ilin, xc, agb, igb, apar, ga, gb);

    // ---- linear recurrence ----
    scan_kernel<<<(B * D + 255) / 256, 256>>>(ga, gb, h0, lru, hlast);

    // ---- z = y * lru (split) ----
    mul_split<<<(unsigned)nbsd_blocks, EW>>>(y, lru, zH, zL, NBSD);

    // ---- residual = z @ W_out + x ----
    gemm_mma<2><<<gDD, 256, GM_SMEM>>>(zH, zL, WoH, WoL, resid, x, D, D);

    // ---- second norm (split) ----
    rmsnorm_split<<<BS, 256>>>(resid, r2w, n2H, n2L);

    // ---- MLP ----
    dim3 gDF(F / 128, BS / 128);
    gemm_mma<1><<<gDF, 256, GM_SMEM>>>(n2H, n2L, WgH, WgL, G, nullptr, F, D);
    gemm_mma<0><<<gDF, 256, GM_SMEM>>>(n2H, n2L, WuH, WuL, U, nullptr, F, D);
    mul_split<<<(unsigned)nbsf_blocks, EW>>>(G, U, guH, guL, NBSF);

    // ---- out = gu @ W_down + residual ----
    gemm_mma<2><<<gDD, 256, GM_SMEM>>>(guH, guL, WdH, WdL, out, resid, D, F);
}

// round 4
// speedup vs baseline: 3.0771x; 1.3399x over previous
#include <cuda_runtime.h>
#include <cuda_fp16.h>
#include <math.h>
#include <stdint.h>

// ---------------- problem constants ----------------
namespace hk {
constexpr int B  = 2;
constexpr int S  = 2048;
constexpr int D  = 2048;
constexpr int H  = 16;
constexpr int HD = 128;
constexpr int F  = 8192;
constexpr int BS = B * S;                     // 4096 rows
constexpr size_t NBSD = (size_t)BS * D;       // 8,388,608
constexpr size_t NBSF = (size_t)BS * F;       // 33,554,432
constexpr size_t NDD  = (size_t)D * D;
constexpr size_t NDF  = (size_t)D * F;
}

// ---------------- scratch: fp32 intermediates ----------------
__device__ float g_y     [hk::NBSD];
__device__ float g_xb    [hk::NBSD];
__device__ float g_xc    [hk::NBSD];
__device__ float g_rlin  [hk::NBSD];
__device__ float g_ilin  [hk::NBSD];
__device__ float g_a     [hk::NBSD];
__device__ float g_bx    [hk::NBSD];
__device__ float g_lru   [hk::NBSD];
__device__ float g_resid [hk::NBSD];
__device__ float g_G     [hk::NBSF];

// ---------------- scratch: fp16 hi/lo split activations ----------------
__device__ __half g_nH [hk::NBSD], g_nL [hk::NBSD];
__device__ __half g_zH [hk::NBSD], g_zL [hk::NBSD];
__device__ __half g_n2H[hk::NBSD], g_n2L[hk::NBSD];
__device__ __half g_guH[hk::NBSF], g_guL[hk::NBSF];

// ---------------- scratch: fp16 transposed weights [N,K] (single) ----------------
__device__ __half g_Wy[hk::NDD];
__device__ __half g_Wx[hk::NDD];
__device__ __half g_Wo[hk::NDD];
__device__ __half g_Wg[hk::NDF];
__device__ __half g_Wu[hk::NDF];
__device__ __half g_Wd[hk::NDF];

// ---------------- helpers ----------------
__device__ __forceinline__ float gelu_tanh(float x) {
    float x3 = x * x * x;
    return 0.5f * x * (1.0f + tanhf(0.7978845608028654f * (x + 0.044715f * x3)));
}

__device__ __forceinline__ uint32_t s2u(const void* p) {
    uint32_t a;
    asm("{ .reg .u64 t; cvta.to.shared.u64 t, %1; cvt.u32.u64 %0, t; }" : "=r"(a) : "l"(p));
    return a;
}

__device__ __forceinline__ void cpa16(uint32_t dst, const void* src) {
    asm volatile("cp.async.cg.shared.global [%0], [%1], 16;" :: "r"(dst), "l"(src));
}

__device__ __forceinline__ void ldmx4(uint32_t* r, uint32_t a) {
    asm volatile("ldmatrix.sync.aligned.m8n8.x4.shared.b16 {%0,%1,%2,%3}, [%4];"
                 : "=r"(r[0]), "=r"(r[1]), "=r"(r[2]), "=r"(r[3]) : "r"(a));
}

__device__ __forceinline__ void ldmx2(uint32_t* r, uint32_t a) {
    asm volatile("ldmatrix.sync.aligned.m8n8.x2.shared.b16 {%0,%1}, [%2];"
                 : "=r"(r[0]), "=r"(r[1]) : "r"(a));
}

__device__ __forceinline__ void mma16816(float* c, const uint32_t* a, const uint32_t* b) {
    asm volatile(
        "mma.sync.aligned.m16n8k16.row.col.f32.f16.f16.f32 "
        "{%0,%1,%2,%3}, {%4,%5,%6,%7}, {%8,%9}, {%0,%1,%2,%3};"
        : "+f"(c[0]), "+f"(c[1]), "+f"(c[2]), "+f"(c[3])
        : "r"(a[0]), "r"(a[1]), "r"(a[2]), "r"(a[3]), "r"(b[0]), "r"(b[1]));
}

__device__ __forceinline__ void split2h(float v, __half& h, __half& l) {
    h = __float2half_rn(v);
    l = __float2half_rn(v - __half2float(h));
}

// =====================================================================
// fp16x2 tensor-core GEMM via mma.sync:
//   C[M,N](fp32) = (Ah+Al)[M,K] @ B[N,K]^T      (A split, B single fp16)
// CTA tile 128x128, BK=32, 8 warps (2x4), 4-stage cp.async pipeline,
// one __syncthreads per K-step. Smem rows padded to 40 fp16 (80 B).
// EPI: 0 none, 1 tanh-gelu, 2 add aux(fp32),
//      3 multiply by aux(fp32) and write split fp16 (OH/OL).
// =====================================================================
constexpr int GM_LDK   = 40;                    // padded row length (fp16 elems)
constexpr int GM_MAT   = 128 * GM_LDK * 2;      // 10240 B per matrix tile
constexpr int GM_STAGE = 3 * GM_MAT;            // Ah, Al, B = 30720 B
constexpr int GM_NSTG  = 4;
constexpr int GM_SMEM  = GM_NSTG * GM_STAGE;    // 122880 B

template<int EPI>
__global__ void __launch_bounds__(256, 1)
gemm_mma(const __half* __restrict__ Ah, const __half* __restrict__ Al,
         const __half* __restrict__ Bw,
         float* __restrict__ C, const float* __restrict__ aux,
         __half* __restrict__ OH, __half* __restrict__ OL,
         int N, int K)
{
    extern __shared__ __align__(128) char smem[];
    const uint32_t sm0 = s2u(smem);

    const int tid  = threadIdx.x;
    const int lane = tid & 31;
    const int wid  = tid >> 5;
    const int wm   = wid >> 2;        // 0..1  -> 64-row slab
    const int wn   = wid & 3;         // 0..3  -> 32-col slab
    const int row0 = blockIdx.y * 128;
    const int col0 = blockIdx.x * 128;
    const int KB   = K >> 5;          // BK = 32

    uint32_t aoff[4], boff[4];
    #pragma unroll
    for (int im = 0; im < 4; im++)
        aoff[im] = (uint32_t)(((wm * 64 + im * 16 + (lane & 15)) * GM_LDK
                               + (lane >> 4) * 8) * 2);
    #pragma unroll
    for (int in = 0; in < 4; in++)
        boff[in] = (uint32_t)(((wn * 32 + in * 8 + (lane & 7)) * GM_LDK
                               + ((lane >> 3) & 1) * 8) * 2);

    float acc[4][4][4];
    #pragma unroll
    for (int im = 0; im < 4; im++)
        #pragma unroll
        for (int in = 0; in < 4; in++)
            #pragma unroll
            for (int q = 0; q < 4; q++) acc[im][in][q] = 0.0f;

    auto load_stage = [&](int kb) {
        const uint32_t sb = sm0 + (uint32_t)(kb % GM_NSTG) * GM_STAGE;
        const size_t k0 = (size_t)kb * 32;
        #pragma unroll
        for (int i = 0; i < 2; i++) {
            int id = tid + i * 256;          // 0..511
            int r = id >> 2, c = id & 3;
            uint32_t so = (uint32_t)((r * GM_LDK + c * 8) * 2);
            size_t gA = (size_t)(row0 + r) * K + k0 + (size_t)c * 8;
            size_t gB = (size_t)(col0 + r) * K + k0 + (size_t)c * 8;
            cpa16(sb + so,              Ah + gA);
            cpa16(sb + GM_MAT + so,     Al + gA);
            cpa16(sb + 2 * GM_MAT + so, Bw + gB);
        }
        asm volatile("cp.async.commit_group;" ::: "memory");
    };

    auto compute_stage = [&](int kb) {
        const uint32_t sb = sm0 + (uint32_t)(kb % GM_NSTG) * GM_STAGE;
        #pragma unroll
        for (int kk = 0; kk < 2; kk++) {
            uint32_t ahf[4][4], alf[4][4], bf[4][2];
            #pragma unroll
            for (int im = 0; im < 4; im++) {
                ldmx4(ahf[im], sb + aoff[im] + kk * 32);
                ldmx4(alf[im], sb + GM_MAT + aoff[im] + kk * 32);
            }
            #pragma unroll
            for (int in = 0; in < 4; in++)
                ldmx2(bf[in], sb + 2 * GM_MAT + boff[in] + kk * 32);
            #pragma unroll
            for (int im = 0; im < 4; im++)
                #pragma unroll
                for (int in = 0; in < 4; in++)
                    mma16816(acc[im][in], ahf[im], bf[in]);
            #pragma unroll
            for (int im = 0; im < 4; im++)
                #pragma unroll
                for (int in = 0; in < 4; in++)
                    mma16816(acc[im][in], alf[im], bf[in]);
        }
    };

    load_stage(0);
    load_stage(1);
    load_stage(2);
    for (int kb = 0; kb < KB; kb++) {
        asm volatile("cp.async.wait_group 2;" ::: "memory");
        __syncthreads();
        if (kb + 3 < KB) load_stage(kb + 3);
        else asm volatile("cp.async.commit_group;" ::: "memory");
        compute_stage(kb);
    }

    // ---- epilogue ----
    const int gid = lane >> 2, t4 = lane & 3;
    #pragma unroll
    for (int im = 0; im < 4; im++) {
        #pragma unroll
        for (int in = 0; in < 4; in++) {
            int r = row0 + wm * 64 + im * 16 + gid;
            int c = col0 + wn * 32 + in * 8 + t4 * 2;
            #pragma unroll
            for (int half = 0; half < 2; half++) {
                int rr = r + half * 8;
                float v0 = acc[im][in][half * 2 + 0];
                float v1 = acc[im][in][half * 2 + 1];
                if (EPI == 1) { v0 = gelu_tanh(v0); v1 = gelu_tanh(v1); }
                if (EPI == 2) {
                    float2 a2 = *reinterpret_cast<const float2*>(aux + (size_t)rr * N + c);
                    v0 += a2.x; v1 += a2.y;
                }
                if (EPI == 3) {
                    float2 a2 = *reinterpret_cast<const float2*>(aux + (size_t)rr * N + c);
                    v0 *= a2.x; v1 *= a2.y;
                    __half h0, l0, h1, l1;
                    split2h(v0, h0, l0); split2h(v1, h1, l1);
                    __half2 hp; hp.x = h0; hp.y = h1;
                    __half2 lp; lp.x = l0; lp.y = l1;
                    *reinterpret_cast<__half2*>(OH + (size_t)rr * N + c) = hp;
                    *reinterpret_cast<__half2*>(OL + (size_t)rr * N + c) = lp;
                } else {
                    float2 o; o.x = v0; o.y = v1;
                    *reinterpret_cast<float2*>(C + (size_t)rr * N + c) = o;
                }
            }
        }
    }
}

// =====================================================================
// transpose to fp16: W[K,N] fp32 -> Wt[N,K] fp16
// =====================================================================
__global__ void trans_half(const float* __restrict__ W, __half* __restrict__ Wt,
                           int K, int N)
{
    __shared__ float t[32][33];
    int n0 = blockIdx.x * 32, k0 = blockIdx.y * 32;
    int tx = threadIdx.x, ty = threadIdx.y;   // 32 x 8
    #pragma unroll
    for (int i = 0; i < 32; i += 8)
        t[ty + i][tx] = W[(size_t)(k0 + ty + i) * N + (n0 + tx)];
    __syncthreads();
    #pragma unroll
    for (int i = 0; i < 32; i += 8)
        Wt[(size_t)(n0 + ty + i) * K + (k0 + tx)] = __float2half_rn(t[tx][ty + i]);
}

// ---------------- rmsnorm with fp16 hi/lo split output ----------------
__global__ void rmsnorm_split(const float* __restrict__ x, const float* __restrict__ w,
                              __half* __restrict__ hi, __half* __restrict__ lo)
{
    using namespace hk;
    const int row = blockIdx.x;
    const float* xr = x + (size_t)row * D;
    float ss = 0.0f;
    for (int d = threadIdx.x; d < D; d += 256) { float v = xr[d]; ss += v * v; }
    __shared__ float red[8];
    #pragma unroll
    for (int o = 16; o > 0; o >>= 1) ss += __shfl_down_sync(0xffffffffu, ss, o);
    if ((threadIdx.x & 31) == 0) red[threadIdx.x >> 5] = ss;
    __syncthreads();
    if (threadIdx.x < 8) {
        float v = red[threadIdx.x];
        #pragma unroll
        for (int o = 4; o > 0; o >>= 1) v += __shfl_down_sync(0xffu, v, o);
        if (threadIdx.x == 0) red[0] = v;
    }
    __syncthreads();
    const float scale = rsqrtf(red[0] / (float)D + 1e-6f);
    size_t base = (size_t)row * D;
    for (int d = threadIdx.x; d < D; d += 256) {
        float v = xr[d] * scale * w[d];
        __half h, l; split2h(v, h, l);
        hi[base + d] = h; lo[base + d] = l;
    }
}

// ---------------- causal depthwise conv, kernel 4 ----------------
__global__ void conv_kernel(const float* __restrict__ xb, const float* __restrict__ cw,
                            const float* __restrict__ cb, float* __restrict__ xc)
{
    using namespace hk;
    size_t idx = (size_t)blockIdx.x * blockDim.x + threadIdx.x;
    if (idx >= NBSD) return;
    int d = (int)(idx % D);
    int s = (int)((idx / D) % S);
    float acc = cb[d];
    #pragma unroll
    for (int k = 0; k < 4; k++) {
        int ss = s + k - 3;
        if (ss >= 0) acc = fmaf(cw[k * D + d], xb[idx + (size_t)(k - 3) * D], acc);
    }
    xc[idx] = acc;
}

// ---------------- SIMT fp32 GEMM (gates only; small) ----------------
__global__ void __launch_bounds__(256)
gemm_tpl(const float* __restrict__ A, const float* __restrict__ Bm,
         float* __restrict__ C,
         int M, int N, int K, int lda, int ldb, int ldc,
         long long sA, long long sB, long long sC)
{
    __shared__ float As[8][128];
    __shared__ float Bs[8][128];
    A  += (size_t)blockIdx.z * sA;
    Bm += (size_t)blockIdx.z * sB;
    C  += (size_t)blockIdx.z * sC;
    const int tid  = threadIdx.x;
    const int row0 = blockIdx.y * 128;
    const int col0 = blockIdx.x * 128;
    const int aRow = tid >> 1, aCol = (tid & 1) * 4;
    const int bRow = tid >> 5, bCol = (tid & 31) * 4;
    const int ty = tid >> 4, tx = tid & 15;
    float acc[8][8];
    #pragma unroll
    for (int i = 0; i < 8; i++)
        #pragma unroll
        for (int j = 0; j < 8; j++) acc[i][j] = 0.0f;
    for (int k0 = 0; k0 < K; k0 += 8) {
        float4 av = *reinterpret_cast<const float4*>(&A[(size_t)(row0 + aRow) * lda + (k0 + aCol)]);
        float4 bv = *reinterpret_cast<const float4*>(&Bm[(size_t)(k0 + bRow) * ldb + (col0 + bCol)]);
        As[aCol + 0][aRow] = av.x; As[aCol + 1][aRow] = av.y;
        As[aCol + 2][aRow] = av.z; As[aCol + 3][aRow] = av.w;
        *reinterpret_cast<float4*>(&Bs[bRow][bCol]) = bv;
        __syncthreads();
        #pragma unroll
        for (int k = 0; k < 8; k++) {
            float ra[8], rb[8];
            #pragma unroll
            for (int i = 0; i < 8; i++) ra[i] = As[k][ty * 8 + i];
            #pragma unroll
            for (int j = 0; j < 8; j++) rb[j] = Bs[k][tx * 8 + j];
            #pragma unroll
            for (int i = 0; i < 8; i++)
                #pragma unroll
                for (int j = 0; j < 8; j++)
                    acc[i][j] = fmaf(ra[i], rb[j], acc[i][j]);
        }
        __syncthreads();
    }
    #pragma unroll
    for (int i = 0; i < 8; i++) {
        int r = row0 + ty * 8 + i;
        #pragma unroll
        for (int j = 0; j < 8; j += 4) {
            int c = col0 + tx * 8 + j;
            float4 v;
            v.x = acc[i][j]; v.y = acc[i][j + 1]; v.z = acc[i][j + 2]; v.w = acc[i][j + 3];
            *reinterpret_cast<float4*>(&C[(size_t)r * ldc + c]) = v;
        }
    }
}

// ---------------- RG-LRU gate pointwise ----------------
__global__ void gate_kernel(const float* __restrict__ rlin, const float* __restrict__ ilin,
                            const float* __restrict__ xc, const float* __restrict__ ab,
                            const float* __restrict__ ib, const float* __restrict__ apar,
                            float* __restrict__ ga, float* __restrict__ gb)
{
    using namespace hk;
    size_t idx = (size_t)blockIdx.x * blockDim.x + threadIdx.x;
    if (idx >= NBSD) return;
    int d = (int)(idx % D);
    float sp = log1pf(expf(-apar[d]));
    float r  = 1.0f / (1.0f + expf(-(rlin[idx] + ab[d])));
    float ii = 1.0f / (1.0f + expf(-(ilin[idx] + ib[d])));
    float la = -8.0f * r * sp;
    ga[idx]  = expf(la);
    float mult = sqrtf(fmaxf(1.0f - expf(2.0f * la), 0.0f));
    gb[idx]  = mult * ii * xc[idx];
}

// ---------------- linear scan ----------------
__global__ void scan_kernel(const float* __restrict__ a, const float* __restrict__ bx,
                            const float* __restrict__ h0, float* __restrict__ lru,
                            float* __restrict__ hlast)
{
    using namespace hk;
    int ch = blockIdx.x * blockDim.x + threadIdx.x;
    if (ch >= B * D) return;
    int b = ch / D, d = ch % D;
    float h = h0[ch];
    size_t base = (size_t)b * S * D + d;
    for (int s = 0; s < S; s++) {
        size_t idx = base + (size_t)s * D;
        h = fmaf(a[idx], h, bx[idx]);
        lru[idx] = h;
    }
    if (hlast) hlast[ch] = h;
}

// ---------------- elementwise multiply with fp16 split output ----------------
__global__ void mul_split(const float* __restrict__ a, const float* __restrict__ b,
                          __half* __restrict__ hi, __half* __restrict__ lo, size_t n)
{
    size_t idx = (size_t)blockIdx.x * blockDim.x + threadIdx.x;
    if (idx < n) {
        float v = a[idx] * b[idx];
        __half h, l; split2h(v, h, l);
        hi[idx] = h; lo[idx] = l;
    }
}

// ---------------- launch ----------------
extern "C" void kernel_launch(void* const* d_in, const int* in_sizes, int n_in,
                              void* d_out, int out_size)
{
    using namespace hk;
    const float* x    = (const float*)d_in[0];
    const float* h0   = (const float*)d_in[1];
    const float* r1w  = (const float*)d_in[2];
    const float* r2w  = (const float*)d_in[3];
    const float* Wx   = (const float*)d_in[4];
    const float* Wy   = (const float*)d_in[5];
    const float* cw   = (const float*)d_in[6];
    const float* cb   = (const float*)d_in[7];
    const float* apar = (const float*)d_in[8];
    const float* igw  = (const float*)d_in[9];
    const float* igb  = (const float*)d_in[10];
    const float* agw  = (const float*)d_in[11];
    const float* agb  = (const float*)d_in[12];
    const float* Wout = (const float*)d_in[13];
    const float* Wg   = (const float*)d_in[14];
    const float* Wu   = (const float*)d_in[15];
    const float* Wd   = (const float*)d_in[16];
    float* out = (float*)d_out;

    float *y, *xb, *xc, *rlin, *ilin, *ga, *gb, *lru, *resid, *G;
    cudaGetSymbolAddress((void**)&y,     g_y);
    cudaGetSymbolAddress((void**)&xb,    g_xb);
    cudaGetSymbolAddress((void**)&xc,    g_xc);
    cudaGetSymbolAddress((void**)&rlin,  g_rlin);
    cudaGetSymbolAddress((void**)&ilin,  g_ilin);
    cudaGetSymbolAddress((void**)&ga,    g_a);
    cudaGetSymbolAddress((void**)&gb,    g_bx);
    cudaGetSymbolAddress((void**)&lru,   g_lru);
    cudaGetSymbolAddress((void**)&resid, g_resid);
    cudaGetSymbolAddress((void**)&G,     g_G);

    __half *nH,*nL,*zH,*zL,*n2H,*n2L,*guH,*guL;
    __half *tWy,*tWx,*tWo,*tWg,*tWu,*tWd;
    cudaGetSymbolAddress((void**)&nH,  g_nH);  cudaGetSymbolAddress((void**)&nL,  g_nL);
    cudaGetSymbolAddress((void**)&zH,  g_zH);  cudaGetSymbolAddress((void**)&zL,  g_zL);
    cudaGetSymbolAddress((void**)&n2H, g_n2H); cudaGetSymbolAddress((void**)&n2L, g_n2L);
    cudaGetSymbolAddress((void**)&guH, g_guH); cudaGetSymbolAddress((void**)&guL, g_guL);
    cudaGetSymbolAddress((void**)&tWy, g_Wy);  cudaGetSymbolAddress((void**)&tWx, g_Wx);
    cudaGetSymbolAddress((void**)&tWo, g_Wo);  cudaGetSymbolAddress((void**)&tWg, g_Wg);
    cudaGetSymbolAddress((void**)&tWu, g_Wu);  cudaGetSymbolAddress((void**)&tWd, g_Wd);

    cudaFuncSetAttribute(gemm_mma<0>, cudaFuncAttributeMaxDynamicSharedMemorySize, GM_SMEM);
    cudaFuncSetAttribute(gemm_mma<1>, cudaFuncAttributeMaxDynamicSharedMemorySize, GM_SMEM);
    cudaFuncSetAttribute(gemm_mma<2>, cudaFuncAttributeMaxDynamicSharedMemorySize, GM_SMEM);
    cudaFuncSetAttribute(gemm_mma<3>, cudaFuncAttributeMaxDynamicSharedMemorySize, GM_SMEM);

    const int EW = 256;
    const size_t nbsd_blocks = (NBSD + EW - 1) / EW;
    float* hlast = (out_size >= (int)(NBSD + (size_t)B * D)) ? (out + NBSD) : nullptr;

    // ---- weight transpose to fp16 (every call; deterministic) ----
    dim3 tb(32, 8);
    trans_half<<<dim3(D / 32, D / 32), tb>>>(Wy,   tWy, D, D);
    trans_half<<<dim3(D / 32, D / 32), tb>>>(Wx,   tWx, D, D);
    trans_half<<<dim3(D / 32, D / 32), tb>>>(Wout, tWo, D, D);
    trans_half<<<dim3(F / 32, D / 32), tb>>>(Wg,   tWg, D, F);
    trans_half<<<dim3(F / 32, D / 32), tb>>>(Wu,   tWu, D, F);
    trans_half<<<dim3(D / 32, F / 32), tb>>>(Wd,   tWd, F, D);

    // ---- temporal pre-norm (split output) ----
    rmsnorm_split<<<BS, 256>>>(x, r1w, nH, nL);

    // ---- y = gelu(normed @ W_y); xb = normed @ W_x ----
    dim3 gDD(D / 128, BS / 128);
    gemm_mma<1><<<gDD, 256, GM_SMEM>>>(nH, nL, tWy, y,  nullptr, nullptr, nullptr, D, D);
    gemm_mma<0><<<gDD, 256, GM_SMEM>>>(nH, nL, tWx, xb, nullptr, nullptr, nullptr, D, D);

    // ---- causal conv ----
    conv_kernel<<<(unsigned)nbsd_blocks, EW>>>(xb, cw, cb, xc);

    // ---- gate GEMMs (SIMT fp32; tiny) ----
    dim3 gGate(HD / 128, BS / 128, H);
    gemm_tpl<<<gGate, 256>>>(xc, agw, rlin, BS, HD, HD, D, HD, D,
                             HD, (long long)HD * HD, HD);
    gemm_tpl<<<gGate, 256>>>(xc, igw, ilin, BS, HD, HD, D, HD, D,
                             HD, (long long)HD * HD, HD);

    // ---- gate pointwise -> a, bx ----
    gate_kernel<<<(unsigned)nbsd_blocks, EW>>>(rlin, ilin, xc, agb, igb, apar, ga, gb);

    // ---- linear recurrence ----
    scan_kernel<<<(B * D + 255) / 256, 256>>>(ga, gb, h0, lru, hlast);

    // ---- z = y * lru (split fp16) ----
    mul_split<<<(unsigned)nbsd_blocks, EW>>>(y, lru, zH, zL, NBSD);

    // ---- residual = z @ W_out + x ----
    gemm_mma<2><<<gDD, 256, GM_SMEM>>>(zH, zL, tWo, resid, x, nullptr, nullptr, D, D);

    // ---- second norm (split) ----
    rmsnorm_split<<<BS, 256>>>(resid, r2w, n2H, n2L);

    // ---- MLP: G = gelu(n2 @ Wg); gu = (n2 @ Wu) * G  (fused split epilogue) ----
    dim3 gDF(F / 128, BS / 128);
    gemm_mma<1><<<gDF, 256, GM_SMEM>>>(n2H, n2L, tWg, G, nullptr, nullptr, nullptr, F, D);
    gemm_mma<3><<<gDF, 256, GM_SMEM>>>(n2H, n2L, tWu, nullptr, G, guH, guL, F, D);

    // ---- out = gu @ W_down + residual ----
    gemm_mma<2><<<gDD, 256, GM_SMEM>>>(guH, guL, tWd, out, resid, nullptr, nullptr, D, F);
}

// round 5
// speedup vs baseline: 3.6339x; 1.1809x over previous
#include <cuda_runtime.h>
#include <cuda_fp16.h>
#include <math.h>
#include <stdint.h>

// ---------------- problem constants ----------------
namespace hk {
constexpr int B  = 2;
constexpr int S  = 2048;
constexpr int D  = 2048;
constexpr int H  = 16;
constexpr int HD = 128;
constexpr int F  = 8192;
constexpr int BS = B * S;                     // 4096 rows
constexpr size_t NBSD = (size_t)BS * D;       // 8,388,608
constexpr size_t NBSF = (size_t)BS * F;       // 33,554,432
constexpr size_t NDD  = (size_t)D * D;
constexpr size_t NDF  = (size_t)D * F;
}

// ---------------- scratch: fp32 intermediates ----------------
__device__ float g_y     [hk::NBSD];
__device__ float g_xb    [hk::NBSD];
__device__ float g_xc    [hk::NBSD];
__device__ float g_rlin  [hk::NBSD];
__device__ float g_ilin  [hk::NBSD];
__device__ float g_a     [hk::NBSD];
__device__ float g_bx    [hk::NBSD];
__device__ float g_lru   [hk::NBSD];
__device__ float g_resid [hk::NBSD];
__device__ float g_G     [hk::NBSF];

// ---------------- scratch: fp16 hi/lo split activations ----------------
__device__ __half g_nH [hk::NBSD], g_nL [hk::NBSD];
__device__ __half g_zH [hk::NBSD], g_zL [hk::NBSD];
__device__ __half g_n2H[hk::NBSD], g_n2L[hk::NBSD];
__device__ __half g_guH[hk::NBSF], g_guL[hk::NBSF];

// ---------------- scratch: fp16 transposed weights [N,K] ----------------
__device__ __half g_Wy[hk::NDD];
__device__ __half g_Wx[hk::NDD];
__device__ __half g_Wo[hk::NDD];
__device__ __half g_Wg[hk::NDF];
__device__ __half g_Wu[hk::NDF];
__device__ __half g_Wd[hk::NDF];

// ---------------- helpers ----------------
__device__ __forceinline__ float gelu_tanh(float x) {
    float x3 = x * x * x;
    return 0.5f * x * (1.0f + tanhf(0.7978845608028654f * (x + 0.044715f * x3)));
}

__device__ __forceinline__ uint32_t s2u(const void* p) {
    uint32_t a;
    asm("{ .reg .u64 t; cvta.to.shared.u64 t, %1; cvt.u32.u64 %0, t; }" : "=r"(a) : "l"(p));
    return a;
}

__device__ __forceinline__ void cpa16(uint32_t dst, const void* src) {
    asm volatile("cp.async.cg.shared.global [%0], [%1], 16;" :: "r"(dst), "l"(src));
}

__device__ __forceinline__ void ldmx4(uint32_t* r, uint32_t a) {
    asm volatile("ldmatrix.sync.aligned.m8n8.x4.shared.b16 {%0,%1,%2,%3}, [%4];"
                 : "=r"(r[0]), "=r"(r[1]), "=r"(r[2]), "=r"(r[3]) : "r"(a));
}

__device__ __forceinline__ void mma16816(float* c, const uint32_t* a, const uint32_t* b) {
    asm volatile(
        "mma.sync.aligned.m16n8k16.row.col.f32.f16.f16.f32 "
        "{%0,%1,%2,%3}, {%4,%5,%6,%7}, {%8,%9}, {%0,%1,%2,%3};"
        : "+f"(c[0]), "+f"(c[1]), "+f"(c[2]), "+f"(c[3])
        : "r"(a[0]), "r"(a[1]), "r"(a[2]), "r"(a[3]), "r"(b[0]), "r"(b[1]));
}

__device__ __forceinline__ void split2h(float v, __half& h, __half& l) {
    h = __float2half_rn(v);
    l = __float2half_rn(v - __half2float(h));
}

// =====================================================================
// fp16x2 tensor-core GEMM via mma.sync:
//   C[M,N](fp32) = (Ah+Al)[M,K] @ B[N,K]^T      (A split, B single fp16)
// CTA tile 128x256, warp tile 64x64 (8 warps 2x4), BK=32,
// 4-stage cp.async pipeline. Smem rows padded to 40 fp16 (80 B).
// EPI: 0 none, 1 tanh-gelu, 2 add aux(fp32),
//      3 multiply by aux(fp32) and write split fp16 (OH/OL).
// =====================================================================
constexpr int GM_LDK   = 40;                    // padded row length (fp16 elems)
constexpr int GM_MATA  = 128 * GM_LDK * 2;      // 10240 B per A matrix tile
constexpr int GM_MATB  = 256 * GM_LDK * 2;      // 20480 B for the B tile
constexpr int GM_STAGE = 2 * GM_MATA + GM_MATB; // Ah, Al, B = 40960 B
constexpr int GM_NSTG  = 4;
constexpr int GM_SMEM  = GM_NSTG * GM_STAGE;    // 163840 B

template<int EPI>
__global__ void __launch_bounds__(256, 1)
gemm_mma(const __half* __restrict__ Ah, const __half* __restrict__ Al,
         const __half* __restrict__ Bw,
         float* __restrict__ C, const float* __restrict__ aux,
         __half* __restrict__ OH, __half* __restrict__ OL,
         int N, int K)
{
    extern __shared__ __align__(128) char smem[];
    const uint32_t sm0 = s2u(smem);

    const int tid  = threadIdx.x;
    const int lane = tid & 31;
    const int wid  = tid >> 5;
    const int wm   = wid >> 2;        // 0..1  -> 64-row slab
    const int wn   = wid & 3;         // 0..3  -> 64-col slab
    const int row0 = blockIdx.y * 128;
    const int col0 = blockIdx.x * 256;
    const int KB   = K >> 5;          // BK = 32

    // ldmatrix byte offsets within tiles
    uint32_t aoff[4], boff[4];
    #pragma unroll
    for (int im = 0; im < 4; im++)
        aoff[im] = (uint32_t)(((wm * 64 + im * 16 + (lane & 15)) * GM_LDK
                               + (lane >> 4) * 8) * 2);
    #pragma unroll
    for (int ip = 0; ip < 4; ip++)    // each ip covers two n8-tiles (16 rows)
        boff[ip] = (uint32_t)(((wn * 64 + ip * 16 + (lane & 7) + ((lane >> 4) & 1) * 8)
                               * GM_LDK + ((lane >> 3) & 1) * 8) * 2);

    float acc[4][8][4];
    #pragma unroll
    for (int im = 0; im < 4; im++)
        #pragma unroll
        for (int in = 0; in < 8; in++)
            #pragma unroll
            for (int q = 0; q < 4; q++) acc[im][in][q] = 0.0f;

    auto load_stage = [&](int kb) {
        const uint32_t sb = sm0 + (uint32_t)(kb % GM_NSTG) * GM_STAGE;
        const size_t k0 = (size_t)kb * 32;
        // A hi + lo: 2 * 128 rows * 4 chunks = 1024 cp.async
        #pragma unroll
        for (int i = 0; i < 4; i++) {
            int id  = tid + i * 256;          // 0..1023
            int mat = id >> 9;                // 0 = hi, 1 = lo
            int rid = id & 511;
            int r = rid >> 2, c = rid & 3;
            uint32_t so = (uint32_t)(mat * GM_MATA + (r * GM_LDK + c * 8) * 2);
            size_t gA = (size_t)(row0 + r) * K + k0 + (size_t)c * 8;
            cpa16(sb + so, (mat ? Al : Ah) + gA);
        }
        // B: 256 rows * 4 chunks = 1024 cp.async
        #pragma unroll
        for (int i = 0; i < 4; i++) {
            int id = tid + i * 256;
            int r = id >> 2, c = id & 3;
            uint32_t so = (uint32_t)(2 * GM_MATA + (r * GM_LDK + c * 8) * 2);
            size_t gB = (size_t)(col0 + r) * K + k0 + (size_t)c * 8;
            cpa16(sb + so, Bw + gB);
        }
        asm volatile("cp.async.commit_group;" ::: "memory");
    };

    auto compute_stage = [&](int kb) {
        const uint32_t sb = sm0 + (uint32_t)(kb % GM_NSTG) * GM_STAGE;
        #pragma unroll
        for (int kk = 0; kk < 2; kk++) {
            uint32_t ahf[4][4], alf[4][4], bf[8][2];
            #pragma unroll
            for (int im = 0; im < 4; im++) {
                ldmx4(ahf[im], sb + aoff[im] + kk * 32);
                ldmx4(alf[im], sb + GM_MATA + aoff[im] + kk * 32);
            }
            #pragma unroll
            for (int ip = 0; ip < 4; ip++) {
                uint32_t r4[4];
                ldmx4(r4, sb + 2 * GM_MATA + boff[ip] + kk * 32);
                bf[2 * ip + 0][0] = r4[0]; bf[2 * ip + 0][1] = r4[1];
                bf[2 * ip + 1][0] = r4[2]; bf[2 * ip + 1][1] = r4[3];
            }
            #pragma unroll
            for (int im = 0; im < 4; im++)
                #pragma unroll
                for (int in = 0; in < 8; in++)
                    mma16816(acc[im][in], ahf[im], bf[in]);
            #pragma unroll
            for (int im = 0; im < 4; im++)
                #pragma unroll
                for (int in = 0; in < 8; in++)
                    mma16816(acc[im][in], alf[im], bf[in]);
        }
    };

    load_stage(0);
    load_stage(1);
    load_stage(2);
    for (int kb = 0; kb < KB; kb++) {
        asm volatile("cp.async.wait_group 2;" ::: "memory");
        __syncthreads();
        if (kb + 3 < KB) load_stage(kb + 3);
        else asm volatile("cp.async.commit_group;" ::: "memory");
        compute_stage(kb);
    }

    // ---- epilogue ----
    const int gid = lane >> 2, t4 = lane & 3;
    #pragma unroll
    for (int im = 0; im < 4; im++) {
        #pragma unroll
        for (int in = 0; in < 8; in++) {
            int r = row0 + wm * 64 + im * 16 + gid;
            int c = col0 + wn * 64 + in * 8 + t4 * 2;
            #pragma unroll
            for (int half = 0; half < 2; half++) {
                int rr = r + half * 8;
                float v0 = acc[im][in][half * 2 + 0];
                float v1 = acc[im][in][half * 2 + 1];
                if (EPI == 1) { v0 = gelu_tanh(v0); v1 = gelu_tanh(v1); }
                if (EPI == 2) {
                    float2 a2 = *reinterpret_cast<const float2*>(aux + (size_t)rr * N + c);
                    v0 += a2.x; v1 += a2.y;
                }
                if (EPI == 3) {
                    float2 a2 = *reinterpret_cast<const float2*>(aux + (size_t)rr * N + c);
                    v0 *= a2.x; v1 *= a2.y;
                    __half h0, l0, h1, l1;
                    split2h(v0, h0, l0); split2h(v1, h1, l1);
                    __half2 hp; hp.x = h0; hp.y = h1;
                    __half2 lp; lp.x = l0; lp.y = l1;
                    *reinterpret_cast<__half2*>(OH + (size_t)rr * N + c) = hp;
                    *reinterpret_cast<__half2*>(OL + (size_t)rr * N + c) = lp;
                } else {
                    float2 o; o.x = v0; o.y = v1;
                    *reinterpret_cast<float2*>(C + (size_t)rr * N + c) = o;
                }
            }
        }
    }
}

// =====================================================================
// transpose to fp16: W[K,N] fp32 -> Wt[N,K] fp16
// =====================================================================
__global__ void trans_half(const float* __restrict__ W, __half* __restrict__ Wt,
                           int K, int N)
{
    __shared__ float t[32][33];
    int n0 = blockIdx.x * 32, k0 = blockIdx.y * 32;
    int tx = threadIdx.x, ty = threadIdx.y;   // 32 x 8
    #pragma unroll
    for (int i = 0; i < 32; i += 8)
        t[ty + i][tx] = W[(size_t)(k0 + ty + i) * N + (n0 + tx)];
    __syncthreads();
    #pragma unroll
    for (int i = 0; i < 32; i += 8)
        Wt[(size_t)(n0 + ty + i) * K + (k0 + tx)] = __float2half_rn(t[tx][ty + i]);
}

// ---------------- rmsnorm with fp16 hi/lo split output ----------------
__global__ void rmsnorm_split(const float* __restrict__ x, const float* __restrict__ w,
                              __half* __restrict__ hi, __half* __restrict__ lo)
{
    using namespace hk;
    const int row = blockIdx.x;
    const float* xr = x + (size_t)row * D;
    float ss = 0.0f;
    for (int d = threadIdx.x; d < D; d += 256) { float v = xr[d]; ss += v * v; }
    __shared__ float red[8];
    #pragma unroll
    for (int o = 16; o > 0; o >>= 1) ss += __shfl_down_sync(0xffffffffu, ss, o);
    if ((threadIdx.x & 31) == 0) red[threadIdx.x >> 5] = ss;
    __syncthreads();
    if (threadIdx.x < 8) {
        float v = red[threadIdx.x];
        #pragma unroll
        for (int o = 4; o > 0; o >>= 1) v += __shfl_down_sync(0xffu, v, o);
        if (threadIdx.x == 0) red[0] = v;
    }
    __syncthreads();
    const float scale = rsqrtf(red[0] / (float)D + 1e-6f);
    size_t base = (size_t)row * D;
    for (int d = threadIdx.x; d < D; d += 256) {
        float v = xr[d] * scale * w[d];
        __half h, l; split2h(v, h, l);
        hi[base + d] = h; lo[base + d] = l;
    }
}

// ---------------- causal depthwise conv, kernel 4 ----------------
__global__ void conv_kernel(const float* __restrict__ xb, const float* __restrict__ cw,
                            const float* __restrict__ cb, float* __restrict__ xc)
{
    using namespace hk;
    size_t idx = (size_t)blockIdx.x * blockDim.x + threadIdx.x;
    if (idx >= NBSD) return;
    int d = (int)(idx % D);
    int s = (int)((idx / D) % S);
    float acc = cb[d];
    #pragma unroll
    for (int k = 0; k < 4; k++) {
        int ss = s + k - 3;
        if (ss >= 0) acc = fmaf(cw[k * D + d], xb[idx + (size_t)(k - 3) * D], acc);
    }
    xc[idx] = acc;
}

// ---------------- SIMT fp32 GEMM (gates only; small) ----------------
__global__ void __launch_bounds__(256)
gemm_tpl(const float* __restrict__ A, const float* __restrict__ Bm,
         float* __restrict__ C,
         int M, int N, int K, int lda, int ldb, int ldc,
         long long sA, long long sB, long long sC)
{
    __shared__ float As[8][128];
    __shared__ float Bs[8][128];
    A  += (size_t)blockIdx.z * sA;
    Bm += (size_t)blockIdx.z * sB;
    C  += (size_t)blockIdx.z * sC;
    const int tid  = threadIdx.x;
    const int row0 = blockIdx.y * 128;
    const int col0 = blockIdx.x * 128;
    const int aRow = tid >> 1, aCol = (tid & 1) * 4;
    const int bRow = tid >> 5, bCol = (tid & 31) * 4;
    const int ty = tid >> 4, tx = tid & 15;
    float acc[8][8];
    #pragma unroll
    for (int i = 0; i < 8; i++)
        #pragma unroll
        for (int j = 0; j < 8; j++) acc[i][j] = 0.0f;
    for (int k0 = 0; k0 < K; k0 += 8) {
        float4 av = *reinterpret_cast<const float4*>(&A[(size_t)(row0 + aRow) * lda + (k0 + aCol)]);
        float4 bv = *reinterpret_cast<const float4*>(&Bm[(size_t)(k0 + bRow) * ldb + (col0 + bCol)]);
        As[aCol + 0][aRow] = av.x; As[aCol + 1][aRow] = av.y;
        As[aCol + 2][aRow] = av.z; As[aCol + 3][aRow] = av.w;
        *reinterpret_cast<float4*>(&Bs[bRow][bCol]) = bv;
        __syncthreads();
        #pragma unroll
        for (int k = 0; k < 8; k++) {
            float ra[8], rb[8];
            #pragma unroll
            for (int i = 0; i < 8; i++) ra[i] = As[k][ty * 8 + i];
            #pragma unroll
            for (int j = 0; j < 8; j++) rb[j] = Bs[k][tx * 8 + j];
            #pragma unroll
            for (int i = 0; i < 8; i++)
                #pragma unroll
                for (int j = 0; j < 8; j++)
                    acc[i][j] = fmaf(ra[i], rb[j], acc[i][j]);
        }
        __syncthreads();
    }
    #pragma unroll
    for (int i = 0; i < 8; i++) {
        int r = row0 + ty * 8 + i;
        #pragma unroll
        for (int j = 0; j < 8; j += 4) {
            int c = col0 + tx * 8 + j;
            float4 v;
            v.x = acc[i][j]; v.y = acc[i][j + 1]; v.z = acc[i][j + 2]; v.w = acc[i][j + 3];
            *reinterpret_cast<float4*>(&C[(size_t)r * ldc + c]) = v;
        }
    }
}

// ---------------- RG-LRU gate pointwise ----------------
__global__ void gate_kernel(const float* __restrict__ rlin, const float* __restrict__ ilin,
                            const float* __restrict__ xc, const float* __restrict__ ab,
                            const float* __restrict__ ib, const float* __restrict__ apar,
                            float* __restrict__ ga, float* __restrict__ gb)
{
    using namespace hk;
    size_t idx = (size_t)blockIdx.x * blockDim.x + threadIdx.x;
    if (idx >= NBSD) return;
    int d = (int)(idx % D);
    float sp = log1pf(expf(-apar[d]));
    float r  = 1.0f / (1.0f + expf(-(rlin[idx] + ab[d])));
    float ii = 1.0f / (1.0f + expf(-(ilin[idx] + ib[d])));
    float la = -8.0f * r * sp;
    ga[idx]  = expf(la);
    float mult = sqrtf(fmaxf(1.0f - expf(2.0f * la), 0.0f));
    gb[idx]  = mult * ii * xc[idx];
}

// ---------------- linear scan ----------------
__global__ void scan_kernel(const float* __restrict__ a, const float* __restrict__ bx,
                            const float* __restrict__ h0, float* __restrict__ lru,
                            float* __restrict__ hlast)
{
    using namespace hk;
    int ch = blockIdx.x * blockDim.x + threadIdx.x;
    if (ch >= B * D) return;
    int b = ch / D, d = ch % D;
    float h = h0[ch];
    size_t base = (size_t)b * S * D + d;
    for (int s = 0; s < S; s++) {
        size_t idx = base + (size_t)s * D;
        h = fmaf(a[idx], h, bx[idx]);
        lru[idx] = h;
    }
    if (hlast) hlast[ch] = h;
}

// ---------------- elementwise multiply with fp16 split output ----------------
__global__ void mul_split(const float* __restrict__ a, const float* __restrict__ b,
                          __half* __restrict__ hi, __half* __restrict__ lo, size_t n)
{
    size_t idx = (size_t)blockIdx.x * blockDim.x + threadIdx.x;
    if (idx < n) {
        float v = a[idx] * b[idx];
        __half h, l; split2h(v, h, l);
        hi[idx] = h; lo[idx] = l;
    }
}

// ---------------- launch ----------------
extern "C" void kernel_launch(void* const* d_in, const int* in_sizes, int n_in,
                              void* d_out, int out_size)
{
    using namespace hk;
    const float* x    = (const float*)d_in[0];
    const float* h0   = (const float*)d_in[1];
    const float* r1w  = (const float*)d_in[2];
    const float* r2w  = (const float*)d_in[3];
    const float* Wx   = (const float*)d_in[4];
    const float* Wy   = (const float*)d_in[5];
    const float* cw   = (const float*)d_in[6];
    const float* cb   = (const float*)d_in[7];
    const float* apar = (const float*)d_in[8];
    const float* igw  = (const float*)d_in[9];
    const float* igb  = (const float*)d_in[10];
    const float* agw  = (const float*)d_in[11];
    const float* agb  = (const float*)d_in[12];
    const float* Wout = (const float*)d_in[13];
    const float* Wg   = (const float*)d_in[14];
    const float* Wu   = (const float*)d_in[15];
    const float* Wd   = (const float*)d_in[16];
    float* out = (float*)d_out;

    float *y, *xb, *xc, *rlin, *ilin, *ga, *gb, *lru, *resid, *G;
    cudaGetSymbolAddress((void**)&y,     g_y);
    cudaGetSymbolAddress((void**)&xb,    g_xb);
    cudaGetSymbolAddress((void**)&xc,    g_xc);
    cudaGetSymbolAddress((void**)&rlin,  g_rlin);
    cudaGetSymbolAddress((void**)&ilin,  g_ilin);
    cudaGetSymbolAddress((void**)&ga,    g_a);
    cudaGetSymbolAddress((void**)&gb,    g_bx);
    cudaGetSymbolAddress((void**)&lru,   g_lru);
    cudaGetSymbolAddress((void**)&resid, g_resid);
    cudaGetSymbolAddress((void**)&G,     g_G);

    __half *nH,*nL,*zH,*zL,*n2H,*n2L,*guH,*guL;
    __half *tWy,*tWx,*tWo,*tWg,*tWu,*tWd;
    cudaGetSymbolAddress((void**)&nH,  g_nH);  cudaGetSymbolAddress((void**)&nL,  g_nL);
    cudaGetSymbolAddress((void**)&zH,  g_zH);  cudaGetSymbolAddress((void**)&zL,  g_zL);
    cudaGetSymbolAddress((void**)&n2H, g_n2H); cudaGetSymbolAddress((void**)&n2L, g_n2L);
    cudaGetSymbolAddress((void**)&guH, g_guH); cudaGetSymbolAddress((void**)&guL, g_guL);
    cudaGetSymbolAddress((void**)&tWy, g_Wy);  cudaGetSymbolAddress((void**)&tWx, g_Wx);
    cudaGetSymbolAddress((void**)&tWo, g_Wo);  cudaGetSymbolAddress((void**)&tWg, g_Wg);
    cudaGetSymbolAddress((void**)&tWu, g_Wu);  cudaGetSymbolAddress((void**)&tWd, g_Wd);

    cudaFuncSetAttribute(gemm_mma<0>, cudaFuncAttributeMaxDynamicSharedMemorySize, GM_SMEM);
    cudaFuncSetAttribute(gemm_mma<1>, cudaFuncAttributeMaxDynamicSharedMemorySize, GM_SMEM);
    cudaFuncSetAttribute(gemm_mma<2>, cudaFuncAttributeMaxDynamicSharedMemorySize, GM_SMEM);
    cudaFuncSetAttribute(gemm_mma<3>, cudaFuncAttributeMaxDynamicSharedMemorySize, GM_SMEM);

    const int EW = 256;
    const size_t nbsd_blocks = (NBSD + EW - 1) / EW;
    float* hlast = (out_size >= (int)(NBSD + (size_t)B * D)) ? (out + NBSD) : nullptr;

    // ---- weight transpose to fp16 (every call; deterministic) ----
    dim3 tb(32, 8);
    trans_half<<<dim3(D / 32, D / 32), tb>>>(Wy,   tWy, D, D);
    trans_half<<<dim3(D / 32, D / 32), tb>>>(Wx,   tWx, D, D);
    trans_half<<<dim3(D / 32, D / 32), tb>>>(Wout, tWo, D, D);
    trans_half<<<dim3(F / 32, D / 32), tb>>>(Wg,   tWg, D, F);
    trans_half<<<dim3(F / 32, D / 32), tb>>>(Wu,   tWu, D, F);
    trans_half<<<dim3(D / 32, F / 32), tb>>>(Wd,   tWd, F, D);

    // ---- temporal pre-norm (split output) ----
    rmsnorm_split<<<BS, 256>>>(x, r1w, nH, nL);

    // ---- y = gelu(normed @ W_y); xb = normed @ W_x ----
    dim3 gDD(D / 256, BS / 128);
    gemm_mma<1><<<gDD, 256, GM_SMEM>>>(nH, nL, tWy, y,  nullptr, nullptr, nullptr, D, D);
    gemm_mma<0><<<gDD, 256, GM_SMEM>>>(nH, nL, tWx, xb, nullptr, nullptr, nullptr, D, D);

    // ---- causal conv ----
    conv_kernel<<<(unsigned)nbsd_blocks, EW>>>(xb, cw, cb, xc);

    // ---- gate GEMMs (SIMT fp32; tiny) ----
    dim3 gGate(HD / 128, BS / 128, H);
    gemm_tpl<<<gGate, 256>>>(xc, agw, rlin, BS, HD, HD, D, HD, D,
                             HD, (long long)HD * HD, HD);
    gemm_tpl<<<gGate, 256>>>(xc, igw, ilin, BS, HD, HD, D, HD, D,
                             HD, (long long)HD * HD, HD);

    // ---- gate pointwise -> a, bx ----
    gate_kernel<<<(unsigned)nbsd_blocks, EW>>>(rlin, ilin, xc, agb, igb, apar, ga, gb);

    // ---- linear recurrence ----
    scan_kernel<<<(B * D + 255) / 256, 256>>>(ga, gb, h0, lru, hlast);

    // ---- z = y * lru (split fp16) ----
    mul_split<<<(unsigned)nbsd_blocks, EW>>>(y, lru, zH, zL, NBSD);

    // ---- residual = z @ W_out + x ----
    gemm_mma<2><<<gDD, 256, GM_SMEM>>>(zH, zL, tWo, resid, x, nullptr, nullptr, D, D);

    // ---- second norm (split) ----
    rmsnorm_split<<<BS, 256>>>(resid, r2w, n2H, n2L);

    // ---- MLP: G = gelu(n2 @ Wg); gu = (n2 @ Wu) * G  (fused split epilogue) ----
    dim3 gDF(F / 256, BS / 128);
    gemm_mma<1><<<gDF, 256, GM_SMEM>>>(n2H, n2L, tWg, G, nullptr, nullptr, nullptr, F, D);
    gemm_mma<3><<<gDF, 256, GM_SMEM>>>(n2H, n2L, tWu, nullptr, G, guH, guL, F, D);

    // ---- out = gu @ W_down + residual ----
    gemm_mma<2><<<gDD, 256, GM_SMEM>>>(guH, guL, tWd, out, resid, nullptr, nullptr, D, F);
}

// round 6
// speedup vs baseline: 4.7333x; 1.3025x over previous
#include <cuda_runtime.h>
#include <cuda.h>
#include <cuda_fp16.h>
#include <math.h>
#include <stdint.h>
#include <dlfcn.h>

// ---------------- problem constants ----------------
namespace hk {
constexpr int B  = 2;
constexpr int S  = 2048;
constexpr int D  = 2048;
constexpr int H  = 16;
constexpr int HD = 128;
constexpr int F  = 8192;
constexpr int BS = B * S;                     // 4096 rows
constexpr size_t NBSD = (size_t)BS * D;       // 8,388,608
constexpr size_t NBSF = (size_t)BS * F;       // 33,554,432
constexpr size_t NDD  = (size_t)D * D;
constexpr size_t NDF  = (size_t)D * F;
}

constexpr int SC_NC = 16;                      // scan chunks
constexpr int SC_L  = hk::S / SC_NC;           // 128 steps per chunk

// ---------------- scratch: fp32 intermediates ----------------
__device__ float g_y     [hk::NBSD];
__device__ float g_xb    [hk::NBSD];
__device__ float g_xc    [hk::NBSD];
__device__ float g_rlin  [hk::NBSD];
__device__ float g_ilin  [hk::NBSD];
__device__ float g_hloc  [hk::NBSD];
__device__ float g_acum  [hk::NBSD];
__device__ float g_resid [hk::NBSD];
__device__ float g_G     [hk::NBSF];
__device__ float g_carry [hk::B * hk::D * SC_NC];

// ---------------- scratch: fp16 hi/lo split activations ----------------
__device__ __half g_nH [hk::NBSD], g_nL [hk::NBSD];
__device__ __half g_zH [hk::NBSD], g_zL [hk::NBSD];
__device__ __half g_n2H[hk::NBSD], g_n2L[hk::NBSD];
__device__ __half g_guH[hk::NBSF], g_guL[hk::NBSF];

// ---------------- scratch: fp16 transposed weights [N,K] ----------------
__device__ __half g_Wy[hk::NDD];
__device__ __half g_Wx[hk::NDD];
__device__ __half g_Wo[hk::NDD];
__device__ __half g_Wg[hk::NDF];
__device__ __half g_Wu[hk::NDF];
__device__ __half g_Wd[hk::NDF];

// ---------------- helpers ----------------
__device__ __forceinline__ float gelu_tanh(float x) {
    float x3 = x * x * x;
    return 0.5f * x * (1.0f + tanhf(0.7978845608028654f * (x + 0.044715f * x3)));
}

__device__ __forceinline__ uint32_t s2u(const void* p) {
    uint32_t a;
    asm("{ .reg .u64 t; cvta.to.shared.u64 t, %1; cvt.u32.u64 %0, t; }" : "=r"(a) : "l"(p));
    return a;
}

__device__ __forceinline__ void ldmx4(uint32_t* r, uint32_t a) {
    asm volatile("ldmatrix.sync.aligned.m8n8.x4.shared.b16 {%0,%1,%2,%3}, [%4];"
                 : "=r"(r[0]), "=r"(r[1]), "=r"(r[2]), "=r"(r[3]) : "r"(a));
}

__device__ __forceinline__ void mma16816(float* c, const uint32_t* a, const uint32_t* b) {
    asm volatile(
        "mma.sync.aligned.m16n8k16.row.col.f32.f16.f16.f32 "
        "{%0,%1,%2,%3}, {%4,%5,%6,%7}, {%8,%9}, {%0,%1,%2,%3};"
        : "+f"(c[0]), "+f"(c[1]), "+f"(c[2]), "+f"(c[3])
        : "r"(a[0]), "r"(a[1]), "r"(a[2]), "r"(a[3]), "r"(b[0]), "r"(b[1]));
}

__device__ __forceinline__ void split2h(float v, __half& h, __half& l) {
    h = __float2half_rn(v);
    l = __float2half_rn(v - __half2float(h));
}

__device__ __forceinline__ void mbar_init(uint32_t mbar, uint32_t cnt) {
    asm volatile("mbarrier.init.shared.b64 [%0], %1;" :: "r"(mbar), "r"(cnt) : "memory");
}

__device__ __forceinline__ void mbar_expect_tx(uint32_t mbar, uint32_t bytes) {
    asm volatile("mbarrier.arrive.expect_tx.shared.b64 _, [%0], %1;"
                 :: "r"(mbar), "r"(bytes) : "memory");
}

__device__ __forceinline__ void mbar_wait(uint32_t mbar, uint32_t phase) {
    asm volatile(
        "{\n\t.reg .pred P;\n\t"
        "WAIT_%=:\n\t"
        "mbarrier.try_wait.parity.shared.b64 P, [%0], %1, 10000000;\n\t"
        "@P bra.uni DONE_%=;\n\t"
        "bra.uni WAIT_%=;\n\t"
        "DONE_%=:\n\t}"
        :: "r"(mbar), "r"(phase) : "memory");
}

__device__ __forceinline__ void tma2d(uint32_t dst, const CUtensorMap* map,
                                      int cx, int cy, uint32_t mbar) {
    asm volatile(
        "cp.async.bulk.tensor.2d.shared::cluster.global.tile.mbarrier::complete_tx::bytes "
        "[%0], [%1, {%2, %3}], [%4];"
        :: "r"(dst), "l"(map), "r"(cx), "r"(cy), "r"(mbar) : "memory");
}

// =====================================================================
// fp16x2 tensor-core GEMM, TMA loads (SW64), mbarrier 5-stage pipeline.
//   C[M,N](fp32) = (Ah+Al)[M,K] @ B[N,K]^T
// CTA tile 128x256, warp tile 64x64 (8 warps 2x4), BK=32.
// EPI: 0 none, 1 tanh-gelu, 2 add aux(fp32),
//      3 multiply by aux(fp32) and write split fp16 (OH/OL).
// =====================================================================
constexpr int GT_NSTG  = 5;
constexpr int GT_TA    = 128 * 64;              // 8192 B per A matrix tile
constexpr int GT_TB    = 256 * 64;              // 16384 B for the B tile
constexpr int GT_STAGE = 2 * GT_TA + GT_TB;     // 32768 B
constexpr int GT_HDR   = 1024;
constexpr int GT_SMEM  = GT_HDR + GT_NSTG * GT_STAGE;   // 164864 B

template<int EPI>
__global__ void __launch_bounds__(256, 1)
gemm_tma(const __grid_constant__ CUtensorMap mAh,
         const __grid_constant__ CUtensorMap mAl,
         const __grid_constant__ CUtensorMap mB,
         float* __restrict__ C, const float* __restrict__ aux,
         __half* __restrict__ OH, __half* __restrict__ OL,
         int N, int K)
{
    extern __shared__ __align__(1024) char smem[];
    const uint32_t sb    = s2u(smem);
    const uint32_t tiles = sb + GT_HDR;

    const int tid  = threadIdx.x;
    const int lane = tid & 31;
    const int wid  = tid >> 5;
    const int wm   = wid >> 2;        // 0..1  -> 64-row slab
    const int wn   = wid & 3;         // 0..3  -> 64-col slab
    const int row0 = blockIdx.y * 128;
    const int col0 = blockIdx.x * 256;
    const int KB   = K >> 5;          // BK = 32

    if (tid == 0) {
        #pragma unroll
        for (int s = 0; s < GT_NSTG; s++) mbar_init(sb + s * 8, 1);
    }
    __syncthreads();

    // precompute per-fragment row offsets + swizzle masks
    uint32_t arow[4], axm[4], brow[4], bxm[4];
    #pragma unroll
    for (int im = 0; im < 4; im++) {
        int r = wm * 64 + im * 16 + (lane & 15);
        arow[im] = (uint32_t)(r * 64);
        axm[im]  = (uint32_t)((r & 6) << 3);
    }
    #pragma unroll
    for (int ip = 0; ip < 4; ip++) {
        int r = wn * 64 + ip * 16 + (lane & 7) + ((lane >> 4) & 1) * 8;
        brow[ip] = (uint32_t)(r * 64);
        bxm[ip]  = (uint32_t)((r & 6) << 3);
    }
    const uint32_t acol = (uint32_t)((lane >> 4) * 16);
    const uint32_t bcol = (uint32_t)(((lane >> 3) & 1) * 16);

    float acc[4][8][4];
    #pragma unroll
    for (int im = 0; im < 4; im++)
        #pragma unroll
        for (int in = 0; in < 8; in++)
            #pragma unroll
            for (int q = 0; q < 4; q++) acc[im][in][q] = 0.0f;

    auto issue = [&](int kb) {
        int slot = kb % GT_NSTG;
        uint32_t bar = sb + slot * 8;
        uint32_t st  = tiles + (uint32_t)slot * GT_STAGE;
        mbar_expect_tx(bar, (uint32_t)GT_STAGE);
        tma2d(st,             &mAh, kb * 32, row0, bar);
        tma2d(st + GT_TA,     &mAl, kb * 32, row0, bar);
        tma2d(st + 2 * GT_TA, &mB,  kb * 32, col0, bar);
    };

    if (tid == 0) {
        #pragma unroll
        for (int s = 0; s < GT_NSTG - 1; s++) issue(s);
    }

    for (int kb = 0; kb < KB; kb++) {
        int slot = kb % GT_NSTG;
        mbar_wait(sb + slot * 8, (uint32_t)((kb / GT_NSTG) & 1));

        const uint32_t sA  = tiles + (uint32_t)slot * GT_STAGE;
        const uint32_t sAl = sA + GT_TA;
        const uint32_t sB  = sA + 2 * GT_TA;

        #pragma unroll
        for (int kk = 0; kk < 2; kk++) {
            uint32_t ahf[4][4], alf[4][4], bf[8][2];
            #pragma unroll
            for (int im = 0; im < 4; im++) {
                uint32_t rest = (acol + (uint32_t)(kk * 32)) ^ axm[im];
                ldmx4(ahf[im], sA  + arow[im] + rest);
                ldmx4(alf[im], sAl + arow[im] + rest);
            }
            #pragma unroll
            for (int ip = 0; ip < 4; ip++) {
                uint32_t rest = (bcol + (uint32_t)(kk * 32)) ^ bxm[ip];
                uint32_t r4[4];
                ldmx4(r4, sB + brow[ip] + rest);
                bf[2 * ip + 0][0] = r4[0]; bf[2 * ip + 0][1] = r4[1];
                bf[2 * ip + 1][0] = r4[2]; bf[2 * ip + 1][1] = r4[3];
            }
            #pragma unroll
            for (int im = 0; im < 4; im++)
                #pragma unroll
                for (int in = 0; in < 8; in++)
                    mma16816(acc[im][in], ahf[im], bf[in]);
            #pragma unroll
            for (int im = 0; im < 4; im++)
                #pragma unroll
                for (int in = 0; in < 8; in++)
                    mma16816(acc[im][in], alf[im], bf[in]);
        }
        __syncthreads();
        int nk = kb + GT_NSTG - 1;
        if (nk < KB && tid == 0) issue(nk);
    }

    // ---- epilogue ----
    const int gid = lane >> 2, t4 = lane & 3;
    #pragma unroll
    for (int im = 0; im < 4; im++) {
        #pragma unroll
        for (int in = 0; in < 8; in++) {
            int r = row0 + wm * 64 + im * 16 + gid;
            int c = col0 + wn * 64 + in * 8 + t4 * 2;
            #pragma unroll
            for (int half = 0; half < 2; half++) {
                int rr = r + half * 8;
                float v0 = acc[im][in][half * 2 + 0];
                float v1 = acc[im][in][half * 2 + 1];
                if (EPI == 1) { v0 = gelu_tanh(v0); v1 = gelu_tanh(v1); }
                if (EPI == 2) {
                    float2 a2 = *reinterpret_cast<const float2*>(aux + (size_t)rr * N + c);
                    v0 += a2.x; v1 += a2.y;
                }
                if (EPI == 3) {
                    float2 a2 = *reinterpret_cast<const float2*>(aux + (size_t)rr * N + c);
                    v0 *= a2.x; v1 *= a2.y;
                    __half h0, l0, h1, l1;
                    split2h(v0, h0, l0); split2h(v1, h1, l1);
                    __half2 hp; hp.x = h0; hp.y = h1;
                    __half2 lp; lp.x = l0; lp.y = l1;
                    *reinterpret_cast<__half2*>(OH + (size_t)rr * N + c) = hp;
                    *reinterpret_cast<__half2*>(OL + (size_t)rr * N + c) = lp;
                } else {
                    float2 o; o.x = v0; o.y = v1;
                    *reinterpret_cast<float2*>(C + (size_t)rr * N + c) = o;
                }
            }
        }
    }
}

// =====================================================================
// transpose to fp16: W[K,N] fp32 -> Wt[N,K] fp16
// =====================================================================
__global__ void trans_half(const float* __restrict__ W, __half* __restrict__ Wt,
                           int K, int N)
{
    __shared__ float t[32][33];
    int n0 = blockIdx.x * 32, k0 = blockIdx.y * 32;
    int tx = threadIdx.x, ty = threadIdx.y;   // 32 x 8
    #pragma unroll
    for (int i = 0; i < 32; i += 8)
        t[ty + i][tx] = W[(size_t)(k0 + ty + i) * N + (n0 + tx)];
    __syncthreads();
    #pragma unroll
    for (int i = 0; i < 32; i += 8)
        Wt[(size_t)(n0 + ty + i) * K + (k0 + tx)] = __float2half_rn(t[tx][ty + i]);
}

// ---------------- rmsnorm with fp16 hi/lo split output ----------------
__global__ void rmsnorm_split(const float* __restrict__ x, const float* __restrict__ w,
                              __half* __restrict__ hi, __half* __restrict__ lo)
{
    using namespace hk;
    const int row = blockIdx.x;
    const float* xr = x + (size_t)row * D;
    float ss = 0.0f;
    for (int d = threadIdx.x; d < D; d += 256) { float v = xr[d]; ss += v * v; }
    __shared__ float red[8];
    #pragma unroll
    for (int o = 16; o > 0; o >>= 1) ss += __shfl_down_sync(0xffffffffu, ss, o);
    if ((threadIdx.x & 31) == 0) red[threadIdx.x >> 5] = ss;
    __syncthreads();
    if (threadIdx.x < 8) {
        float v = red[threadIdx.x];
        #pragma unroll
        for (int o = 4; o > 0; o >>= 1) v += __shfl_down_sync(0xffu, v, o);
        if (threadIdx.x == 0) red[0] = v;
    }
    __syncthreads();
    const float scale = rsqrtf(red[0] / (float)D + 1e-6f);
    size_t base = (size_t)row * D;
    for (int d = threadIdx.x; d < D; d += 256) {
        float v = xr[d] * scale * w[d];
        __half h, l; split2h(v, h, l);
        hi[base + d] = h; lo[base + d] = l;
    }
}

// ---------------- causal depthwise conv, kernel 4 ----------------
__global__ void conv_kernel(const float* __restrict__ xb, const float* __restrict__ cw,
                            const float* __restrict__ cb, float* __restrict__ xc)
{
    using namespace hk;
    size_t idx = (size_t)blockIdx.x * blockDim.x + threadIdx.x;
    if (idx >= NBSD) return;
    int d = (int)(idx % D);
    int s = (int)((idx / D) % S);
    float acc = cb[d];
    #pragma unroll
    for (int k = 0; k < 4; k++) {
        int ss = s + k - 3;
        if (ss >= 0) acc = fmaf(cw[k * D + d], xb[idx + (size_t)(k - 3) * D], acc);
    }
    xc[idx] = acc;
}

// ---------------- SIMT fp32 GEMM (gates only; small) ----------------
__global__ void __launch_bounds__(256)
gemm_tpl(const float* __restrict__ A, const float* __restrict__ Bm,
         float* __restrict__ C,
         int M, int N, int K, int lda, int ldb, int ldc,
         long long sA, long long sB, long long sC)
{
    __shared__ float As[8][128];
    __shared__ float Bs[8][128];
    A  += (size_t)blockIdx.z * sA;
    Bm += (size_t)blockIdx.z * sB;
    C  += (size_t)blockIdx.z * sC;
    const int tid  = threadIdx.x;
    const int row0 = blockIdx.y * 128;
    const int col0 = blockIdx.x * 128;
    const int aRow = tid >> 1, aCol = (tid & 1) * 4;
    const int bRow = tid >> 5, bCol = (tid & 31) * 4;
    const int ty = tid >> 4, tx = tid & 15;
    float acc[8][8];
    #pragma unroll
    for (int i = 0; i < 8; i++)
        #pragma unroll
        for (int j = 0; j < 8; j++) acc[i][j] = 0.0f;
    for (int k0 = 0; k0 < K; k0 += 8) {
        float4 av = *reinterpret_cast<const float4*>(&A[(size_t)(row0 + aRow) * lda + (k0 + aCol)]);
        float4 bv = *reinterpret_cast<const float4*>(&Bm[(size_t)(k0 + bRow) * ldb + (col0 + bCol)]);
        As[aCol + 0][aRow] = av.x; As[aCol + 1][aRow] = av.y;
        As[aCol + 2][aRow] = av.z; As[aCol + 3][aRow] = av.w;
        *reinterpret_cast<float4*>(&Bs[bRow][bCol]) = bv;
        __syncthreads();
        #pragma unroll
        for (int k = 0; k < 8; k++) {
            float ra[8], rb[8];
            #pragma unroll
            for (int i = 0; i < 8; i++) ra[i] = As[k][ty * 8 + i];
            #pragma unroll
            for (int j = 0; j < 8; j++) rb[j] = Bs[k][tx * 8 + j];
            #pragma unroll
            for (int i = 0; i < 8; i++)
                #pragma unroll
                for (int j = 0; j < 8; j++)
                    acc[i][j] = fmaf(ra[i], rb[j], acc[i][j]);
        }
        __syncthreads();
    }
    #pragma unroll
    for (int i = 0; i < 8; i++) {
        int r = row0 + ty * 8 + i;
        #pragma unroll
        for (int j = 0; j < 8; j += 4) {
            int c = col0 + tx * 8 + j;
            float4 v;
            v.x = acc[i][j]; v.y = acc[i][j + 1]; v.z = acc[i][j + 2]; v.w = acc[i][j + 3];
            *reinterpret_cast<float4*>(&C[(size_t)r * ldc + c]) = v;
        }
    }
}

// ---------------- chunked parallel RG-LRU scan ----------------
// pass1: per (b, chunk, d) — gates inline + local scan + cumulative a
__global__ void scan_pass1(const float* __restrict__ rlin, const float* __restrict__ ilin,
                           const float* __restrict__ xc, const float* __restrict__ ab,
                           const float* __restrict__ ib, const float* __restrict__ apar,
                           float* __restrict__ hloc, float* __restrict__ acum)
{
    using namespace hk;
    int t = blockIdx.x * blockDim.x + threadIdx.x;
    if (t >= B * SC_NC * D) return;
    int d = t % D;
    int c = (t / D) % SC_NC;
    int b = t / (D * SC_NC);
    float sp  = log1pf(expf(-apar[d]));
    float ab_ = ab[d], ib_ = ib[d];
    float h = 0.0f, A = 1.0f;
    size_t g = ((size_t)b * S + (size_t)c * SC_L) * D + d;
    for (int i = 0; i < SC_L; i++, g += D) {
        float r  = 1.0f / (1.0f + expf(-(rlin[g] + ab_)));
        float ii = 1.0f / (1.0f + expf(-(ilin[g] + ib_)));
        float la = -8.0f * r * sp;
        float a  = expf(la);
        float mult = sqrtf(fmaxf(1.0f - expf(2.0f * la), 0.0f));
        float bt = mult * ii * xc[g];
        h = fmaf(a, h, bt);
        A *= a;
        hloc[g] = h;
        acum[g] = A;
    }
}

// pass2: per (b,d) — chunk carries + h_last
__global__ void scan_pass2(const float* __restrict__ hloc, const float* __restrict__ acum,
                           const float* __restrict__ h0, float* __restrict__ carry,
                           float* __restrict__ hlast)
{
    using namespace hk;
    int ch = blockIdx.x * blockDim.x + threadIdx.x;
    if (ch >= B * D) return;
    int b = ch / D, d = ch % D;
    float cur = h0[ch];
    for (int c = 0; c < SC_NC; c++) {
        carry[((size_t)b * SC_NC + c) * D + d] = cur;
        size_t ge = ((size_t)b * S + (size_t)c * SC_L + SC_L - 1) * D + d;
        cur = fmaf(acum[ge], cur, hloc[ge]);
    }
    if (hlast) hlast[ch] = cur;
}

// pass3: apply carry, multiply by y, write split fp16
__global__ void scan_pass3(const float* __restrict__ hloc, const float* __restrict__ acum,
                           const float* __restrict__ carry, const float* __restrict__ y,
                           __half* __restrict__ zH, __half* __restrict__ zL)
{
    using namespace hk;
    size_t g = (size_t)blockIdx.x * blockDim.x + threadIdx.x;
    if (g >= NBSD) return;
    int d = (int)(g % D);
    int s = (int)((g / D) % S);
    int b = (int)(g / ((size_t)S * D));
    int c = s / SC_L;
    float cr = carry[((size_t)b * SC_NC + c) * D + d];
    float h = fmaf(acum[g], cr, hloc[g]);
    float v = y[g] * h;
    __half hh, ll; split2h(v, hh, ll);
    zH[g] = hh; zL[g] = ll;
}

// =====================================================================
// host-side tensormap encoding (driver symbol via dlsym; no -lcuda dep)
// =====================================================================
typedef CUresult (*EncodeFn)(CUtensorMap*, CUtensorMapDataType, cuuint32_t, void*,
                             const cuuint64_t*, const cuuint64_t*, const cuuint32_t*,
                             const cuuint32_t*, CUtensorMapInterleave, CUtensorMapSwizzle,
                             CUtensorMapL2promotion, CUtensorMapFloatOOBfill);

static EncodeFn get_encode() {
    static EncodeFn fn = nullptr;
    if (!fn) {
        fn = (EncodeFn)dlsym(RTLD_DEFAULT, "cuTensorMapEncodeTiled");
        if (!fn) {
            void* h = dlopen("libcuda.so.1", RTLD_LAZY | RTLD_GLOBAL);
            if (h) fn = (EncodeFn)dlsym(h, "cuTensorMapEncodeTiled");
        }
    }
    return fn;
}

static void enc_map(CUtensorMap* m, void* ptr, uint64_t K, uint64_t ROWS, uint32_t boxRows) {
    cuuint64_t dims[2]    = {K, ROWS};
    cuuint64_t strides[1] = {K * 2};
    cuuint32_t box[2]     = {32, boxRows};
    cuuint32_t es[2]      = {1, 1};
    get_encode()(m, CU_TENSOR_MAP_DATA_TYPE_FLOAT16, 2, ptr, dims, strides, box, es,
                 CU_TENSOR_MAP_INTERLEAVE_NONE, CU_TENSOR_MAP_SWIZZLE_64B,
                 CU_TENSOR_MAP_L2_PROMOTION_L2_128B, CU_TENSOR_MAP_FLOAT_OOB_FILL_NONE);
}

// ---------------- launch ----------------
extern "C" void kernel_launch(void* const* d_in, const int* in_sizes, int n_in,
                              void* d_out, int out_size)
{
    using namespace hk;
    const float* x    = (const float*)d_in[0];
    const float* h0   = (const float*)d_in[1];
    const float* r1w  = (const float*)d_in[2];
    const float* r2w  = (const float*)d_in[3];
    const float* Wx   = (const float*)d_in[4];
    const float* Wy   = (const float*)d_in[5];
    const float* cw   = (const float*)d_in[6];
    const float* cb   = (const float*)d_in[7];
    const float* apar = (const float*)d_in[8];
    const float* igw  = (const float*)d_in[9];
    const float* igb  = (const float*)d_in[10];
    const float* agw  = (const float*)d_in[11];
    const float* agb  = (const float*)d_in[12];
    const float* Wout = (const float*)d_in[13];
    const float* Wg   = (const float*)d_in[14];
    const float* Wu   = (const float*)d_in[15];
    const float* Wd   = (const float*)d_in[16];
    float* out = (float*)d_out;

    float *y, *xb, *xc, *rlin, *ilin, *hloc, *acum, *resid, *G, *carry;
    cudaGetSymbolAddress((void**)&y,     g_y);
    cudaGetSymbolAddress((void**)&xb,    g_xb);
    cudaGetSymbolAddress((void**)&xc,    g_xc);
    cudaGetSymbolAddress((void**)&rlin,  g_rlin);
    cudaGetSymbolAddress((void**)&ilin,  g_ilin);
    cudaGetSymbolAddress((void**)&hloc,  g_hloc);
    cudaGetSymbolAddress((void**)&acum,  g_acum);
    cudaGetSymbolAddress((void**)&resid, g_resid);
    cudaGetSymbolAddress((void**)&G,     g_G);
    cudaGetSymbolAddress((void**)&carry, g_carry);

    __half *nH,*nL,*zH,*zL,*n2H,*n2L,*guH,*guL;
    __half *tWy,*tWx,*tWo,*tWg,*tWu,*tWd;
    cudaGetSymbolAddress((void**)&nH,  g_nH);  cudaGetSymbolAddress((void**)&nL,  g_nL);
    cudaGetSymbolAddress((void**)&zH,  g_zH);  cudaGetSymbolAddress((void**)&zL,  g_zL);
    cudaGetSymbolAddress((void**)&n2H, g_n2H); cudaGetSymbolAddress((void**)&n2L, g_n2L);
    cudaGetSymbolAddress((void**)&guH, g_guH); cudaGetSymbolAddress((void**)&guL, g_guL);
    cudaGetSymbolAddress((void**)&tWy, g_Wy);  cudaGetSymbolAddress((void**)&tWx, g_Wx);
    cudaGetSymbolAddress((void**)&tWo, g_Wo);  cudaGetSymbolAddress((void**)&tWg, g_Wg);
    cudaGetSymbolAddress((void**)&tWu, g_Wu);  cudaGetSymbolAddress((void**)&tWd, g_Wd);

    // ---- tensormaps (host-side; encoded at capture time, deterministic) ----
    static CUtensorMap mnH, mnL, mzH, mzL, mn2H, mn2L, mguH, mguL;
    static CUtensorMap mWy, mWx, mWo, mWg, mWu, mWd;
    enc_map(&mnH,  nH,  D, BS, 128);  enc_map(&mnL,  nL,  D, BS, 128);
    enc_map(&mzH,  zH,  D, BS, 128);  enc_map(&mzL,  zL,  D, BS, 128);
    enc_map(&mn2H, n2H, D, BS, 128);  enc_map(&mn2L, n2L, D, BS, 128);
    enc_map(&mguH, guH, F, BS, 128);  enc_map(&mguL, guL, F, BS, 128);
    enc_map(&mWy,  tWy, D, D, 256);   enc_map(&mWx,  tWx, D, D, 256);
    enc_map(&mWo,  tWo, D, D, 256);   enc_map(&mWg,  tWg, D, F, 256);
    enc_map(&mWu,  tWu, D, F, 256);   enc_map(&mWd,  tWd, F, D, 256);

    cudaFuncSetAttribute(gemm_tma<0>, cudaFuncAttributeMaxDynamicSharedMemorySize, GT_SMEM);
    cudaFuncSetAttribute(gemm_tma<1>, cudaFuncAttributeMaxDynamicSharedMemorySize, GT_SMEM);
    cudaFuncSetAttribute(gemm_tma<2>, cudaFuncAttributeMaxDynamicSharedMemorySize, GT_SMEM);
    cudaFuncSetAttribute(gemm_tma<3>, cudaFuncAttributeMaxDynamicSharedMemorySize, GT_SMEM);

    const int EW = 256;
    const size_t nbsd_blocks = (NBSD + EW - 1) / EW;
    float* hlast = (out_size >= (int)(NBSD + (size_t)B * D)) ? (out + NBSD) : nullptr;

    // ---- weight transpose to fp16 ----
    dim3 tb(32, 8);
    trans_half<<<dim3(D / 32, D / 32), tb>>>(Wy,   tWy, D, D);
    trans_half<<<dim3(D / 32, D / 32), tb>>>(Wx,   tWx, D, D);
    trans_half<<<dim3(D / 32, D / 32), tb>>>(Wout, tWo, D, D);
    trans_half<<<dim3(F / 32, D / 32), tb>>>(Wg,   tWg, D, F);
    trans_half<<<dim3(F / 32, D / 32), tb>>>(Wu,   tWu, D, F);
    trans_half<<<dim3(D / 32, F / 32), tb>>>(Wd,   tWd, F, D);

    // ---- temporal pre-norm (split output) ----
    rmsnorm_split<<<BS, 256>>>(x, r1w, nH, nL);

    // ---- y = gelu(normed @ W_y); xb = normed @ W_x ----
    dim3 gDD(D / 256, BS / 128);
    gemm_tma<1><<<gDD, 256, GT_SMEM>>>(mnH, mnL, mWy, y,  nullptr, nullptr, nullptr, D, D);
    gemm_tma<0><<<gDD, 256, GT_SMEM>>>(mnH, mnL, mWx, xb, nullptr, nullptr, nullptr, D, D);

    // ---- causal conv ----
    conv_kernel<<<(unsigned)nbsd_blocks, EW>>>(xb, cw, cb, xc);

    // ---- gate GEMMs (SIMT fp32; tiny) ----
    dim3 gGate(HD / 128, BS / 128, H);
    gemm_tpl<<<gGate, 256>>>(xc, agw, rlin, BS, HD, HD, D, HD, D,
                             HD, (long long)HD * HD, HD);
    gemm_tpl<<<gGate, 256>>>(xc, igw, ilin, BS, HD, HD, D, HD, D,
                             HD, (long long)HD * HD, HD);

    // ---- chunked scan (gates fused in pass1; y-mul + split fused in pass3) ----
    scan_pass1<<<(B * SC_NC * D + 255) / 256, 256>>>(rlin, ilin, xc, agb, igb, apar,
                                                     hloc, acum);
    scan_pass2<<<(B * D + 255) / 256, 256>>>(hloc, acum, h0, carry, hlast);
    scan_pass3<<<(unsigned)nbsd_blocks, EW>>>(hloc, acum, carry, y, zH, zL);

    // ---- residual = z @ W_out + x ----
    gemm_tma<2><<<gDD, 256, GT_SMEM>>>(mzH, mzL, mWo, resid, x, nullptr, nullptr, D, D);

    // ---- second norm (split) ----
    rmsnorm_split<<<BS, 256>>>(resid, r2w, n2H, n2L);

    // ---- MLP: G = gelu(n2 @ Wg); gu = (n2 @ Wu) * G ----
    dim3 gDF(F / 256, BS / 128);
    gemm_tma<1><<<gDF, 256, GT_SMEM>>>(mn2H, mn2L, mWg, G, nullptr, nullptr, nullptr, F, D);
    gemm_tma<3><<<gDF, 256, GT_SMEM>>>(mn2H, mn2L, mWu, nullptr, G, guH, guL, F, D);

    // ---- out = gu @ W_down + residual ----
    gemm_tma<2><<<gDD, 256, GT_SMEM>>>(mguH, mguL, mWd, out, resid, nullptr, nullptr, D, F);
}

// round 7
// speedup vs baseline: 5.0152x; 1.0596x over previous
#include <cuda_runtime.h>
#include <cuda.h>
#include <cuda_fp16.h>
#include <math.h>
#include <stdint.h>
#include <dlfcn.h>

// ---------------- problem constants ----------------
namespace hk {
constexpr int B  = 2;
constexpr int S  = 2048;
constexpr int D  = 2048;
constexpr int H  = 16;
constexpr int HD = 128;
constexpr int F  = 8192;
constexpr int BS = B * S;                     // 4096 rows
constexpr size_t NBSD = (size_t)BS * D;       // 8,388,608
constexpr size_t NBSF = (size_t)BS * F;       // 33,554,432
constexpr size_t NDD  = (size_t)D * D;
constexpr size_t NDF  = (size_t)D * F;
constexpr size_t NGW  = (size_t)H * HD * HD;  // 262,144
}

constexpr int SC_NC = 16;                      // scan chunks
constexpr int SC_L  = hk::S / SC_NC;           // 128 steps per chunk

// ---------------- scratch: fp32 intermediates ----------------
__device__ float g_y     [hk::NBSD];
__device__ float g_xb    [hk::NBSD];
__device__ float g_ga    [hk::NBSD];
__device__ float g_gb    [hk::NBSD];
__device__ float g_hloc  [hk::NBSD];
__device__ float g_acum  [hk::NBSD];
__device__ float g_resid [hk::NBSD];
__device__ float g_G     [hk::NBSF];
__device__ float g_carry [hk::B * hk::D * SC_NC];

// ---------------- scratch: fp16 hi/lo split activations ----------------
__device__ __half g_nH [hk::NBSD], g_nL [hk::NBSD];
__device__ __half g_xcH[hk::NBSD], g_xcL[hk::NBSD];
__device__ __half g_zH [hk::NBSD], g_zL [hk::NBSD];
__device__ __half g_n2H[hk::NBSD], g_n2L[hk::NBSD];
__device__ __half g_guH[hk::NBSF], g_guL[hk::NBSF];

// ---------------- scratch: fp16 transposed weights [N,K] ----------------
__device__ __half g_Wy[hk::NDD];
__device__ __half g_Wx[hk::NDD];
__device__ __half g_Wo[hk::NDD];
__device__ __half g_Wg[hk::NDF];
__device__ __half g_Wu[hk::NDF];
__device__ __half g_Wd[hk::NDF];
// gate weights, transposed per head [H][e][d], hi/lo split
__device__ __half g_aWH[hk::NGW], g_aWL[hk::NGW];
__device__ __half g_iWH[hk::NGW], g_iWL[hk::NGW];

// ---------------- helpers ----------------
__device__ __forceinline__ float gelu_tanh(float x) {
    float x3 = x * x * x;
    return 0.5f * x * (1.0f + tanhf(0.7978845608028654f * (x + 0.044715f * x3)));
}

__device__ __forceinline__ uint32_t s2u(const void* p) {
    uint32_t a;
    asm("{ .reg .u64 t; cvta.to.shared.u64 t, %1; cvt.u32.u64 %0, t; }" : "=r"(a) : "l"(p));
    return a;
}

__device__ __forceinline__ void ldmx4(uint32_t* r, uint32_t a) {
    asm volatile("ldmatrix.sync.aligned.m8n8.x4.shared.b16 {%0,%1,%2,%3}, [%4];"
                 : "=r"(r[0]), "=r"(r[1]), "=r"(r[2]), "=r"(r[3]) : "r"(a));
}

__device__ __forceinline__ void mma16816(float* c, const uint32_t* a, const uint32_t* b) {
    asm volatile(
        "mma.sync.aligned.m16n8k16.row.col.f32.f16.f16.f32 "
        "{%0,%1,%2,%3}, {%4,%5,%6,%7}, {%8,%9}, {%0,%1,%2,%3};"
        : "+f"(c[0]), "+f"(c[1]), "+f"(c[2]), "+f"(c[3])
        : "r"(a[0]), "r"(a[1]), "r"(a[2]), "r"(a[3]), "r"(b[0]), "r"(b[1]));
}

__device__ __forceinline__ void split2h(float v, __half& h, __half& l) {
    h = __float2half_rn(v);
    l = __float2half_rn(v - __half2float(h));
}

__device__ __forceinline__ void mbar_init(uint32_t mbar, uint32_t cnt) {
    asm volatile("mbarrier.init.shared.b64 [%0], %1;" :: "r"(mbar), "r"(cnt) : "memory");
}

__device__ __forceinline__ void mbar_expect_tx(uint32_t mbar, uint32_t bytes) {
    asm volatile("mbarrier.arrive.expect_tx.shared.b64 _, [%0], %1;"
                 :: "r"(mbar), "r"(bytes) : "memory");
}

__device__ __forceinline__ void mbar_wait(uint32_t mbar, uint32_t phase) {
    asm volatile(
        "{\n\t.reg .pred P;\n\t"
        "WAIT_%=:\n\t"
        "mbarrier.try_wait.parity.shared.b64 P, [%0], %1, 10000000;\n\t"
        "@P bra.uni DONE_%=;\n\t"
        "bra.uni WAIT_%=;\n\t"
        "DONE_%=:\n\t}"
        :: "r"(mbar), "r"(phase) : "memory");
}

__device__ __forceinline__ void tma2d(uint32_t dst, const CUtensorMap* map,
                                      int cx, int cy, uint32_t mbar) {
    asm volatile(
        "cp.async.bulk.tensor.2d.shared::cluster.global.tile.mbarrier::complete_tx::bytes "
        "[%0], [%1, {%2, %3}], [%4];"
        :: "r"(dst), "l"(map), "r"(cx), "r"(cy), "r"(mbar) : "memory");
}

// =====================================================================
// fp16x2 tensor-core GEMM, TMA loads (SW64), mbarrier 5-stage pipeline.
//   C[M,N](fp32) = (Ah+Al)[M,K] @ B[N,K]^T
// CTA tile 128x256, warp tile 64x64 (8 warps 2x4), BK=32.
// EPI: 0 none, 1 tanh-gelu, 2 add aux(fp32),
//      3 multiply by aux(fp32) and write split fp16 (OH/OL).
// =====================================================================
constexpr int GT_NSTG  = 5;
constexpr int GT_TA    = 128 * 64;              // 8192 B per A matrix tile
constexpr int GT_TB    = 256 * 64;              // 16384 B for the B tile
constexpr int GT_STAGE = 2 * GT_TA + GT_TB;     // 32768 B
constexpr int GT_HDR   = 1024;
constexpr int GT_SMEM  = GT_HDR + GT_NSTG * GT_STAGE;   // 164864 B

template<int EPI>
__global__ void __launch_bounds__(256, 1)
gemm_tma(const __grid_constant__ CUtensorMap mAh,
         const __grid_constant__ CUtensorMap mAl,
         const __grid_constant__ CUtensorMap mB,
         float* __restrict__ C, const float* __restrict__ aux,
         __half* __restrict__ OH, __half* __restrict__ OL,
         int N, int K)
{
    extern __shared__ __align__(1024) char smem[];
    const uint32_t sb    = s2u(smem);
    const uint32_t tiles = sb + GT_HDR;

    const int tid  = threadIdx.x;
    const int lane = tid & 31;
    const int wid  = tid >> 5;
    const int wm   = wid >> 2;
    const int wn   = wid & 3;
    const int row0 = blockIdx.y * 128;
    const int col0 = blockIdx.x * 256;
    const int KB   = K >> 5;

    if (tid == 0) {
        #pragma unroll
        for (int s = 0; s < GT_NSTG; s++) mbar_init(sb + s * 8, 1);
    }
    __syncthreads();

    uint32_t arow[4], axm[4], brow[4], bxm[4];
    #pragma unroll
    for (int im = 0; im < 4; im++) {
        int r = wm * 64 + im * 16 + (lane & 15);
        arow[im] = (uint32_t)(r * 64);
        axm[im]  = (uint32_t)((r & 6) << 3);
    }
    #pragma unroll
    for (int ip = 0; ip < 4; ip++) {
        int r = wn * 64 + ip * 16 + (lane & 7) + ((lane >> 4) & 1) * 8;
        brow[ip] = (uint32_t)(r * 64);
        bxm[ip]  = (uint32_t)((r & 6) << 3);
    }
    const uint32_t acol = (uint32_t)((lane >> 4) * 16);
    const uint32_t bcol = (uint32_t)(((lane >> 3) & 1) * 16);

    float acc[4][8][4];
    #pragma unroll
    for (int im = 0; im < 4; im++)
        #pragma unroll
        for (int in = 0; in < 8; in++)
            #pragma unroll
            for (int q = 0; q < 4; q++) acc[im][in][q] = 0.0f;

    auto issue = [&](int kb) {
        int slot = kb % GT_NSTG;
        uint32_t bar = sb + slot * 8;
        uint32_t st  = tiles + (uint32_t)slot * GT_STAGE;
        mbar_expect_tx(bar, (uint32_t)GT_STAGE);
        tma2d(st,             &mAh, kb * 32, row0, bar);
        tma2d(st + GT_TA,     &mAl, kb * 32, row0, bar);
        tma2d(st + 2 * GT_TA, &mB,  kb * 32, col0, bar);
    };

    if (tid == 0) {
        #pragma unroll
        for (int s = 0; s < GT_NSTG - 1; s++) issue(s);
    }

    for (int kb = 0; kb < KB; kb++) {
        int slot = kb % GT_NSTG;
        mbar_wait(sb + slot * 8, (uint32_t)((kb / GT_NSTG) & 1));

        const uint32_t sA  = tiles + (uint32_t)slot * GT_STAGE;
        const uint32_t sAl = sA + GT_TA;
        const uint32_t sB  = sA + 2 * GT_TA;

        #pragma unroll
        for (int kk = 0; kk < 2; kk++) {
            uint32_t ahf[4][4], alf[4][4], bf[8][2];
            #pragma unroll
            for (int im = 0; im < 4; im++) {
                uint32_t rest = (acol + (uint32_t)(kk * 32)) ^ axm[im];
                ldmx4(ahf[im], sA  + arow[im] + rest);
                ldmx4(alf[im], sAl + arow[im] + rest);
            }
            #pragma unroll
            for (int ip = 0; ip < 4; ip++) {
                uint32_t rest = (bcol + (uint32_t)(kk * 32)) ^ bxm[ip];
                uint32_t r4[4];
                ldmx4(r4, sB + brow[ip] + rest);
                bf[2 * ip + 0][0] = r4[0]; bf[2 * ip + 0][1] = r4[1];
                bf[2 * ip + 1][0] = r4[2]; bf[2 * ip + 1][1] = r4[3];
            }
            #pragma unroll
            for (int im = 0; im < 4; im++)
                #pragma unroll
                for (int in = 0; in < 8; in++)
                    mma16816(acc[im][in], ahf[im], bf[in]);
            #pragma unroll
            for (int im = 0; im < 4; im++)
                #pragma unroll
                for (int in = 0; in < 8; in++)
                    mma16816(acc[im][in], alf[im], bf[in]);
        }
        __syncthreads();
        int nk = kb + GT_NSTG - 1;
        if (nk < KB && tid == 0) issue(nk);
    }

    // ---- epilogue ----
    const int gid = lane >> 2, t4 = lane & 3;
    #pragma unroll
    for (int im = 0; im < 4; im++) {
        #pragma unroll
        for (int in = 0; in < 8; in++) {
            int r = row0 + wm * 64 + im * 16 + gid;
            int c = col0 + wn * 64 + in * 8 + t4 * 2;
            #pragma unroll
            for (int half = 0; half < 2; half++) {
                int rr = r + half * 8;
                float v0 = acc[im][in][half * 2 + 0];
                float v1 = acc[im][in][half * 2 + 1];
                if (EPI == 1) { v0 = gelu_tanh(v0); v1 = gelu_tanh(v1); }
                if (EPI == 2) {
                    float2 a2 = *reinterpret_cast<const float2*>(aux + (size_t)rr * N + c);
                    v0 += a2.x; v1 += a2.y;
                }
                if (EPI == 3) {
                    float2 a2 = *reinterpret_cast<const float2*>(aux + (size_t)rr * N + c);
                    v0 *= a2.x; v1 *= a2.y;
                    __half h0, l0, h1, l1;
                    split2h(v0, h0, l0); split2h(v1, h1, l1);
                    __half2 hp; hp.x = h0; hp.y = h1;
                    __half2 lp; lp.x = l0; lp.y = l1;
                    *reinterpret_cast<__half2*>(OH + (size_t)rr * N + c) = hp;
                    *reinterpret_cast<__half2*>(OL + (size_t)rr * N + c) = lp;
                } else {
                    float2 o; o.x = v0; o.y = v1;
                    *reinterpret_cast<float2*>(C + (size_t)rr * N + c) = o;
                }
            }
        }
    }
}

// =====================================================================
// gate_mma: per (128-row block, head) compute r/i pre-activations with
// fp16x2 split A (xc) and split weights, then full RG-LRU gate math in
// the epilogue; writes a (ga) and b (gb) fp32.
// Warp tile 64x32; both gates accumulated per warp. TMA single-phase load.
// =====================================================================
constexpr int GG_CH   = 8192;                 // one 128-row x 32-k chunk
constexpr int GG_MAT  = 4 * GG_CH;            // 32768 B per matrix (K=128)
constexpr int GG_HDR  = 1024;
constexpr int GG_SMEM = GG_HDR + 6 * GG_MAT;  // 197632 B

__global__ void __launch_bounds__(256, 1)
gate_mma(const __grid_constant__ CUtensorMap mXh,
         const __grid_constant__ CUtensorMap mXl,
         const __grid_constant__ CUtensorMap mWaH,
         const __grid_constant__ CUtensorMap mWaL,
         const __grid_constant__ CUtensorMap mWiH,
         const __grid_constant__ CUtensorMap mWiL,
         const float* __restrict__ ab, const float* __restrict__ ib,
         const float* __restrict__ apar,
         float* __restrict__ ga, float* __restrict__ gb)
{
    using namespace hk;
    extern __shared__ __align__(1024) char smem[];
    const uint32_t sb    = s2u(smem);
    const uint32_t tiles = sb + GG_HDR;

    const int tid  = threadIdx.x;
    const int lane = tid & 31;
    const int wid  = tid >> 5;
    const int wm   = wid >> 2;         // 0..1 -> 64-row slab
    const int wn   = wid & 3;          // 0..3 -> 32-col slab
    const int row0 = blockIdx.x * 128;
    const int h    = blockIdx.y;

    if (tid == 0) mbar_init(sb, 1);
    __syncthreads();

    if (tid == 0) {
        mbar_expect_tx(sb, (uint32_t)(6 * GG_MAT));
        #pragma unroll
        for (int c = 0; c < 4; c++) {
            int kx = c * 32;
            tma2d(tiles + 0 * GG_MAT + c * GG_CH, &mXh,  h * HD + kx, row0,   sb);
            tma2d(tiles + 1 * GG_MAT + c * GG_CH, &mXl,  h * HD + kx, row0,   sb);
            tma2d(tiles + 2 * GG_MAT + c * GG_CH, &mWaH, kx,          h * HD, sb);
            tma2d(tiles + 3 * GG_MAT + c * GG_CH, &mWaL, kx,          h * HD, sb);
            tma2d(tiles + 4 * GG_MAT + c * GG_CH, &mWiH, kx,          h * HD, sb);
            tma2d(tiles + 5 * GG_MAT + c * GG_CH, &mWiL, kx,          h * HD, sb);
        }
    }
    mbar_wait(sb, 0);
    __syncthreads();

    uint32_t arow[4], axm[4], brow[2], bxm[2];
    #pragma unroll
    for (int im = 0; im < 4; im++) {
        int r = wm * 64 + im * 16 + (lane & 15);
        arow[im] = (uint32_t)(r * 64);
        axm[im]  = (uint32_t)((r & 6) << 3);
    }
    #pragma unroll
    for (int ip = 0; ip < 2; ip++) {
        int r = wn * 32 + ip * 16 + (lane & 7) + ((lane >> 4) & 1) * 8;
        brow[ip] = (uint32_t)(r * 64);
        bxm[ip]  = (uint32_t)((r & 6) << 3);
    }
    const uint32_t acol = (uint32_t)((lane >> 4) * 16);
    const uint32_t bcol = (uint32_t)(((lane >> 3) & 1) * 16);

    float accR[4][4][4], accI[4][4][4];
    #pragma unroll
    for (int im = 0; im < 4; im++)
        #pragma unroll
        for (int in = 0; in < 4; in++)
            #pragma unroll
            for (int q = 0; q < 4; q++) { accR[im][in][q] = 0.0f; accI[im][in][q] = 0.0f; }

    #pragma unroll
    for (int c = 0; c < 4; c++) {
        const uint32_t sAh = tiles + 0 * GG_MAT + c * GG_CH;
        const uint32_t sAl = tiles + 1 * GG_MAT + c * GG_CH;
        const uint32_t sWa = tiles + 2 * GG_MAT + c * GG_CH;
        const uint32_t sWal= tiles + 3 * GG_MAT + c * GG_CH;
        const uint32_t sWi = tiles + 4 * GG_MAT + c * GG_CH;
        const uint32_t sWil= tiles + 5 * GG_MAT + c * GG_CH;
        #pragma unroll
        for (int kk = 0; kk < 2; kk++) {
            uint32_t ahf[4][4], alf[4][4];
            uint32_t waH[4][2], waL[4][2], wiH[4][2], wiL[4][2];
            #pragma unroll
            for (int im = 0; im < 4; im++) {
                uint32_t rest = (acol + (uint32_t)(kk * 32)) ^ axm[im];
                ldmx4(ahf[im], sAh + arow[im] + rest);
                ldmx4(alf[im], sAl + arow[im] + rest);
            }
            #pragma unroll
            for (int ip = 0; ip < 2; ip++) {
                uint32_t rest = (bcol + (uint32_t)(kk * 32)) ^ bxm[ip];
                uint32_t r4[4];
                ldmx4(r4, sWa + brow[ip] + rest);
                waH[2*ip][0]=r4[0]; waH[2*ip][1]=r4[1]; waH[2*ip+1][0]=r4[2]; waH[2*ip+1][1]=r4[3];
                ldmx4(r4, sWal + brow[ip] + rest);
                waL[2*ip][0]=r4[0]; waL[2*ip][1]=r4[1]; waL[2*ip+1][0]=r4[2]; waL[2*ip+1][1]=r4[3];
                ldmx4(r4, sWi + brow[ip] + rest);
                wiH[2*ip][0]=r4[0]; wiH[2*ip][1]=r4[1]; wiH[2*ip+1][0]=r4[2]; wiH[2*ip+1][1]=r4[3];
                ldmx4(r4, sWil + brow[ip] + rest);
                wiL[2*ip][0]=r4[0]; wiL[2*ip][1]=r4[1]; wiL[2*ip+1][0]=r4[2]; wiL[2*ip+1][1]=r4[3];
            }
            #pragma unroll
            for (int im = 0; im < 4; im++)
                #pragma unroll
                for (int in = 0; in < 4; in++) {
                    mma16816(accR[im][in], ahf[im], waH[in]);
                    mma16816(accR[im][in], alf[im], waH[in]);
                    mma16816(accR[im][in], ahf[im], waL[in]);
                    mma16816(accI[im][in], ahf[im], wiH[in]);
                    mma16816(accI[im][in], alf[im], wiH[in]);
                    mma16816(accI[im][in], ahf[im], wiL[in]);
                }
        }
    }

    // ---- gate epilogue ----
    const int gid = lane >> 2, t4 = lane & 3;
    #pragma unroll
    for (int in = 0; in < 4; in++) {
        int c0 = wn * 32 + in * 8 + t4 * 2;      // within-head d index (even)
        #pragma unroll
        for (int q = 0; q < 2; q++) {
            int col = c0 + q;
            int dd  = h * HD + col;
            float ab_ = ab[dd], ib_ = ib[dd];
            float sp  = log1pf(expf(-apar[dd]));
            // xc smem byte offset pieces for this column
            int cch = col >> 5;
            uint32_t cb = (uint32_t)((col & 31) * 2);
            uint32_t cbase = (uint32_t)(cch * GG_CH);
            #pragma unroll
            for (int im = 0; im < 4; im++) {
                #pragma unroll
                for (int half = 0; half < 2; half++) {
                    int row = wm * 64 + im * 16 + gid + half * 8;
                    float rv = accR[im][in][half * 2 + q] + ab_;
                    float iv = accI[im][in][half * 2 + q] + ib_;
                    float r  = 1.0f / (1.0f + expf(-rv));
                    float ii = 1.0f / (1.0f + expf(-iv));
                    float la = -8.0f * r * sp;
                    float a  = expf(la);
                    float mult = sqrtf(fmaxf(1.0f - expf(2.0f * la), 0.0f));
                    uint32_t off = cbase + (uint32_t)(row * 64)
                                 + ((cb & 48u) ^ (uint32_t)((row & 6) << 3)) + (cb & 15u);
                    float xcv = __half2float(*reinterpret_cast<const __half*>(
                                    smem + GG_HDR + off))
                              + __half2float(*reinterpret_cast<const __half*>(
                                    smem + GG_HDR + GG_MAT + off));
                    size_t g = (size_t)(row0 + row) * D + dd;
                    ga[g] = a;
                    gb[g] = mult * ii * xcv;
                }
            }
        }
    }
}

// =====================================================================
// vectorized transpose to fp16: W[K,N] fp32 -> Wt[N,K] fp16 (64x64 tiles)
// =====================================================================
__global__ void __launch_bounds__(256)
trans_half2(const float* __restrict__ W, __half* __restrict__ Wt, int K, int N)
{
    __shared__ float t[64][65];
    int n0 = blockIdx.x * 64, k0 = blockIdx.y * 64;
    int tid = threadIdx.x;
    int lr = tid >> 4;
    int lc = (tid & 15) * 4;
    #pragma unroll
    for (int i = 0; i < 4; i++) {
        int r = lr + i * 16;
        float4 v = *reinterpret_cast<const float4*>(&W[(size_t)(k0 + r) * N + n0 + lc]);
        t[r][lc] = v.x; t[r][lc + 1] = v.y; t[r][lc + 2] = v.z; t[r][lc + 3] = v.w;
    }
    __syncthreads();
    #pragma unroll
    for (int i = 0; i < 2; i++) {
        int task = tid + i * 256;
        int n  = task >> 3;
        int kg = (task & 7) * 8;
        __half h8[8];
        #pragma unroll
        for (int j = 0; j < 8; j++) h8[j] = __float2half_rn(t[kg + j][n]);
        *reinterpret_cast<uint4*>(&Wt[(size_t)(n0 + n) * K + k0 + kg]) =
            *reinterpret_cast<uint4*>(h8);
    }
}

// gate-weight transpose + hi/lo split: W[H][d][e] -> hi/lo [H][e][d]
__global__ void trans_gate(const float* __restrict__ W,
                           __half* __restrict__ hi, __half* __restrict__ lo)
{
    using namespace hk;
    __shared__ float t[32][33];
    int e0 = blockIdx.x * 32, d0 = blockIdx.y * 32, hh = blockIdx.z;
    int tx = threadIdx.x, ty = threadIdx.y;   // 32 x 8
    const float* Wh = W + (size_t)hh * HD * HD;
    #pragma unroll
    for (int i = 0; i < 32; i += 8)
        t[ty + i][tx] = Wh[(size_t)(d0 + ty + i) * HD + (e0 + tx)];
    __syncthreads();
    #pragma unroll
    for (int i = 0; i < 32; i += 8) {
        float v = t[tx][ty + i];
        size_t o = ((size_t)hh * HD + (e0 + ty + i)) * HD + (d0 + tx);
        __half a, b; split2h(v, a, b);
        hi[o] = a; lo[o] = b;
    }
}

// ---------------- rmsnorm with fp16 hi/lo split output ----------------
__global__ void rmsnorm_split(const float* __restrict__ x, const float* __restrict__ w,
                              __half* __restrict__ hi, __half* __restrict__ lo)
{
    using namespace hk;
    const int row = blockIdx.x;
    const float* xr = x + (size_t)row * D;
    float ss = 0.0f;
    for (int d = threadIdx.x; d < D; d += 256) { float v = xr[d]; ss += v * v; }
    __shared__ float red[8];
    #pragma unroll
    for (int o = 16; o > 0; o >>= 1) ss += __shfl_down_sync(0xffffffffu, ss, o);
    if ((threadIdx.x & 31) == 0) red[threadIdx.x >> 5] = ss;
    __syncthreads();
    if (threadIdx.x < 8) {
        float v = red[threadIdx.x];
        #pragma unroll
        for (int o = 4; o > 0; o >>= 1) v += __shfl_down_sync(0xffu, v, o);
        if (threadIdx.x == 0) red[0] = v;
    }
    __syncthreads();
    const float scale = rsqrtf(red[0] / (float)D + 1e-6f);
    size_t base = (size_t)row * D;
    for (int d = threadIdx.x; d < D; d += 256) {
        float v = xr[d] * scale * w[d];
        __half h, l; split2h(v, h, l);
        hi[base + d] = h; lo[base + d] = l;
    }
}

// ---------------- causal depthwise conv, kernel 4; split fp16 output ----------------
__global__ void conv_split(const float* __restrict__ xb, const float* __restrict__ cw,
                           const float* __restrict__ cb,
                           __half* __restrict__ xcH, __half* __restrict__ xcL)
{
    using namespace hk;
    size_t idx = (size_t)blockIdx.x * blockDim.x + threadIdx.x;
    if (idx >= NBSD) return;
    int d = (int)(idx % D);
    int s = (int)((idx / D) % S);
    float acc = cb[d];
    #pragma unroll
    for (int k = 0; k < 4; k++) {
        int ss = s + k - 3;
        if (ss >= 0) acc = fmaf(cw[k * D + d], xb[idx + (size_t)(k - 3) * D], acc);
    }
    __half h, l; split2h(acc, h, l);
    xcH[idx] = h; xcL[idx] = l;
}

// ---------------- chunked parallel RG-LRU scan ----------------
__global__ void scan_pass1(const float* __restrict__ ga, const float* __restrict__ gb,
                           float* __restrict__ hloc, float* __restrict__ acum)
{
    using namespace hk;
    int t = blockIdx.x * blockDim.x + threadIdx.x;
    if (t >= B * SC_NC * D) return;
    int d = t % D;
    int c = (t / D) % SC_NC;
    int b = t / (D * SC_NC);
    float h = 0.0f, A = 1.0f;
    size_t g = ((size_t)b * S + (size_t)c * SC_L) * D + d;
    for (int i = 0; i < SC_L; i++, g += D) {
        float a = ga[g];
        h = fmaf(a, h, gb[g]);
        A *= a;
        hloc[g] = h;
        acum[g] = A;
    }
}

__global__ void scan_pass2(const float* __restrict__ hloc, const float* __restrict__ acum,
                           const float* __restrict__ h0, float* __restrict__ carry,
                           float* __restrict__ hlast)
{
    using namespace hk;
    int ch = blockIdx.x * blockDim.x + threadIdx.x;
    if (ch >= B * D) return;
    int b = ch / D, d = ch % D;
    float cur = h0[ch];
    for (int c = 0; c < SC_NC; c++) {
        carry[((size_t)b * SC_NC + c) * D + d] = cur;
        size_t ge = ((size_t)b * S + (size_t)c * SC_L + SC_L - 1) * D + d;
        cur = fmaf(acum[ge], cur, hloc[ge]);
    }
    if (hlast) hlast[ch] = cur;
}

__global__ void scan_pass3(const float* __restrict__ hloc, const float* __restrict__ acum,
                           const float* __restrict__ carry, const float* __restrict__ y,
                           __half* __restrict__ zH, __half* __restrict__ zL)
{
    using namespace hk;
    size_t g = (size_t)blockIdx.x * blockDim.x + threadIdx.x;
    if (g >= NBSD) return;
    int d = (int)(g % D);
    int s = (int)((g / D) % S);
    int b = (int)(g / ((size_t)S * D));
    int c = s / SC_L;
    float cr = carry[((size_t)b * SC_NC + c) * D + d];
    float h = fmaf(acum[g], cr, hloc[g]);
    float v = y[g] * h;
    __half hh, ll; split2h(v, hh, ll);
    zH[g] = hh; zL[g] = ll;
}

// =====================================================================
// host-side tensormap encoding (driver symbol via dlsym)
// =====================================================================
typedef CUresult (*EncodeFn)(CUtensorMap*, CUtensorMapDataType, cuuint32_t, void*,
                             const cuuint64_t*, const cuuint64_t*, const cuuint32_t*,
                             const cuuint32_t*, CUtensorMapInterleave, CUtensorMapSwizzle,
                             CUtensorMapL2promotion, CUtensorMapFloatOOBfill);

static EncodeFn get_encode() {
    static EncodeFn fn = nullptr;
    if (!fn) {
        fn = (EncodeFn)dlsym(RTLD_DEFAULT, "cuTensorMapEncodeTiled");
        if (!fn) {
            void* h = dlopen("libcuda.so.1", RTLD_LAZY | RTLD_GLOBAL);
            if (h) fn = (EncodeFn)dlsym(h, "cuTensorMapEncodeTiled");
        }
    }
    return fn;
}

static void enc_map(CUtensorMap* m, void* ptr, uint64_t K, uint64_t ROWS, uint32_t boxRows) {
    cuuint64_t dims[2]    = {K, ROWS};
    cuuint64_t strides[1] = {K * 2};
    cuuint32_t box[2]     = {32, boxRows};
    cuuint32_t es[2]      = {1, 1};
    get_encode()(m, CU_TENSOR_MAP_DATA_TYPE_FLOAT16, 2, ptr, dims, strides, box, es,
                 CU_TENSOR_MAP_INTERLEAVE_NONE, CU_TENSOR_MAP_SWIZZLE_64B,
                 CU_TENSOR_MAP_L2_PROMOTION_L2_128B, CU_TENSOR_MAP_FLOAT_OOB_FILL_NONE);
}

// ---------------- launch ----------------
extern "C" void kernel_launch(void* const* d_in, const int* in_sizes, int n_in,
                              void* d_out, int out_size)
{
    using namespace hk;
    const float* x    = (const float*)d_in[0];
    const float* h0   = (const float*)d_in[1];
    const float* r1w  = (const float*)d_in[2];
    const float* r2w  = (const float*)d_in[3];
    const float* Wx   = (const float*)d_in[4];
    const float* Wy   = (const float*)d_in[5];
    const float* cw   = (const float*)d_in[6];
    const float* cb   = (const float*)d_in[7];
    const float* apar = (const float*)d_in[8];
    const float* igw  = (const float*)d_in[9];
    const float* igb  = (const float*)d_in[10];
    const float* agw  = (const float*)d_in[11];
    const float* agb  = (const float*)d_in[12];
    const float* Wout = (const float*)d_in[13];
    const float* Wg   = (const float*)d_in[14];
    const float* Wu   = (const float*)d_in[15];
    const float* Wd   = (const float*)d_in[16];
    float* out = (float*)d_out;

    float *y, *xb, *ga, *gb, *hloc, *acum, *resid, *G, *carry;
    cudaGetSymbolAddress((void**)&y,     g_y);
    cudaGetSymbolAddress((void**)&xb,    g_xb);
    cudaGetSymbolAddress((void**)&ga,    g_ga);
    cudaGetSymbolAddress((void**)&gb,    g_gb);
    cudaGetSymbolAddress((void**)&hloc,  g_hloc);
    cudaGetSymbolAddress((void**)&acum,  g_acum);
    cudaGetSymbolAddress((void**)&resid, g_resid);
    cudaGetSymbolAddress((void**)&G,     g_G);
    cudaGetSymbolAddress((void**)&carry, g_carry);

    __half *nH,*nL,*xcH,*xcL,*zH,*zL,*n2H,*n2L,*guH,*guL;
    __half *tWy,*tWx,*tWo,*tWg,*tWu,*tWd,*aWH,*aWL,*iWH,*iWL;
    cudaGetSymbolAddress((void**)&nH,  g_nH);  cudaGetSymbolAddress((void**)&nL,  g_nL);
    cudaGetSymbolAddress((void**)&xcH, g_xcH); cudaGetSymbolAddress((void**)&xcL, g_xcL);
    cudaGetSymbolAddress((void**)&zH,  g_zH);  cudaGetSymbolAddress((void**)&zL,  g_zL);
    cudaGetSymbolAddress((void**)&n2H, g_n2H); cudaGetSymbolAddress((void**)&n2L, g_n2L);
    cudaGetSymbolAddress((void**)&guH, g_guH); cudaGetSymbolAddress((void**)&guL, g_guL);
    cudaGetSymbolAddress((void**)&tWy, g_Wy);  cudaGetSymbolAddress((void**)&tWx, g_Wx);
    cudaGetSymbolAddress((void**)&tWo, g_Wo);  cudaGetSymbolAddress((void**)&tWg, g_Wg);
    cudaGetSymbolAddress((void**)&tWu, g_Wu);  cudaGetSymbolAddress((void**)&tWd, g_Wd);
    cudaGetSymbolAddress((void**)&aWH, g_aWH); cudaGetSymbolAddress((void**)&aWL, g_aWL);
    cudaGetSymbolAddress((void**)&iWH, g_iWH); cudaGetSymbolAddress((void**)&iWL, g_iWL);

    // ---- tensormaps ----
    static CUtensorMap mnH, mnL, mzH, mzL, mn2H, mn2L, mguH, mguL;
    static CUtensorMap mWy, mWx, mWo, mWg, mWu, mWd;
    static CUtensorMap mXh, mXl, mWaH, mWaL, mWiH, mWiL;
    enc_map(&mnH,  nH,  D, BS, 128);  enc_map(&mnL,  nL,  D, BS, 128);
    enc_map(&mzH,  zH,  D, BS, 128);  enc_map(&mzL,  zL,  D, BS, 128);
    enc_map(&mn2H, n2H, D, BS, 128);  enc_map(&mn2L, n2L, D, BS, 128);
    enc_map(&mguH, guH, F, BS, 128);  enc_map(&mguL, guL, F, BS, 128);
    enc_map(&mWy,  tWy, D, D, 256);   enc_map(&mWx,  tWx, D, D, 256);
    enc_map(&mWo,  tWo, D, D, 256);   enc_map(&mWg,  tWg, D, F, 256);
    enc_map(&mWu,  tWu, D, F, 256);   enc_map(&mWd,  tWd, F, D, 256);
    enc_map(&mXh,  xcH, D, BS, 128);  enc_map(&mXl,  xcL, D, BS, 128);
    enc_map(&mWaH, aWH, HD, (uint64_t)H * HD, 128);
    enc_map(&mWaL, aWL, HD, (uint64_t)H * HD, 128);
    enc_map(&mWiH, iWH, HD, (uint64_t)H * HD, 128);
    enc_map(&mWiL, iWL, HD, (uint64_t)H * HD, 128);

    cudaFuncSetAttribute(gemm_tma<0>, cudaFuncAttributeMaxDynamicSharedMemorySize, GT_SMEM);
    cudaFuncSetAttribute(gemm_tma<1>, cudaFuncAttributeMaxDynamicSharedMemorySize, GT_SMEM);
    cudaFuncSetAttribute(gemm_tma<2>, cudaFuncAttributeMaxDynamicSharedMemorySize, GT_SMEM);
    cudaFuncSetAttribute(gemm_tma<3>, cudaFuncAttributeMaxDynamicSharedMemorySize, GT_SMEM);
    cudaFuncSetAttribute(gate_mma,    cudaFuncAttributeMaxDynamicSharedMemorySize, GG_SMEM);

    const int EW = 256;
    const size_t nbsd_blocks = (NBSD + EW - 1) / EW;
    float* hlast = (out_size >= (int)(NBSD + (size_t)B * D)) ? (out + NBSD) : nullptr;

    // ---- weight transpose to fp16 ----
    trans_half2<<<dim3(D / 64, D / 64), 256>>>(Wy,   tWy, D, D);
    trans_half2<<<dim3(D / 64, D / 64), 256>>>(Wx,   tWx, D, D);
    trans_half2<<<dim3(D / 64, D / 64), 256>>>(Wout, tWo, D, D);
    trans_half2<<<dim3(F / 64, D / 64), 256>>>(Wg,   tWg, D, F);
    trans_half2<<<dim3(F / 64, D / 64), 256>>>(Wu,   tWu, D, F);
    trans_half2<<<dim3(D / 64, F / 64), 256>>>(Wd,   tWd, F, D);
    dim3 tg(HD / 32, HD / 32, H);
    trans_gate<<<tg, dim3(32, 8)>>>(agw, aWH, aWL);
    trans_gate<<<tg, dim3(32, 8)>>>(igw, iWH, iWL);

    // ---- temporal pre-norm (split output) ----
    rmsnorm_split<<<BS, 256>>>(x, r1w, nH, nL);

    // ---- y = gelu(normed @ W_y); xb = normed @ W_x ----
    dim3 gDD(D / 256, BS / 128);
    gemm_tma<1><<<gDD, 256, GT_SMEM>>>(mnH, mnL, mWy, y,  nullptr, nullptr, nullptr, D, D);
    gemm_tma<0><<<gDD, 256, GT_SMEM>>>(mnH, mnL, mWx, xb, nullptr, nullptr, nullptr, D, D);

    // ---- causal conv (split fp16 out) ----
    conv_split<<<(unsigned)nbsd_blocks, EW>>>(xb, cw, cb, xcH, xcL);

    // ---- fused gate GEMM + gate math -> a, b ----
    gate_mma<<<dim3(BS / 128, H), 256, GG_SMEM>>>(mXh, mXl, mWaH, mWaL, mWiH, mWiL,
                                                  agb, igb, apar, ga, gb);

    // ---- chunked scan ----
    scan_pass1<<<(B * SC_NC * D + 255) / 256, 256>>>(ga, gb, hloc, acum);
    scan_pass2<<<(B * D + 255) / 256, 256>>>(hloc, acum, h0, carry, hlast);
    scan_pass3<<<(unsigned)nbsd_blocks, EW>>>(hloc, acum, carry, y, zH, zL);

    // ---- residual = z @ W_out + x ----
    gemm_tma<2><<<gDD, 256, GT_SMEM>>>(mzH, mzL, mWo, resid, x, nullptr, nullptr, D, D);

    // ---- second norm (split) ----
    rmsnorm_split<<<BS, 256>>>(resid, r2w, n2H, n2L);

    // ---- MLP: G = gelu(n2 @ Wg); gu = (n2 @ Wu) * G ----
    dim3 gDF(F / 256, BS / 128);
    gemm_tma<1><<<gDF, 256, GT_SMEM>>>(mn2H, mn2L, mWg, G, nullptr, nullptr, nullptr, F, D);
    gemm_tma<3><<<gDF, 256, GT_SMEM>>>(mn2H, mn2L, mWu, nullptr, G, guH, guL, F, D);

    // ---- out = gu @ W_down + residual ----
    gemm_tma<2><<<gDD, 256, GT_SMEM>>>(mguH, mguL, mWd, out, resid, nullptr, nullptr, D, F);
}

// round 8
// speedup vs baseline: 7.8563x; 1.5665x over previous
#include <cuda_runtime.h>
#include <cuda.h>
#include <cuda_fp16.h>
#include <math.h>
#include <stdint.h>
#include <dlfcn.h>

// ---------------- problem constants ----------------
namespace hk {
constexpr int B  = 2;
constexpr int S  = 2048;
constexpr int D  = 2048;
constexpr int H  = 16;
constexpr int HD = 128;
constexpr int F  = 8192;
constexpr int BS = B * S;                     // 4096 rows
constexpr size_t NBSD = (size_t)BS * D;       // 8,388,608
constexpr size_t NBSF = (size_t)BS * F;       // 33,554,432
constexpr size_t NDD  = (size_t)D * D;
constexpr size_t NDF  = (size_t)D * F;
constexpr size_t NGW  = (size_t)H * HD * HD;  // 262,144
}

constexpr int SC_NC = 16;                      // scan chunks
constexpr int SC_L  = hk::S / SC_NC;           // 128 steps per chunk

// ---------------- scratch: fp32 intermediates ----------------
__device__ float g_y     [hk::NBSD];
__device__ float g_xb    [hk::NBSD];
__device__ float g_ga    [hk::NBSD];
__device__ float g_gb    [hk::NBSD];
__device__ float g_hloc  [hk::NBSD];
__device__ float g_acum  [hk::NBSD];
__device__ float g_resid [hk::NBSD];
__device__ float g_G     [hk::NBSF];
__device__ float g_carry [hk::B * hk::D * SC_NC];

// ---------------- scratch: fp16 activations (single, except gate path) ----------------
__device__ __half g_nA  [hk::NBSD];
__device__ __half g_xcH [hk::NBSD], g_xcL[hk::NBSD];   // gate path stays split
__device__ __half g_zA  [hk::NBSD];
__device__ __half g_n2A [hk::NBSD];
__device__ __half g_guA [hk::NBSF];

// ---------------- scratch: fp16 transposed weights [N,K] ----------------
__device__ __half g_Wy[hk::NDD];
__device__ __half g_Wx[hk::NDD];
__device__ __half g_Wo[hk::NDD];
__device__ __half g_Wg[hk::NDF];
__device__ __half g_Wu[hk::NDF];
__device__ __half g_Wd[hk::NDF];
// gate weights, transposed per head [H][e][d], hi/lo split
__device__ __half g_aWH[hk::NGW], g_aWL[hk::NGW];
__device__ __half g_iWH[hk::NGW], g_iWL[hk::NGW];

// ---------------- helpers ----------------
__device__ __forceinline__ float gelu_tanh(float x) {
    float x3 = x * x * x;
    return 0.5f * x * (1.0f + tanhf(0.7978845608028654f * (x + 0.044715f * x3)));
}

__device__ __forceinline__ uint32_t s2u(const void* p) {
    uint32_t a;
    asm("{ .reg .u64 t; cvta.to.shared.u64 t, %1; cvt.u32.u64 %0, t; }" : "=r"(a) : "l"(p));
    return a;
}

__device__ __forceinline__ void ldmx4(uint32_t* r, uint32_t a) {
    asm volatile("ldmatrix.sync.aligned.m8n8.x4.shared.b16 {%0,%1,%2,%3}, [%4];"
                 : "=r"(r[0]), "=r"(r[1]), "=r"(r[2]), "=r"(r[3]) : "r"(a));
}

__device__ __forceinline__ void mma16816(float* c, const uint32_t* a, const uint32_t* b) {
    asm volatile(
        "mma.sync.aligned.m16n8k16.row.col.f32.f16.f16.f32 "
        "{%0,%1,%2,%3}, {%4,%5,%6,%7}, {%8,%9}, {%0,%1,%2,%3};"
        : "+f"(c[0]), "+f"(c[1]), "+f"(c[2]), "+f"(c[3])
        : "r"(a[0]), "r"(a[1]), "r"(a[2]), "r"(a[3]), "r"(b[0]), "r"(b[1]));
}

__device__ __forceinline__ void split2h(float v, __half& h, __half& l) {
    h = __float2half_rn(v);
    l = __float2half_rn(v - __half2float(h));
}

__device__ __forceinline__ void mbar_init(uint32_t mbar, uint32_t cnt) {
    asm volatile("mbarrier.init.shared.b64 [%0], %1;" :: "r"(mbar), "r"(cnt) : "memory");
}

__device__ __forceinline__ void mbar_expect_tx(uint32_t mbar, uint32_t bytes) {
    asm volatile("mbarrier.arrive.expect_tx.shared.b64 _, [%0], %1;"
                 :: "r"(mbar), "r"(bytes) : "memory");
}

__device__ __forceinline__ void mbar_wait(uint32_t mbar, uint32_t phase) {
    asm volatile(
        "{\n\t.reg .pred P;\n\t"
        "WAIT_%=:\n\t"
        "mbarrier.try_wait.parity.shared.b64 P, [%0], %1, 10000000;\n\t"
        "@P bra.uni DONE_%=;\n\t"
        "bra.uni WAIT_%=;\n\t"
        "DONE_%=:\n\t}"
        :: "r"(mbar), "r"(phase) : "memory");
}

__device__ __forceinline__ void tma2d(uint32_t dst, const CUtensorMap* map,
                                      int cx, int cy, uint32_t mbar) {
    asm volatile(
        "cp.async.bulk.tensor.2d.shared::cluster.global.tile.mbarrier::complete_tx::bytes "
        "[%0], [%1, {%2, %3}], [%4];"
        :: "r"(dst), "l"(map), "r"(cx), "r"(cy), "r"(mbar) : "memory");
}

// =====================================================================
// fp16 tensor-core GEMM (single-precision operands), TMA loads (SW64),
// mbarrier 7-stage pipeline.
//   C[M,N](fp32) = A[M,K] @ B[N,K]^T
// CTA tile 128x256, warp tile 64x64 (8 warps 2x4), BK=32.
// EPI: 0 none, 1 tanh-gelu, 2 add aux(fp32),
//      3 multiply by aux(fp32) and write fp16 (OH).
// =====================================================================
constexpr int GT_NSTG  = 7;
constexpr int GT_TA    = 128 * 64;              // 8192 B A tile
constexpr int GT_TB    = 256 * 64;              // 16384 B B tile
constexpr int GT_STAGE = GT_TA + GT_TB;         // 24576 B
constexpr int GT_HDR   = 1024;
constexpr int GT_SMEM  = GT_HDR + GT_NSTG * GT_STAGE;   // 173056 B

template<int EPI>
__global__ void __launch_bounds__(256, 1)
gemm_tma(const __grid_constant__ CUtensorMap mA,
         const __grid_constant__ CUtensorMap mB,
         float* __restrict__ C, const float* __restrict__ aux,
         __half* __restrict__ OH,
         int N, int K)
{
    extern __shared__ __align__(1024) char smem[];
    const uint32_t sb    = s2u(smem);
    const uint32_t tiles = sb + GT_HDR;

    const int tid  = threadIdx.x;
    const int lane = tid & 31;
    const int wid  = tid >> 5;
    const int wm   = wid >> 2;
    const int wn   = wid & 3;
    const int row0 = blockIdx.y * 128;
    const int col0 = blockIdx.x * 256;
    const int KB   = K >> 5;

    if (tid == 0) {
        #pragma unroll
        for (int s = 0; s < GT_NSTG; s++) mbar_init(sb + s * 8, 1);
    }
    __syncthreads();

    uint32_t arow[4], axm[4], brow[4], bxm[4];
    #pragma unroll
    for (int im = 0; im < 4; im++) {
        int r = wm * 64 + im * 16 + (lane & 15);
        arow[im] = (uint32_t)(r * 64);
        axm[im]  = (uint32_t)((r & 6) << 3);
    }
    #pragma unroll
    for (int ip = 0; ip < 4; ip++) {
        int r = wn * 64 + ip * 16 + (lane & 7) + ((lane >> 4) & 1) * 8;
        brow[ip] = (uint32_t)(r * 64);
        bxm[ip]  = (uint32_t)((r & 6) << 3);
    }
    const uint32_t acol = (uint32_t)((lane >> 4) * 16);
    const uint32_t bcol = (uint32_t)(((lane >> 3) & 1) * 16);

    float acc[4][8][4];
    #pragma unroll
    for (int im = 0; im < 4; im++)
        #pragma unroll
        for (int in = 0; in < 8; in++)
            #pragma unroll
            for (int q = 0; q < 4; q++) acc[im][in][q] = 0.0f;

    auto issue = [&](int kb) {
        int slot = kb % GT_NSTG;
        uint32_t bar = sb + slot * 8;
        uint32_t st  = tiles + (uint32_t)slot * GT_STAGE;
        mbar_expect_tx(bar, (uint32_t)GT_STAGE);
        tma2d(st,         &mA, kb * 32, row0, bar);
        tma2d(st + GT_TA, &mB, kb * 32, col0, bar);
    };

    if (tid == 0) {
        #pragma unroll
        for (int s = 0; s < GT_NSTG - 1; s++) issue(s);
    }

    for (int kb = 0; kb < KB; kb++) {
        int slot = kb % GT_NSTG;
        mbar_wait(sb + slot * 8, (uint32_t)((kb / GT_NSTG) & 1));

        const uint32_t sA = tiles + (uint32_t)slot * GT_STAGE;
        const uint32_t sB = sA + GT_TA;

        #pragma unroll
        for (int kk = 0; kk < 2; kk++) {
            uint32_t af[4][4], bf[8][2];
            #pragma unroll
            for (int im = 0; im < 4; im++) {
                uint32_t rest = (acol + (uint32_t)(kk * 32)) ^ axm[im];
                ldmx4(af[im], sA + arow[im] + rest);
            }
            #pragma unroll
            for (int ip = 0; ip < 4; ip++) {
                uint32_t rest = (bcol + (uint32_t)(kk * 32)) ^ bxm[ip];
                uint32_t r4[4];
                ldmx4(r4, sB + brow[ip] + rest);
                bf[2 * ip + 0][0] = r4[0]; bf[2 * ip + 0][1] = r4[1];
                bf[2 * ip + 1][0] = r4[2]; bf[2 * ip + 1][1] = r4[3];
            }
            #pragma unroll
            for (int im = 0; im < 4; im++)
                #pragma unroll
                for (int in = 0; in < 8; in++)
                    mma16816(acc[im][in], af[im], bf[in]);
        }
        __syncthreads();
        int nk = kb + GT_NSTG - 1;
        if (nk < KB && tid == 0) issue(nk);
    }

    // ---- epilogue ----
    const int gid = lane >> 2, t4 = lane & 3;
    #pragma unroll
    for (int im = 0; im < 4; im++) {
        #pragma unroll
        for (int in = 0; in < 8; in++) {
            int r = row0 + wm * 64 + im * 16 + gid;
            int c = col0 + wn * 64 + in * 8 + t4 * 2;
            #pragma unroll
            for (int half = 0; half < 2; half++) {
                int rr = r + half * 8;
                float v0 = acc[im][in][half * 2 + 0];
                float v1 = acc[im][in][half * 2 + 1];
                if (EPI == 1) { v0 = gelu_tanh(v0); v1 = gelu_tanh(v1); }
                if (EPI == 2) {
                    float2 a2 = *reinterpret_cast<const float2*>(aux + (size_t)rr * N + c);
                    v0 += a2.x; v1 += a2.y;
                }
                if (EPI == 3) {
                    float2 a2 = *reinterpret_cast<const float2*>(aux + (size_t)rr * N + c);
                    v0 *= a2.x; v1 *= a2.y;
                    __half2 hp; hp.x = __float2half_rn(v0); hp.y = __float2half_rn(v1);
                    *reinterpret_cast<__half2*>(OH + (size_t)rr * N + c) = hp;
                } else {
                    float2 o; o.x = v0; o.y = v1;
                    *reinterpret_cast<float2*>(C + (size_t)rr * N + c) = o;
                }
            }
        }
    }
}

// =====================================================================
// gate_mma: per (128-row block, head) r/i pre-activations with split xc
// and split gate weights (scan path kept effectively exact), gate math
// fused in epilogue -> a (ga), b (gb) fp32.
// =====================================================================
constexpr int GG_CH   = 8192;
constexpr int GG_MAT  = 4 * GG_CH;            // 32768 B per matrix (K=128)
constexpr int GG_HDR  = 1024;
constexpr int GG_SMEM = GG_HDR + 6 * GG_MAT;  // 197632 B

__global__ void __launch_bounds__(256, 1)
gate_mma(const __grid_constant__ CUtensorMap mXh,
         const __grid_constant__ CUtensorMap mXl,
         const __grid_constant__ CUtensorMap mWaH,
         const __grid_constant__ CUtensorMap mWaL,
         const __grid_constant__ CUtensorMap mWiH,
         const __grid_constant__ CUtensorMap mWiL,
         const float* __restrict__ ab, const float* __restrict__ ib,
         const float* __restrict__ apar,
         float* __restrict__ ga, float* __restrict__ gb)
{
    using namespace hk;
    extern __shared__ __align__(1024) char smem[];
    const uint32_t sb    = s2u(smem);
    const uint32_t tiles = sb + GG_HDR;

    const int tid  = threadIdx.x;
    const int lane = tid & 31;
    const int wid  = tid >> 5;
    const int wm   = wid >> 2;
    const int wn   = wid & 3;
    const int row0 = blockIdx.x * 128;
    const int h    = blockIdx.y;

    if (tid == 0) mbar_init(sb, 1);
    __syncthreads();

    if (tid == 0) {
        mbar_expect_tx(sb, (uint32_t)(6 * GG_MAT));
        #pragma unroll
        for (int c = 0; c < 4; c++) {
            int kx = c * 32;
            tma2d(tiles + 0 * GG_MAT + c * GG_CH, &mXh,  h * HD + kx, row0,   sb);
            tma2d(tiles + 1 * GG_MAT + c * GG_CH, &mXl,  h * HD + kx, row0,   sb);
            tma2d(tiles + 2 * GG_MAT + c * GG_CH, &mWaH, kx,          h * HD, sb);
            tma2d(tiles + 3 * GG_MAT + c * GG_CH, &mWaL, kx,          h * HD, sb);
            tma2d(tiles + 4 * GG_MAT + c * GG_CH, &mWiH, kx,          h * HD, sb);
            tma2d(tiles + 5 * GG_MAT + c * GG_CH, &mWiL, kx,          h * HD, sb);
        }
    }
    mbar_wait(sb, 0);
    __syncthreads();

    uint32_t arow[4], axm[4], brow[2], bxm[2];
    #pragma unroll
    for (int im = 0; im < 4; im++) {
        int r = wm * 64 + im * 16 + (lane & 15);
        arow[im] = (uint32_t)(r * 64);
        axm[im]  = (uint32_t)((r & 6) << 3);
    }
    #pragma unroll
    for (int ip = 0; ip < 2; ip++) {
        int r = wn * 32 + ip * 16 + (lane & 7) + ((lane >> 4) & 1) * 8;
        brow[ip] = (uint32_t)(r * 64);
        bxm[ip]  = (uint32_t)((r & 6) << 3);
    }
    const uint32_t acol = (uint32_t)((lane >> 4) * 16);
    const uint32_t bcol = (uint32_t)(((lane >> 3) & 1) * 16);

    float accR[4][4][4], accI[4][4][4];
    #pragma unroll
    for (int im = 0; im < 4; im++)
        #pragma unroll
        for (int in = 0; in < 4; in++)
            #pragma unroll
            for (int q = 0; q < 4; q++) { accR[im][in][q] = 0.0f; accI[im][in][q] = 0.0f; }

    #pragma unroll
    for (int c = 0; c < 4; c++) {
        const uint32_t sAh = tiles + 0 * GG_MAT + c * GG_CH;
        const uint32_t sAl = tiles + 1 * GG_MAT + c * GG_CH;
        const uint32_t sWa = tiles + 2 * GG_MAT + c * GG_CH;
        const uint32_t sWal= tiles + 3 * GG_MAT + c * GG_CH;
        const uint32_t sWi = tiles + 4 * GG_MAT + c * GG_CH;
        const uint32_t sWil= tiles + 5 * GG_MAT + c * GG_CH;
        #pragma unroll
        for (int kk = 0; kk < 2; kk++) {
            uint32_t ahf[4][4], alf[4][4];
            uint32_t waH[4][2], waL[4][2], wiH[4][2], wiL[4][2];
            #pragma unroll
            for (int im = 0; im < 4; im++) {
                uint32_t rest = (acol + (uint32_t)(kk * 32)) ^ axm[im];
                ldmx4(ahf[im], sAh + arow[im] + rest);
                ldmx4(alf[im], sAl + arow[im] + rest);
            }
            #pragma unroll
            for (int ip = 0; ip < 2; ip++) {
                uint32_t rest = (bcol + (uint32_t)(kk * 32)) ^ bxm[ip];
                uint32_t r4[4];
                ldmx4(r4, sWa + brow[ip] + rest);
                waH[2*ip][0]=r4[0]; waH[2*ip][1]=r4[1]; waH[2*ip+1][0]=r4[2]; waH[2*ip+1][1]=r4[3];
                ldmx4(r4, sWal + brow[ip] + rest);
                waL[2*ip][0]=r4[0]; waL[2*ip][1]=r4[1]; waL[2*ip+1][0]=r4[2]; waL[2*ip+1][1]=r4[3];
                ldmx4(r4, sWi + brow[ip] + rest);
                wiH[2*ip][0]=r4[0]; wiH[2*ip][1]=r4[1]; wiH[2*ip+1][0]=r4[2]; wiH[2*ip+1][1]=r4[3];
                ldmx4(r4, sWil + brow[ip] + rest);
                wiL[2*ip][0]=r4[0]; wiL[2*ip][1]=r4[1]; wiL[2*ip+1][0]=r4[2]; wiL[2*ip+1][1]=r4[3];
            }
            #pragma unroll
            for (int im = 0; im < 4; im++)
                #pragma unroll
                for (int in = 0; in < 4; in++) {
                    mma16816(accR[im][in], ahf[im], waH[in]);
                    mma16816(accR[im][in], alf[im], waH[in]);
                    mma16816(accR[im][in], ahf[im], waL[in]);
                    mma16816(accI[im][in], ahf[im], wiH[in]);
                    mma16816(accI[im][in], alf[im], wiH[in]);
                    mma16816(accI[im][in], ahf[im], wiL[in]);
                }
        }
    }

    // ---- gate epilogue ----
    const int gid = lane >> 2, t4 = lane & 3;
    #pragma unroll
    for (int in = 0; in < 4; in++) {
        int c0 = wn * 32 + in * 8 + t4 * 2;
        #pragma unroll
        for (int q = 0; q < 2; q++) {
            int col = c0 + q;
            int dd  = h * HD + col;
            float ab_ = ab[dd], ib_ = ib[dd];
            float sp  = log1pf(expf(-apar[dd]));
            int cch = col >> 5;
            uint32_t cb = (uint32_t)((col & 31) * 2);
            uint32_t cbase = (uint32_t)(cch * GG_CH);
            #pragma unroll
            for (int im = 0; im < 4; im++) {
                #pragma unroll
                for (int half = 0; half < 2; half++) {
                    int row = wm * 64 + im * 16 + gid + half * 8;
                    float rv = accR[im][in][half * 2 + q] + ab_;
                    float iv = accI[im][in][half * 2 + q] + ib_;
                    float r  = 1.0f / (1.0f + expf(-rv));
                    float ii = 1.0f / (1.0f + expf(-iv));
                    float la = -8.0f * r * sp;
                    float a  = expf(la);
                    float mult = sqrtf(fmaxf(1.0f - expf(2.0f * la), 0.0f));
                    uint32_t off = cbase + (uint32_t)(row * 64)
                                 + ((cb & 48u) ^ (uint32_t)((row & 6) << 3)) + (cb & 15u);
                    float xcv = __half2float(*reinterpret_cast<const __half*>(
                                    smem + GG_HDR + off))
                              + __half2float(*reinterpret_cast<const __half*>(
                                    smem + GG_HDR + GG_MAT + off));
                    size_t g = (size_t)(row0 + row) * D + dd;
                    ga[g] = a;
                    gb[g] = mult * ii * xcv;
                }
            }
        }
    }
}

// =====================================================================
// vectorized transpose to fp16: W[K,N] fp32 -> Wt[N,K] fp16 (64x64 tiles)
// =====================================================================
__global__ void __launch_bounds__(256)
trans_half2(const float* __restrict__ W, __half* __restrict__ Wt, int K, int N)
{
    __shared__ float t[64][65];
    int n0 = blockIdx.x * 64, k0 = blockIdx.y * 64;
    int tid = threadIdx.x;
    int lr = tid >> 4;
    int lc = (tid & 15) * 4;
    #pragma unroll
    for (int i = 0; i < 4; i++) {
        int r = lr + i * 16;
        float4 v = *reinterpret_cast<const float4*>(&W[(size_t)(k0 + r) * N + n0 + lc]);
        t[r][lc] = v.x; t[r][lc + 1] = v.y; t[r][lc + 2] = v.z; t[r][lc + 3] = v.w;
    }
    __syncthreads();
    #pragma unroll
    for (int i = 0; i < 2; i++) {
        int task = tid + i * 256;
        int n  = task >> 3;
        int kg = (task & 7) * 8;
        __half h8[8];
        #pragma unroll
        for (int j = 0; j < 8; j++) h8[j] = __float2half_rn(t[kg + j][n]);
        *reinterpret_cast<uint4*>(&Wt[(size_t)(n0 + n) * K + k0 + kg]) =
            *reinterpret_cast<uint4*>(h8);
    }
}

// gate-weight transpose + hi/lo split: W[H][d][e] -> hi/lo [H][e][d]
__global__ void trans_gate(const float* __restrict__ W,
                           __half* __restrict__ hi, __half* __restrict__ lo)
{
    using namespace hk;
    __shared__ float t[32][33];
    int e0 = blockIdx.x * 32, d0 = blockIdx.y * 32, hh = blockIdx.z;
    int tx = threadIdx.x, ty = threadIdx.y;
    const float* Wh = W + (size_t)hh * HD * HD;
    #pragma unroll
    for (int i = 0; i < 32; i += 8)
        t[ty + i][tx] = Wh[(size_t)(d0 + ty + i) * HD + (e0 + tx)];
    __syncthreads();
    #pragma unroll
    for (int i = 0; i < 32; i += 8) {
        float v = t[tx][ty + i];
        size_t o = ((size_t)hh * HD + (e0 + ty + i)) * HD + (d0 + tx);
        __half a, b; split2h(v, a, b);
        hi[o] = a; lo[o] = b;
    }
}

// ---------------- rmsnorm with fp16 output ----------------
__global__ void rmsnorm_h(const float* __restrict__ x, const float* __restrict__ w,
                          __half* __restrict__ o)
{
    using namespace hk;
    const int row = blockIdx.x;
    const float* xr = x + (size_t)row * D;
    float ss = 0.0f;
    for (int d = threadIdx.x; d < D; d += 256) { float v = xr[d]; ss += v * v; }
    __shared__ float red[8];
    #pragma unroll
    for (int off = 16; off > 0; off >>= 1) ss += __shfl_down_sync(0xffffffffu, ss, off);
    if ((threadIdx.x & 31) == 0) red[threadIdx.x >> 5] = ss;
    __syncthreads();
    if (threadIdx.x < 8) {
        float v = red[threadIdx.x];
        #pragma unroll
        for (int off = 4; off > 0; off >>= 1) v += __shfl_down_sync(0xffu, v, off);
        if (threadIdx.x == 0) red[0] = v;
    }
    __syncthreads();
    const float scale = rsqrtf(red[0] / (float)D + 1e-6f);
    size_t base = (size_t)row * D;
    for (int d = threadIdx.x; d < D; d += 256)
        o[base + d] = __float2half_rn(xr[d] * scale * w[d]);
}

// ---------------- causal depthwise conv, kernel 4; split fp16 output ----------------
__global__ void conv_split(const float* __restrict__ xb, const float* __restrict__ cw,
                           const float* __restrict__ cb,
                           __half* __restrict__ xcH, __half* __restrict__ xcL)
{
    using namespace hk;
    size_t idx = (size_t)blockIdx.x * blockDim.x + threadIdx.x;
    if (idx >= NBSD) return;
    int d = (int)(idx % D);
    int s = (int)((idx / D) % S);
    float acc = cb[d];
    #pragma unroll
    for (int k = 0; k < 4; k++) {
        int ss = s + k - 3;
        if (ss >= 0) acc = fmaf(cw[k * D + d], xb[idx + (size_t)(k - 3) * D], acc);
    }
    __half h, l; split2h(acc, h, l);
    xcH[idx] = h; xcL[idx] = l;
}

// ---------------- chunked parallel RG-LRU scan ----------------
__global__ void scan_pass1(const float* __restrict__ ga, const float* __restrict__ gb,
                           float* __restrict__ hloc, float* __restrict__ acum)
{
    using namespace hk;
    int t = blockIdx.x * blockDim.x + threadIdx.x;
    if (t >= B * SC_NC * D) return;
    int d = t % D;
    int c = (t / D) % SC_NC;
    int b = t / (D * SC_NC);
    float h = 0.0f, A = 1.0f;
    size_t g = ((size_t)b * S + (size_t)c * SC_L) * D + d;
    for (int i = 0; i < SC_L; i++, g += D) {
        float a = ga[g];
        h = fmaf(a, h, gb[g]);
        A *= a;
        hloc[g] = h;
        acum[g] = A;
    }
}

__global__ void scan_pass2(const float* __restrict__ hloc, const float* __restrict__ acum,
                           const float* __restrict__ h0, float* __restrict__ carry,
                           float* __restrict__ hlast)
{
    using namespace hk;
    int ch = blockIdx.x * blockDim.x + threadIdx.x;
    if (ch >= B * D) return;
    int b = ch / D, d = ch % D;
    float cur = h0[ch];
    for (int c = 0; c < SC_NC; c++) {
        carry[((size_t)b * SC_NC + c) * D + d] = cur;
        size_t ge = ((size_t)b * S + (size_t)c * SC_L + SC_L - 1) * D + d;
        cur = fmaf(acum[ge], cur, hloc[ge]);
    }
    if (hlast) hlast[ch] = cur;
}

__global__ void scan_pass3(const float* __restrict__ hloc, const float* __restrict__ acum,
                           const float* __restrict__ carry, const float* __restrict__ y,
                           __half* __restrict__ zA)
{
    using namespace hk;
    size_t g = (size_t)blockIdx.x * blockDim.x + threadIdx.x;
    if (g >= NBSD) return;
    int d = (int)(g % D);
    int s = (int)((g / D) % S);
    int b = (int)(g / ((size_t)S * D));
    int c = s / SC_L;
    float cr = carry[((size_t)b * SC_NC + c) * D + d];
    float h = fmaf(acum[g], cr, hloc[g]);
    zA[g] = __float2half_rn(y[g] * h);
}

// =====================================================================
// host-side tensormap encoding (driver symbol via dlsym)
// =====================================================================
typedef CUresult (*EncodeFn)(CUtensorMap*, CUtensorMapDataType, cuuint32_t, void*,
                             const cuuint64_t*, const cuuint64_t*, const cuuint32_t*,
                             const cuuint32_t*, CUtensorMapInterleave, CUtensorMapSwizzle,
                             CUtensorMapL2promotion, CUtensorMapFloatOOBfill);

static EncodeFn get_encode() {
    static EncodeFn fn = nullptr;
    if (!fn) {
        fn = (EncodeFn)dlsym(RTLD_DEFAULT, "cuTensorMapEncodeTiled");
        if (!fn) {
            void* h = dlopen("libcuda.so.1", RTLD_LAZY | RTLD_GLOBAL);
            if (h) fn = (EncodeFn)dlsym(h, "cuTensorMapEncodeTiled");
        }
    }
    return fn;
}

static void enc_map(CUtensorMap* m, void* ptr, uint64_t K, uint64_t ROWS, uint32_t boxRows) {
    cuuint64_t dims[2]    = {K, ROWS};
    cuuint64_t strides[1] = {K * 2};
    cuuint32_t box[2]     = {32, boxRows};
    cuuint32_t es[2]      = {1, 1};
    get_encode()(m, CU_TENSOR_MAP_DATA_TYPE_FLOAT16, 2, ptr, dims, strides, box, es,
                 CU_TENSOR_MAP_INTERLEAVE_NONE, CU_TENSOR_MAP_SWIZZLE_64B,
                 CU_TENSOR_MAP_L2_PROMOTION_L2_128B, CU_TENSOR_MAP_FLOAT_OOB_FILL_NONE);
}

// ---------------- launch ----------------
extern "C" void kernel_launch(void* const* d_in, const int* in_sizes, int n_in,
                              void* d_out, int out_size)
{
    using namespace hk;
    const float* x    = (const float*)d_in[0];
    const float* h0   = (const float*)d_in[1];
    const float* r1w  = (const float*)d_in[2];
    const float* r2w  = (const float*)d_in[3];
    const float* Wx   = (const float*)d_in[4];
    const float* Wy   = (const float*)d_in[5];
    const float* cw   = (const float*)d_in[6];
    const float* cb   = (const float*)d_in[7];
    const float* apar = (const float*)d_in[8];
    const float* igw  = (const float*)d_in[9];
    const float* igb  = (const float*)d_in[10];
    const float* agw  = (const float*)d_in[11];
    const float* agb  = (const float*)d_in[12];
    const float* Wout = (const float*)d_in[13];
    const float* Wg   = (const float*)d_in[14];
    const float* Wu   = (const float*)d_in[15];
    const float* Wd   = (const float*)d_in[16];
    float* out = (float*)d_out;

    float *y, *xb, *ga, *gb, *hloc, *acum, *resid, *G, *carry;
    cudaGetSymbolAddress((void**)&y,     g_y);
    cudaGetSymbolAddress((void**)&xb,    g_xb);
    cudaGetSymbolAddress((void**)&ga,    g_ga);
    cudaGetSymbolAddress((void**)&gb,    g_gb);
    cudaGetSymbolAddress((void**)&hloc,  g_hloc);
    cudaGetSymbolAddress((void**)&acum,  g_acum);
    cudaGetSymbolAddress((void**)&resid, g_resid);
    cudaGetSymbolAddress((void**)&G,     g_G);
    cudaGetSymbolAddress((void**)&carry, g_carry);

    __half *nA,*xcH,*xcL,*zA,*n2A,*guA;
    __half *tWy,*tWx,*tWo,*tWg,*tWu,*tWd,*aWH,*aWL,*iWH,*iWL;
    cudaGetSymbolAddress((void**)&nA,  g_nA);
    cudaGetSymbolAddress((void**)&xcH, g_xcH); cudaGetSymbolAddress((void**)&xcL, g_xcL);
    cudaGetSymbolAddress((void**)&zA,  g_zA);
    cudaGetSymbolAddress((void**)&n2A, g_n2A);
    cudaGetSymbolAddress((void**)&guA, g_guA);
    cudaGetSymbolAddress((void**)&tWy, g_Wy);  cudaGetSymbolAddress((void**)&tWx, g_Wx);
    cudaGetSymbolAddress((void**)&tWo, g_Wo);  cudaGetSymbolAddress((void**)&tWg, g_Wg);
    cudaGetSymbolAddress((void**)&tWu, g_Wu);  cudaGetSymbolAddress((void**)&tWd, g_Wd);
    cudaGetSymbolAddress((void**)&aWH, g_aWH); cudaGetSymbolAddress((void**)&aWL, g_aWL);
    cudaGetSymbolAddress((void**)&iWH, g_iWH); cudaGetSymbolAddress((void**)&iWL, g_iWL);

    // ---- tensormaps ----
    static CUtensorMap mnA, mzA, mn2A, mguA;
    static CUtensorMap mWy, mWx, mWo, mWg, mWu, mWd;
    static CUtensorMap mXh, mXl, mWaH, mWaL, mWiH, mWiL;
    enc_map(&mnA,  nA,  D, BS, 128);
    enc_map(&mzA,  zA,  D, BS, 128);
    enc_map(&mn2A, n2A, D, BS, 128);
    enc_map(&mguA, guA, F, BS, 128);
    enc_map(&mWy,  tWy, D, D, 256);   enc_map(&mWx,  tWx, D, D, 256);
    enc_map(&mWo,  tWo, D, D, 256);   enc_map(&mWg,  tWg, D, F, 256);
    enc_map(&mWu,  tWu, D, F, 256);   enc_map(&mWd,  tWd, F, D, 256);
    enc_map(&mXh,  xcH, D, BS, 128);  enc_map(&mXl,  xcL, D, BS, 128);
    enc_map(&mWaH, aWH, HD, (uint64_t)H * HD, 128);
    enc_map(&mWaL, aWL, HD, (uint64_t)H * HD, 128);
    enc_map(&mWiH, iWH, HD, (uint64_t)H * HD, 128);
    enc_map(&mWiL, iWL, HD, (uint64_t)H * HD, 128);

    cudaFuncSetAttribute(gemm_tma<0>, cudaFuncAttributeMaxDynamicSharedMemorySize, GT_SMEM);
    cudaFuncSetAttribute(gemm_tma<1>, cudaFuncAttributeMaxDynamicSharedMemorySize, GT_SMEM);
    cudaFuncSetAttribute(gemm_tma<2>, cudaFuncAttributeMaxDynamicSharedMemorySize, GT_SMEM);
    cudaFuncSetAttribute(gemm_tma<3>, cudaFuncAttributeMaxDynamicSharedMemorySize, GT_SMEM);
    cudaFuncSetAttribute(gate_mma,    cudaFuncAttributeMaxDynamicSharedMemorySize, GG_SMEM);

    const int EW = 256;
    const size_t nbsd_blocks = (NBSD + EW - 1) / EW;
    float* hlast = (out_size >= (int)(NBSD + (size_t)B * D)) ? (out + NBSD) : nullptr;

    // ---- weight transpose to fp16 ----
    trans_half2<<<dim3(D / 64, D / 64), 256>>>(Wy,   tWy, D, D);
    trans_half2<<<dim3(D / 64, D / 64), 256>>>(Wx,   tWx, D, D);
    trans_half2<<<dim3(D / 64, D / 64), 256>>>(Wout, tWo, D, D);
    trans_half2<<<dim3(F / 64, D / 64), 256>>>(Wg,   tWg, D, F);
    trans_half2<<<dim3(F / 64, D / 64), 256>>>(Wu,   tWu, D, F);
    trans_half2<<<dim3(D / 64, F / 64), 256>>>(Wd,   tWd, F, D);
    dim3 tg(HD / 32, HD / 32, H);
    trans_gate<<<tg, dim3(32, 8)>>>(agw, aWH, aWL);
    trans_gate<<<tg, dim3(32, 8)>>>(igw, iWH, iWL);

    // ---- temporal pre-norm ----
    rmsnorm_h<<<BS, 256>>>(x, r1w, nA);

    // ---- y = gelu(normed @ W_y); xb = normed @ W_x ----
    dim3 gDD(D / 256, BS / 128);
    gemm_tma<1><<<gDD, 256, GT_SMEM>>>(mnA, mWy, y,  nullptr, nullptr, D, D);
    gemm_tma<0><<<gDD, 256, GT_SMEM>>>(mnA, mWx, xb, nullptr, nullptr, D, D);

    // ---- causal conv (split fp16 out for gate path) ----
    conv_split<<<(unsigned)nbsd_blocks, EW>>>(xb, cw, cb, xcH, xcL);

    // ---- fused gate GEMM + gate math -> a, b ----
    gate_mma<<<dim3(BS / 128, H), 256, GG_SMEM>>>(mXh, mXl, mWaH, mWaL, mWiH, mWiL,
                                                  agb, igb, apar, ga, gb);

    // ---- chunked scan ----
    scan_pass1<<<(B * SC_NC * D + 255) / 256, 256>>>(ga, gb, hloc, acum);
    scan_pass2<<<(B * D + 255) / 256, 256>>>(hloc, acum, h0, carry, hlast);
    scan_pass3<<<(unsigned)nbsd_blocks, EW>>>(hloc, acum, carry, y, zA);

    // ---- residual = z @ W_out + x ----
    gemm_tma<2><<<gDD, 256, GT_SMEM>>>(mzA, mWo, resid, x, nullptr, D, D);

    // ---- second norm ----
    rmsnorm_h<<<BS, 256>>>(resid, r2w, n2A);

    // ---- MLP: G = gelu(n2 @ Wg); gu = (n2 @ Wu) * G ----
    dim3 gDF(F / 256, BS / 128);
    gemm_tma<1><<<gDF, 256, GT_SMEM>>>(mn2A, mWg, G, nullptr, nullptr, F, D);
    gemm_tma<3><<<gDF, 256, GT_SMEM>>>(mn2A, mWu, nullptr, G, guA, F, D);

    // ---- out = gu @ W_down + residual ----
    gemm_tma<2><<<gDD, 256, GT_SMEM>>>(mguA, mWd, out, resid, nullptr, D, F);
}

// round 9
// speedup vs baseline: 7.9195x; 1.0080x over previous
#include <cuda_runtime.h>
#include <cuda.h>
#include <cuda_fp16.h>
#include <math.h>
#include <stdint.h>
#include <dlfcn.h>

// ---------------- problem constants ----------------
namespace hk {
constexpr int B  = 2;
constexpr int S  = 2048;
constexpr int D  = 2048;
constexpr int H  = 16;
constexpr int HD = 128;
constexpr int F  = 8192;
constexpr int BS = B * S;                     // 4096 rows
constexpr size_t NBSD = (size_t)BS * D;       // 8,388,608
constexpr size_t NBSF = (size_t)BS * F;       // 33,554,432
constexpr size_t NDD  = (size_t)D * D;
constexpr size_t NDF  = (size_t)D * F;
constexpr size_t NGW  = (size_t)H * HD * HD;  // 262,144
}

constexpr int SC_NC = 16;                      // scan chunks
constexpr int SC_L  = hk::S / SC_NC;           // 128 steps per chunk

// ---------------- scratch: fp32 intermediates ----------------
__device__ float g_xb    [hk::NBSD];
__device__ float g_ga    [hk::NBSD];
__device__ float g_gb    [hk::NBSD];
__device__ float g_resid [hk::NBSD];
__device__ float g_hend  [hk::B * hk::D * SC_NC];
__device__ float g_aend  [hk::B * hk::D * SC_NC];
__device__ float g_carry [hk::B * hk::D * SC_NC];

// ---------------- scratch: fp16 activations ----------------
__device__ __half g_nA  [hk::NBSD];
__device__ __half g_yA  [hk::NBSD];
__device__ __half g_xcH [hk::NBSD], g_xcL[hk::NBSD];   // gate path stays split
__device__ __half g_zA  [hk::NBSD];
__device__ __half g_n2A [hk::NBSD];
__device__ __half g_GA  [hk::NBSF];
__device__ __half g_guA [hk::NBSF];

// ---------------- scratch: fp16 transposed weights [N,K] ----------------
__device__ __half g_Wy[hk::NDD];
__device__ __half g_Wx[hk::NDD];
__device__ __half g_Wo[hk::NDD];
__device__ __half g_Wg[hk::NDF];
__device__ __half g_Wu[hk::NDF];
__device__ __half g_Wd[hk::NDF];
// gate weights, transposed per head [H][e][d], hi/lo split
__device__ __half g_aWH[hk::NGW], g_aWL[hk::NGW];
__device__ __half g_iWH[hk::NGW], g_iWL[hk::NGW];

// ---------------- helpers ----------------
__device__ __forceinline__ float gelu_tanh(float x) {
    float x3 = x * x * x;
    return 0.5f * x * (1.0f + tanhf(0.7978845608028654f * (x + 0.044715f * x3)));
}

__device__ __forceinline__ uint32_t s2u(const void* p) {
    uint32_t a;
    asm("{ .reg .u64 t; cvta.to.shared.u64 t, %1; cvt.u32.u64 %0, t; }" : "=r"(a) : "l"(p));
    return a;
}

__device__ __forceinline__ void ldmx4(uint32_t* r, uint32_t a) {
    asm volatile("ldmatrix.sync.aligned.m8n8.x4.shared.b16 {%0,%1,%2,%3}, [%4];"
                 : "=r"(r[0]), "=r"(r[1]), "=r"(r[2]), "=r"(r[3]) : "r"(a));
}

__device__ __forceinline__ void mma16816(float* c, const uint32_t* a, const uint32_t* b) {
    asm volatile(
        "mma.sync.aligned.m16n8k16.row.col.f32.f16.f16.f32 "
        "{%0,%1,%2,%3}, {%4,%5,%6,%7}, {%8,%9}, {%0,%1,%2,%3};"
        : "+f"(c[0]), "+f"(c[1]), "+f"(c[2]), "+f"(c[3])
        : "r"(a[0]), "r"(a[1]), "r"(a[2]), "r"(a[3]), "r"(b[0]), "r"(b[1]));
}

__device__ __forceinline__ void split2h(float v, __half& h, __half& l) {
    h = __float2half_rn(v);
    l = __float2half_rn(v - __half2float(h));
}

__device__ __forceinline__ void mbar_init(uint32_t mbar, uint32_t cnt) {
    asm volatile("mbarrier.init.shared.b64 [%0], %1;" :: "r"(mbar), "r"(cnt) : "memory");
}

__device__ __forceinline__ void mbar_expect_tx(uint32_t mbar, uint32_t bytes) {
    asm volatile("mbarrier.arrive.expect_tx.shared.b64 _, [%0], %1;"
                 :: "r"(mbar), "r"(bytes) : "memory");
}

__device__ __forceinline__ void mbar_wait(uint32_t mbar, uint32_t phase) {
    asm volatile(
        "{\n\t.reg .pred P;\n\t"
        "WAIT_%=:\n\t"
        "mbarrier.try_wait.parity.shared.b64 P, [%0], %1, 10000000;\n\t"
        "@P bra.uni DONE_%=;\n\t"
        "bra.uni WAIT_%=;\n\t"
        "DONE_%=:\n\t}"
        :: "r"(mbar), "r"(phase) : "memory");
}

__device__ __forceinline__ void tma2d(uint32_t dst, const CUtensorMap* map,
                                      int cx, int cy, uint32_t mbar) {
    asm volatile(
        "cp.async.bulk.tensor.2d.shared::cluster.global.tile.mbarrier::complete_tx::bytes "
        "[%0], [%1, {%2, %3}], [%4];"
        :: "r"(dst), "l"(map), "r"(cx), "r"(cy), "r"(mbar) : "memory");
}

// =====================================================================
// fp16 tensor-core GEMM, TMA loads (SW64), mbarrier 7-stage pipeline.
//   C[M,N](fp32) = A[M,K] @ B[N,K]^T
// CTA tile 128x256, warp tile 64x64 (8 warps 2x4), BK=32.
// EPI: 0 C fp32; 2 add aux fp32 -> C fp32;
//      3 multiply by auxh (fp16) -> OH fp16; 4 gelu -> OH fp16.
// =====================================================================
constexpr int GT_NSTG  = 7;
constexpr int GT_TA    = 128 * 64;              // 8192 B A tile
constexpr int GT_TB    = 256 * 64;              // 16384 B B tile
constexpr int GT_STAGE = GT_TA + GT_TB;         // 24576 B
constexpr int GT_HDR   = 1024;
constexpr int GT_SMEM  = GT_HDR + GT_NSTG * GT_STAGE;   // 173056 B

template<int EPI>
__global__ void __launch_bounds__(256, 1)
gemm_tma(const __grid_constant__ CUtensorMap mA,
         const __grid_constant__ CUtensorMap mB,
         float* __restrict__ C, const float* __restrict__ aux,
         const __half* __restrict__ auxh, __half* __restrict__ OH,
         int N, int K)
{
    extern __shared__ __align__(1024) char smem[];
    const uint32_t sb    = s2u(smem);
    const uint32_t tiles = sb + GT_HDR;

    const int tid  = threadIdx.x;
    const int lane = tid & 31;
    const int wid  = tid >> 5;
    const int wm   = wid >> 2;
    const int wn   = wid & 3;
    const int row0 = blockIdx.y * 128;
    const int col0 = blockIdx.x * 256;
    const int KB   = K >> 5;

    if (tid == 0) {
        #pragma unroll
        for (int s = 0; s < GT_NSTG; s++) mbar_init(sb + s * 8, 1);
    }
    __syncthreads();

    uint32_t arow[4], axm[4], brow[4], bxm[4];
    #pragma unroll
    for (int im = 0; im < 4; im++) {
        int r = wm * 64 + im * 16 + (lane & 15);
        arow[im] = (uint32_t)(r * 64);
        axm[im]  = (uint32_t)((r & 6) << 3);
    }
    #pragma unroll
    for (int ip = 0; ip < 4; ip++) {
        int r = wn * 64 + ip * 16 + (lane & 7) + ((lane >> 4) & 1) * 8;
        brow[ip] = (uint32_t)(r * 64);
        bxm[ip]  = (uint32_t)((r & 6) << 3);
    }
    const uint32_t acol = (uint32_t)((lane >> 4) * 16);
    const uint32_t bcol = (uint32_t)(((lane >> 3) & 1) * 16);

    float acc[4][8][4];
    #pragma unroll
    for (int im = 0; im < 4; im++)
        #pragma unroll
        for (int in = 0; in < 8; in++)
            #pragma unroll
            for (int q = 0; q < 4; q++) acc[im][in][q] = 0.0f;

    auto issue = [&](int kb) {
        int slot = kb % GT_NSTG;
        uint32_t bar = sb + slot * 8;
        uint32_t st  = tiles + (uint32_t)slot * GT_STAGE;
        mbar_expect_tx(bar, (uint32_t)GT_STAGE);
        tma2d(st,         &mA, kb * 32, row0, bar);
        tma2d(st + GT_TA, &mB, kb * 32, col0, bar);
    };

    if (tid == 0) {
        #pragma unroll
        for (int s = 0; s < GT_NSTG - 1; s++) issue(s);
    }

    for (int kb = 0; kb < KB; kb++) {
        int slot = kb % GT_NSTG;
        mbar_wait(sb + slot * 8, (uint32_t)((kb / GT_NSTG) & 1));

        const uint32_t sA = tiles + (uint32_t)slot * GT_STAGE;
        const uint32_t sB = sA + GT_TA;

        #pragma unroll
        for (int kk = 0; kk < 2; kk++) {
            uint32_t af[4][4], bf[8][2];
            #pragma unroll
            for (int im = 0; im < 4; im++) {
                uint32_t rest = (acol + (uint32_t)(kk * 32)) ^ axm[im];
                ldmx4(af[im], sA + arow[im] + rest);
            }
            #pragma unroll
            for (int ip = 0; ip < 4; ip++) {
                uint32_t rest = (bcol + (uint32_t)(kk * 32)) ^ bxm[ip];
                uint32_t r4[4];
                ldmx4(r4, sB + brow[ip] + rest);
                bf[2 * ip + 0][0] = r4[0]; bf[2 * ip + 0][1] = r4[1];
                bf[2 * ip + 1][0] = r4[2]; bf[2 * ip + 1][1] = r4[3];
            }
            #pragma unroll
            for (int im = 0; im < 4; im++)
                #pragma unroll
                for (int in = 0; in < 8; in++)
                    mma16816(acc[im][in], af[im], bf[in]);
        }
        __syncthreads();
        int nk = kb + GT_NSTG - 1;
        if (nk < KB && tid == 0) issue(nk);
    }

    // ---- epilogue ----
    const int gid = lane >> 2, t4 = lane & 3;
    #pragma unroll
    for (int im = 0; im < 4; im++) {
        #pragma unroll
        for (int in = 0; in < 8; in++) {
            int r = row0 + wm * 64 + im * 16 + gid;
            int c = col0 + wn * 64 + in * 8 + t4 * 2;
            #pragma unroll
            for (int half = 0; half < 2; half++) {
                int rr = r + half * 8;
                float v0 = acc[im][in][half * 2 + 0];
                float v1 = acc[im][in][half * 2 + 1];
                if (EPI == 2) {
                    float2 a2 = *reinterpret_cast<const float2*>(aux + (size_t)rr * N + c);
                    v0 += a2.x; v1 += a2.y;
                    float2 o; o.x = v0; o.y = v1;
                    *reinterpret_cast<float2*>(C + (size_t)rr * N + c) = o;
                } else if (EPI == 3) {
                    __half2 a2 = *reinterpret_cast<const __half2*>(auxh + (size_t)rr * N + c);
                    v0 *= __half2float(a2.x); v1 *= __half2float(a2.y);
                    __half2 hp; hp.x = __float2half_rn(v0); hp.y = __float2half_rn(v1);
                    *reinterpret_cast<__half2*>(OH + (size_t)rr * N + c) = hp;
                } else if (EPI == 4) {
                    v0 = gelu_tanh(v0); v1 = gelu_tanh(v1);
                    __half2 hp; hp.x = __float2half_rn(v0); hp.y = __float2half_rn(v1);
                    *reinterpret_cast<__half2*>(OH + (size_t)rr * N + c) = hp;
                } else {
                    float2 o; o.x = v0; o.y = v1;
                    *reinterpret_cast<float2*>(C + (size_t)rr * N + c) = o;
                }
            }
        }
    }
}

// =====================================================================
// gate_mma: per (128-row block, head) r/i pre-activations with split xc
// and split gate weights (scan path kept effectively exact), gate math
// fused in epilogue -> a (ga), b (gb) fp32.
// =====================================================================
constexpr int GG_CH   = 8192;
constexpr int GG_MAT  = 4 * GG_CH;            // 32768 B per matrix (K=128)
constexpr int GG_HDR  = 1024;
constexpr int GG_SMEM = GG_HDR + 6 * GG_MAT;  // 197632 B

__global__ void __launch_bounds__(256, 1)
gate_mma(const __grid_constant__ CUtensorMap mXh,
         const __grid_constant__ CUtensorMap mXl,
         const __grid_constant__ CUtensorMap mWaH,
         const __grid_constant__ CUtensorMap mWaL,
         const __grid_constant__ CUtensorMap mWiH,
         const __grid_constant__ CUtensorMap mWiL,
         const float* __restrict__ ab, const float* __restrict__ ib,
         const float* __restrict__ apar,
         float* __restrict__ ga, float* __restrict__ gb)
{
    using namespace hk;
    extern __shared__ __align__(1024) char smem[];
    const uint32_t sb    = s2u(smem);
    const uint32_t tiles = sb + GG_HDR;

    const int tid  = threadIdx.x;
    const int lane = tid & 31;
    const int wid  = tid >> 5;
    const int wm   = wid >> 2;
    const int wn   = wid & 3;
    const int row0 = blockIdx.x * 128;
    const int h    = blockIdx.y;

    if (tid == 0) mbar_init(sb, 1);
    __syncthreads();

    if (tid == 0) {
        mbar_expect_tx(sb, (uint32_t)(6 * GG_MAT));
        #pragma unroll
        for (int c = 0; c < 4; c++) {
            int kx = c * 32;
            tma2d(tiles + 0 * GG_MAT + c * GG_CH, &mXh,  h * HD + kx, row0,   sb);
            tma2d(tiles + 1 * GG_MAT + c * GG_CH, &mXl,  h * HD + kx, row0,   sb);
            tma2d(tiles + 2 * GG_MAT + c * GG_CH, &mWaH, kx,          h * HD, sb);
            tma2d(tiles + 3 * GG_MAT + c * GG_CH, &mWaL, kx,          h * HD, sb);
            tma2d(tiles + 4 * GG_MAT + c * GG_CH, &mWiH, kx,          h * HD, sb);
            tma2d(tiles + 5 * GG_MAT + c * GG_CH, &mWiL, kx,          h * HD, sb);
        }
    }
    mbar_wait(sb, 0);
    __syncthreads();

    uint32_t arow[4], axm[4], brow[2], bxm[2];
    #pragma unroll
    for (int im = 0; im < 4; im++) {
        int r = wm * 64 + im * 16 + (lane & 15);
        arow[im] = (uint32_t)(r * 64);
        axm[im]  = (uint32_t)((r & 6) << 3);
    }
    #pragma unroll
    for (int ip = 0; ip < 2; ip++) {
        int r = wn * 32 + ip * 16 + (lane & 7) + ((lane >> 4) & 1) * 8;
        brow[ip] = (uint32_t)(r * 64);
        bxm[ip]  = (uint32_t)((r & 6) << 3);
    }
    const uint32_t acol = (uint32_t)((lane >> 4) * 16);
    const uint32_t bcol = (uint32_t)(((lane >> 3) & 1) * 16);

    float accR[4][4][4], accI[4][4][4];
    #pragma unroll
    for (int im = 0; im < 4; im++)
        #pragma unroll
        for (int in = 0; in < 4; in++)
            #pragma unroll
            for (int q = 0; q < 4; q++) { accR[im][in][q] = 0.0f; accI[im][in][q] = 0.0f; }

    #pragma unroll
    for (int c = 0; c < 4; c++) {
        const uint32_t sAh = tiles + 0 * GG_MAT + c * GG_CH;
        const uint32_t sAl = tiles + 1 * GG_MAT + c * GG_CH;
        const uint32_t sWa = tiles + 2 * GG_MAT + c * GG_CH;
        const uint32_t sWal= tiles + 3 * GG_MAT + c * GG_CH;
        const uint32_t sWi = tiles + 4 * GG_MAT + c * GG_CH;
        const uint32_t sWil= tiles + 5 * GG_MAT + c * GG_CH;
        #pragma unroll
        for (int kk = 0; kk < 2; kk++) {
            uint32_t ahf[4][4], alf[4][4];
            uint32_t waH[4][2], waL[4][2], wiH[4][2], wiL[4][2];
            #pragma unroll
            for (int im = 0; im < 4; im++) {
                uint32_t rest = (acol + (uint32_t)(kk * 32)) ^ axm[im];
                ldmx4(ahf[im], sAh + arow[im] + rest);
                ldmx4(alf[im], sAl + arow[im] + rest);
            }
            #pragma unroll
            for (int ip = 0; ip < 2; ip++) {
                uint32_t rest = (bcol + (uint32_t)(kk * 32)) ^ bxm[ip];
                uint32_t r4[4];
                ldmx4(r4, sWa + brow[ip] + rest);
                waH[2*ip][0]=r4[0]; waH[2*ip][1]=r4[1]; waH[2*ip+1][0]=r4[2]; waH[2*ip+1][1]=r4[3];
                ldmx4(r4, sWal + brow[ip] + rest);
                waL[2*ip][0]=r4[0]; waL[2*ip][1]=r4[1]; waL[2*ip+1][0]=r4[2]; waL[2*ip+1][1]=r4[3];
                ldmx4(r4, sWi + brow[ip] + rest);
                wiH[2*ip][0]=r4[0]; wiH[2*ip][1]=r4[1]; wiH[2*ip+1][0]=r4[2]; wiH[2*ip+1][1]=r4[3];
                ldmx4(r4, sWil + brow[ip] + rest);
                wiL[2*ip][0]=r4[0]; wiL[2*ip][1]=r4[1]; wiL[2*ip+1][0]=r4[2]; wiL[2*ip+1][1]=r4[3];
            }
            #pragma unroll
            for (int im = 0; im < 4; im++)
                #pragma unroll
                for (int in = 0; in < 4; in++) {
                    mma16816(accR[im][in], ahf[im], waH[in]);
                    mma16816(accR[im][in], alf[im], waH[in]);
                    mma16816(accR[im][in], ahf[im], waL[in]);
                    mma16816(accI[im][in], ahf[im], wiH[in]);
                    mma16816(accI[im][in], alf[im], wiH[in]);
                    mma16816(accI[im][in], ahf[im], wiL[in]);
                }
        }
    }

    // ---- gate epilogue ----
    const int gid = lane >> 2, t4 = lane & 3;
    #pragma unroll
    for (int in = 0; in < 4; in++) {
        int c0 = wn * 32 + in * 8 + t4 * 2;
        #pragma unroll
        for (int q = 0; q < 2; q++) {
            int col = c0 + q;
            int dd  = h * HD + col;
            float ab_ = ab[dd], ib_ = ib[dd];
            float sp  = log1pf(expf(-apar[dd]));
            int cch = col >> 5;
            uint32_t cb = (uint32_t)((col & 31) * 2);
            uint32_t cbase = (uint32_t)(cch * GG_CH);
            #pragma unroll
            for (int im = 0; im < 4; im++) {
                #pragma unroll
                for (int half = 0; half < 2; half++) {
                    int row = wm * 64 + im * 16 + gid + half * 8;
                    float rv = accR[im][in][half * 2 + q] + ab_;
                    float iv = accI[im][in][half * 2 + q] + ib_;
                    float r  = 1.0f / (1.0f + expf(-rv));
                    float ii = 1.0f / (1.0f + expf(-iv));
                    float la = -8.0f * r * sp;
                    float a  = expf(la);
                    float mult = sqrtf(fmaxf(1.0f - expf(2.0f * la), 0.0f));
                    uint32_t off = cbase + (uint32_t)(row * 64)
                                 + ((cb & 48u) ^ (uint32_t)((row & 6) << 3)) + (cb & 15u);
                    float xcv = __half2float(*reinterpret_cast<const __half*>(
                                    smem + GG_HDR + off))
                              + __half2float(*reinterpret_cast<const __half*>(
                                    smem + GG_HDR + GG_MAT + off));
                    size_t g = (size_t)(row0 + row) * D + dd;
                    ga[g] = a;
                    gb[g] = mult * ii * xcv;
                }
            }
        }
    }
}

// =====================================================================
// vectorized transpose to fp16: W[K,N] fp32 -> Wt[N,K] fp16 (64x64 tiles)
// =====================================================================
__global__ void __launch_bounds__(256)
trans_half2(const float* __restrict__ W, __half* __restrict__ Wt, int K, int N)
{
    __shared__ float t[64][65];
    int n0 = blockIdx.x * 64, k0 = blockIdx.y * 64;
    int tid = threadIdx.x;
    int lr = tid >> 4;
    int lc = (tid & 15) * 4;
    #pragma unroll
    for (int i = 0; i < 4; i++) {
        int r = lr + i * 16;
        float4 v = *reinterpret_cast<const float4*>(&W[(size_t)(k0 + r) * N + n0 + lc]);
        t[r][lc] = v.x; t[r][lc + 1] = v.y; t[r][lc + 2] = v.z; t[r][lc + 3] = v.w;
    }
    __syncthreads();
    #pragma unroll
    for (int i = 0; i < 2; i++) {
        int task = tid + i * 256;
        int n  = task >> 3;
        int kg = (task & 7) * 8;
        __half h8[8];
        #pragma unroll
        for (int j = 0; j < 8; j++) h8[j] = __float2half_rn(t[kg + j][n]);
        *reinterpret_cast<uint4*>(&Wt[(size_t)(n0 + n) * K + k0 + kg]) =
            *reinterpret_cast<uint4*>(h8);
    }
}

// gate-weight transpose + hi/lo split: W[H][d][e] -> hi/lo [H][e][d]
__global__ void trans_gate(const float* __restrict__ W,
                           __half* __restrict__ hi, __half* __restrict__ lo)
{
    using namespace hk;
    __shared__ float t[32][33];
    int e0 = blockIdx.x * 32, d0 = blockIdx.y * 32, hh = blockIdx.z;
    int tx = threadIdx.x, ty = threadIdx.y;
    const float* Wh = W + (size_t)hh * HD * HD;
    #pragma unroll
    for (int i = 0; i < 32; i += 8)
        t[ty + i][tx] = Wh[(size_t)(d0 + ty + i) * HD + (e0 + tx)];
    __syncthreads();
    #pragma unroll
    for (int i = 0; i < 32; i += 8) {
        float v = t[tx][ty + i];
        size_t o = ((size_t)hh * HD + (e0 + ty + i)) * HD + (d0 + tx);
        __half a, b; split2h(v, a, b);
        hi[o] = a; lo[o] = b;
    }
}

// ---------------- rmsnorm with fp16 output ----------------
__global__ void rmsnorm_h(const float* __restrict__ x, const float* __restrict__ w,
                          __half* __restrict__ o)
{
    using namespace hk;
    const int row = blockIdx.x;
    const float* xr = x + (size_t)row * D;
    float ss = 0.0f;
    for (int d = threadIdx.x; d < D; d += 256) { float v = xr[d]; ss += v * v; }
    __shared__ float red[8];
    #pragma unroll
    for (int off = 16; off > 0; off >>= 1) ss += __shfl_down_sync(0xffffffffu, ss, off);
    if ((threadIdx.x & 31) == 0) red[threadIdx.x >> 5] = ss;
    __syncthreads();
    if (threadIdx.x < 8) {
        float v = red[threadIdx.x];
        #pragma unroll
        for (int off = 4; off > 0; off >>= 1) v += __shfl_down_sync(0xffu, v, off);
        if (threadIdx.x == 0) red[0] = v;
    }
    __syncthreads();
    const float scale = rsqrtf(red[0] / (float)D + 1e-6f);
    size_t base = (size_t)row * D;
    for (int d = threadIdx.x; d < D; d += 256)
        o[base + d] = __float2half_rn(xr[d] * scale * w[d]);
}

// ---------------- causal depthwise conv, kernel 4; split fp16 output ----------------
__global__ void conv_split(const float* __restrict__ xb, const float* __restrict__ cw,
                           const float* __restrict__ cb,
                           __half* __restrict__ xcH, __half* __restrict__ xcL)
{
    using namespace hk;
    size_t idx = (size_t)blockIdx.x * blockDim.x + threadIdx.x;
    if (idx >= NBSD) return;
    int d = (int)(idx % D);
    int s = (int)((idx / D) % S);
    float acc = cb[d];
    #pragma unroll
    for (int k = 0; k < 4; k++) {
        int ss = s + k - 3;
        if (ss >= 0) acc = fmaf(cw[k * D + d], xb[idx + (size_t)(k - 3) * D], acc);
    }
    __half h, l; split2h(acc, h, l);
    xcH[idx] = h; xcL[idx] = l;
}

// ---------------- chunked parallel RG-LRU scan (no per-step materialization) ----
// pass1: per (b, chunk, d) — local scan, store chunk-end (A, h) only
__global__ void scan_pass1(const float* __restrict__ ga, const float* __restrict__ gb,
                           float* __restrict__ hend, float* __restrict__ aend)
{
    using namespace hk;
    int t = blockIdx.x * blockDim.x + threadIdx.x;
    if (t >= B * SC_NC * D) return;
    int d = t % D;
    int c = (t / D) % SC_NC;
    int b = t / (D * SC_NC);
    float h = 0.0f, A = 1.0f;
    size_t g = ((size_t)b * S + (size_t)c * SC_L) * D + d;
    for (int i = 0; i < SC_L; i++, g += D) {
        float a = ga[g];
        h = fmaf(a, h, gb[g]);
        A *= a;
    }
    size_t o = ((size_t)b * SC_NC + c) * D + d;
    hend[o] = h;
    aend[o] = A;
}

// pass2: per (b,d) — combine chunk summaries into carries + h_last
__global__ void scan_pass2(const float* __restrict__ hend, const float* __restrict__ aend,
                           const float* __restrict__ h0, float* __restrict__ carry,
                           float* __restrict__ hlast)
{
    using namespace hk;
    int ch = blockIdx.x * blockDim.x + threadIdx.x;
    if (ch >= B * D) return;
    int b = ch / D, d = ch % D;
    float cur = h0[ch];
    for (int c = 0; c < SC_NC; c++) {
        size_t o = ((size_t)b * SC_NC + c) * D + d;
        carry[o] = cur;
        cur = fmaf(aend[o], cur, hend[o]);
    }
    if (hlast) hlast[ch] = cur;
}

// pass3: per (b, chunk, d) — re-scan from carry (exact recurrence), write z = y*h fp16
__global__ void scan_pass3(const float* __restrict__ ga, const float* __restrict__ gb,
                           const float* __restrict__ carry, const __half* __restrict__ yA,
                           __half* __restrict__ zA)
{
    using namespace hk;
    int t = blockIdx.x * blockDim.x + threadIdx.x;
    if (t >= B * SC_NC * D) return;
    int d = t % D;
    int c = (t / D) % SC_NC;
    int b = t / (D * SC_NC);
    float h = carry[((size_t)b * SC_NC + c) * D + d];
    size_t g = ((size_t)b * S + (size_t)c * SC_L) * D + d;
    for (int i = 0; i < SC_L; i++, g += D) {
        h = fmaf(ga[g], h, gb[g]);
        zA[g] = __float2half_rn(__half2float(yA[g]) * h);
    }
}

// =====================================================================
// host-side tensormap encoding (driver symbol via dlsym)
// =====================================================================
typedef CUresult (*EncodeFn)(CUtensorMap*, CUtensorMapDataType, cuuint32_t, void*,
                             const cuuint64_t*, const cuuint64_t*, const cuuint32_t*,
                             const cuuint32_t*, CUtensorMapInterleave, CUtensorMapSwizzle,
                             CUtensorMapL2promotion, CUtensorMapFloatOOBfill);

static EncodeFn get_encode() {
    static EncodeFn fn = nullptr;
    if (!fn) {
        fn = (EncodeFn)dlsym(RTLD_DEFAULT, "cuTensorMapEncodeTiled");
        if (!fn) {
            void* h = dlopen("libcuda.so.1", RTLD_LAZY | RTLD_GLOBAL);
            if (h) fn = (EncodeFn)dlsym(h, "cuTensorMapEncodeTiled");
        }
    }
    return fn;
}

static void enc_map(CUtensorMap* m, void* ptr, uint64_t K, uint64_t ROWS, uint32_t boxRows) {
    cuuint64_t dims[2]    = {K, ROWS};
    cuuint64_t strides[1] = {K * 2};
    cuuint32_t box[2]     = {32, boxRows};
    cuuint32_t es[2]      = {1, 1};
    get_encode()(m, CU_TENSOR_MAP_DATA_TYPE_FLOAT16, 2, ptr, dims, strides, box, es,
                 CU_TENSOR_MAP_INTERLEAVE_NONE, CU_TENSOR_MAP_SWIZZLE_64B,
                 CU_TENSOR_MAP_L2_PROMOTION_L2_128B, CU_TENSOR_MAP_FLOAT_OOB_FILL_NONE);
}

// ---------------- launch ----------------
extern "C" void kernel_launch(void* const* d_in, const int* in_sizes, int n_in,
                              void* d_out, int out_size)
{
    using namespace hk;
    const float* x    = (const float*)d_in[0];
    const float* h0   = (const float*)d_in[1];
    const float* r1w  = (const float*)d_in[2];
    const float* r2w  = (const float*)d_in[3];
    const float* Wx   = (const float*)d_in[4];
    const float* Wy   = (const float*)d_in[5];
    const float* cw   = (const float*)d_in[6];
    const float* cb   = (const float*)d_in[7];
    const float* apar = (const float*)d_in[8];
    const float* igw  = (const float*)d_in[9];
    const float* igb  = (const float*)d_in[10];
    const float* agw  = (const float*)d_in[11];
    const float* agb  = (const float*)d_in[12];
    const float* Wout = (const float*)d_in[13];
    const float* Wg   = (const float*)d_in[14];
    const float* Wu   = (const float*)d_in[15];
    const float* Wd   = (const float*)d_in[16];
    float* out = (float*)d_out;

    float *xb, *ga, *gb, *resid, *hend, *aend, *carry;
    cudaGetSymbolAddress((void**)&xb,    g_xb);
    cudaGetSymbolAddress((void**)&ga,    g_ga);
    cudaGetSymbolAddress((void**)&gb,    g_gb);
    cudaGetSymbolAddress((void**)&resid, g_resid);
    cudaGetSymbolAddress((void**)&hend,  g_hend);
    cudaGetSymbolAddress((void**)&aend,  g_aend);
    cudaGetSymbolAddress((void**)&carry, g_carry);

    __half *nA,*yA,*xcH,*xcL,*zA,*n2A,*GA,*guA;
    __half *tWy,*tWx,*tWo,*tWg,*tWu,*tWd,*aWH,*aWL,*iWH,*iWL;
    cudaGetSymbolAddress((void**)&nA,  g_nA);
    cudaGetSymbolAddress((void**)&yA,  g_yA);
    cudaGetSymbolAddress((void**)&xcH, g_xcH); cudaGetSymbolAddress((void**)&xcL, g_xcL);
    cudaGetSymbolAddress((void**)&zA,  g_zA);
    cudaGetSymbolAddress((void**)&n2A, g_n2A);
    cudaGetSymbolAddress((void**)&GA,  g_GA);
    cudaGetSymbolAddress((void**)&guA, g_guA);
    cudaGetSymbolAddress((void**)&tWy, g_Wy);  cudaGetSymbolAddress((void**)&tWx, g_Wx);
    cudaGetSymbolAddress((void**)&tWo, g_Wo);  cudaGetSymbolAddress((void**)&tWg, g_Wg);
    cudaGetSymbolAddress((void**)&tWu, g_Wu);  cudaGetSymbolAddress((void**)&tWd, g_Wd);
    cudaGetSymbolAddress((void**)&aWH, g_aWH); cudaGetSymbolAddress((void**)&aWL, g_aWL);
    cudaGetSymbolAddress((void**)&iWH, g_iWH); cudaGetSymbolAddress((void**)&iWL, g_iWL);

    // ---- tensormaps ----
    static CUtensorMap mnA, mzA, mn2A, mguA;
    static CUtensorMap mWy, mWx, mWo, mWg, mWu, mWd;
    static CUtensorMap mXh, mXl, mWaH, mWaL, mWiH, mWiL;
    enc_map(&mnA,  nA,  D, BS, 128);
    enc_map(&mzA,  zA,  D, BS, 128);
    enc_map(&mn2A, n2A, D, BS, 128);
    enc_map(&mguA, guA, F, BS, 128);
    enc_map(&mWy,  tWy, D, D, 256);   enc_map(&mWx,  tWx, D, D, 256);
    enc_map(&mWo,  tWo, D, D, 256);   enc_map(&mWg,  tWg, D, F, 256);
    enc_map(&mWu,  tWu, D, F, 256);   enc_map(&mWd,  tWd, F, D, 256);
    enc_map(&mXh,  xcH, D, BS, 128);  enc_map(&mXl,  xcL, D, BS, 128);
    enc_map(&mWaH, aWH, HD, (uint64_t)H * HD, 128);
    enc_map(&mWaL, aWL, HD, (uint64_t)H * HD, 128);
    enc_map(&mWiH, iWH, HD, (uint64_t)H * HD, 128);
    enc_map(&mWiL, iWL, HD, (uint64_t)H * HD, 128);

    cudaFuncSetAttribute(gemm_tma<0>, cudaFuncAttributeMaxDynamicSharedMemorySize, GT_SMEM);
    cudaFuncSetAttribute(gemm_tma<2>, cudaFuncAttributeMaxDynamicSharedMemorySize, GT_SMEM);
    cudaFuncSetAttribute(gemm_tma<3>, cudaFuncAttributeMaxDynamicSharedMemorySize, GT_SMEM);
    cudaFuncSetAttribute(gemm_tma<4>, cudaFuncAttributeMaxDynamicSharedMemorySize, GT_SMEM);
    cudaFuncSetAttribute(gate_mma,    cudaFuncAttributeMaxDynamicSharedMemorySize, GG_SMEM);

    const int EW = 256;
    const size_t nbsd_blocks = (NBSD + EW - 1) / EW;
    float* hlast = (out_size >= (int)(NBSD + (size_t)B * D)) ? (out + NBSD) : nullptr;

    // ---- weight transpose to fp16 ----
    trans_half2<<<dim3(D / 64, D / 64), 256>>>(Wy,   tWy, D, D);
    trans_half2<<<dim3(D / 64, D / 64), 256>>>(Wx,   tWx, D, D);
    trans_half2<<<dim3(D / 64, D / 64), 256>>>(Wout, tWo, D, D);
    trans_half2<<<dim3(F / 64, D / 64), 256>>>(Wg,   tWg, D, F);
    trans_half2<<<dim3(F / 64, D / 64), 256>>>(Wu,   tWu, D, F);
    trans_half2<<<dim3(D / 64, F / 64), 256>>>(Wd,   tWd, F, D);
    dim3 tg(HD / 32, HD / 32, H);
    trans_gate<<<tg, dim3(32, 8)>>>(agw, aWH, aWL);
    trans_gate<<<tg, dim3(32, 8)>>>(igw, iWH, iWL);

    // ---- temporal pre-norm ----
    rmsnorm_h<<<BS, 256>>>(x, r1w, nA);

    // ---- y = gelu(normed @ W_y) fp16; xb = normed @ W_x fp32 ----
    dim3 gDD(D / 256, BS / 128);
    gemm_tma<4><<<gDD, 256, GT_SMEM>>>(mnA, mWy, nullptr, nullptr, nullptr, yA, D, D);
    gemm_tma<0><<<gDD, 256, GT_SMEM>>>(mnA, mWx, xb, nullptr, nullptr, nullptr, D, D);

    // ---- causal conv (split fp16 out for gate path) ----
    conv_split<<<(unsigned)nbsd_blocks, EW>>>(xb, cw, cb, xcH, xcL);

    // ---- fused gate GEMM + gate math -> a, b ----
    gate_mma<<<dim3(BS / 128, H), 256, GG_SMEM>>>(mXh, mXl, mWaH, mWaL, mWiH, mWiL,
                                                  agb, igb, apar, ga, gb);

    // ---- chunked scan (ends-only pass1; exact rescan pass3 fused with y-mul) ----
    scan_pass1<<<(B * SC_NC * D + 255) / 256, 256>>>(ga, gb, hend, aend);
    scan_pass2<<<(B * D + 255) / 256, 256>>>(hend, aend, h0, carry, hlast);
    scan_pass3<<<(B * SC_NC * D + 255) / 256, 256>>>(ga, gb, carry, yA, zA);

    // ---- residual = z @ W_out + x ----
    gemm_tma<2><<<gDD, 256, GT_SMEM>>>(mzA, mWo, resid, x, nullptr, nullptr, D, D);

    // ---- second norm ----
    rmsnorm_h<<<BS, 256>>>(resid, r2w, n2A);

    // ---- MLP: G = gelu(n2 @ Wg) fp16; gu = (n2 @ Wu) * G fp16 ----
    dim3 gDF(F / 256, BS / 128);
    gemm_tma<4><<<gDF, 256, GT_SMEM>>>(mn2A, mWg, nullptr, nullptr, nullptr, GA, F, D);
    gemm_tma<3><<<gDF, 256, GT_SMEM>>>(mn2A, mWu, nullptr, nullptr, GA, guA, F, D);

    // ---- out = gu @ W_down + residual ----
    gemm_tma<2><<<gDD, 256, GT_SMEM>>>(mguA, mWd, out, resid, nullptr, nullptr, D, F);
}

// round 10
// speedup vs baseline: 8.3162x; 1.0501x over previous
#include <cuda_runtime.h>
#include <cuda.h>
#include <cuda_fp16.h>
#include <math.h>
#include <stdint.h>
#include <dlfcn.h>

// ---------------- problem constants ----------------
namespace hk {
constexpr int B  = 2;
constexpr int S  = 2048;
constexpr int D  = 2048;
constexpr int H  = 16;
constexpr int HD = 128;
constexpr int F  = 8192;
constexpr int BS = B * S;                     // 4096 rows
constexpr size_t NBSD = (size_t)BS * D;       // 8,388,608
constexpr size_t NBSF = (size_t)BS * F;       // 33,554,432
constexpr size_t NDD  = (size_t)D * D;
constexpr size_t NDF  = (size_t)D * F;
constexpr size_t NGW  = (size_t)H * HD * HD;  // 262,144
}

constexpr int SC_NC = 16;                      // scan chunks
constexpr int SC_L  = hk::S / SC_NC;           // 128 steps per chunk

// ---------------- scratch: fp32 intermediates ----------------
__device__ float g_xb    [hk::NBSD];
__device__ float g_ga    [hk::NBSD];
__device__ float g_resid [hk::NBSD];
__device__ float g_hend  [hk::B * hk::D * SC_NC];
__device__ float g_aend  [hk::B * hk::D * SC_NC];
__device__ float g_carry [hk::B * hk::D * SC_NC];

// ---------------- scratch: fp16 activations ----------------
__device__ __half g_gbh [hk::NBSD];
__device__ __half g_nA  [hk::NBSD];
__device__ __half g_yA  [hk::NBSD];
__device__ __half g_xcH [hk::NBSD], g_xcL[hk::NBSD];   // gate path stays split
__device__ __half g_zA  [hk::NBSD];
__device__ __half g_n2A [hk::NBSD];
__device__ __half g_GA  [hk::NBSF];
__device__ __half g_guA [hk::NBSF];

// ---------------- scratch: fp16 transposed weights [N,K] ----------------
__device__ __half g_Wy[hk::NDD];
__device__ __half g_Wx[hk::NDD];
__device__ __half g_Wo[hk::NDD];
__device__ __half g_Wg[hk::NDF];
__device__ __half g_Wu[hk::NDF];
__device__ __half g_Wd[hk::NDF];
// gate weights, transposed per head [H][e][d], hi/lo split
__device__ __half g_aWH[hk::NGW], g_aWL[hk::NGW];
__device__ __half g_iWH[hk::NGW], g_iWL[hk::NGW];

// ---------------- helpers ----------------
__device__ __forceinline__ float gelu_tanh(float x) {
    float x3 = x * x * x;
    return 0.5f * x * (1.0f + tanhf(0.7978845608028654f * (x + 0.044715f * x3)));
}

__device__ __forceinline__ uint32_t s2u(const void* p) {
    uint32_t a;
    asm("{ .reg .u64 t; cvta.to.shared.u64 t, %1; cvt.u32.u64 %0, t; }" : "=r"(a) : "l"(p));
    return a;
}

__device__ __forceinline__ void ldmx4(uint32_t* r, uint32_t a) {
    asm volatile("ldmatrix.sync.aligned.m8n8.x4.shared.b16 {%0,%1,%2,%3}, [%4];"
                 : "=r"(r[0]), "=r"(r[1]), "=r"(r[2]), "=r"(r[3]) : "r"(a));
}

__device__ __forceinline__ void mma16816(float* c, const uint32_t* a, const uint32_t* b) {
    asm volatile(
        "mma.sync.aligned.m16n8k16.row.col.f32.f16.f16.f32 "
        "{%0,%1,%2,%3}, {%4,%5,%6,%7}, {%8,%9}, {%0,%1,%2,%3};"
        : "+f"(c[0]), "+f"(c[1]), "+f"(c[2]), "+f"(c[3])
        : "r"(a[0]), "r"(a[1]), "r"(a[2]), "r"(a[3]), "r"(b[0]), "r"(b[1]));
}

__device__ __forceinline__ void split2h(float v, __half& h, __half& l) {
    h = __float2half_rn(v);
    l = __float2half_rn(v - __half2float(h));
}

__device__ __forceinline__ void mbar_init(uint32_t mbar, uint32_t cnt) {
    asm volatile("mbarrier.init.shared.b64 [%0], %1;" :: "r"(mbar), "r"(cnt) : "memory");
}

__device__ __forceinline__ void mbar_expect_tx(uint32_t mbar, uint32_t bytes) {
    asm volatile("mbarrier.arrive.expect_tx.shared.b64 _, [%0], %1;"
                 :: "r"(mbar), "r"(bytes) : "memory");
}

__device__ __forceinline__ void mbar_wait(uint32_t mbar, uint32_t phase) {
    asm volatile(
        "{\n\t.reg .pred P;\n\t"
        "WAIT_%=:\n\t"
        "mbarrier.try_wait.parity.shared.b64 P, [%0], %1, 10000000;\n\t"
        "@P bra.uni DONE_%=;\n\t"
        "bra.uni WAIT_%=;\n\t"
        "DONE_%=:\n\t}"
        :: "r"(mbar), "r"(phase) : "memory");
}

__device__ __forceinline__ void tma2d(uint32_t dst, const CUtensorMap* map,
                                      int cx, int cy, uint32_t mbar) {
    asm volatile(
        "cp.async.bulk.tensor.2d.shared::cluster.global.tile.mbarrier::complete_tx::bytes "
        "[%0], [%1, {%2, %3}], [%4];"
        :: "r"(dst), "l"(map), "r"(cx), "r"(cy), "r"(mbar) : "memory");
}

// =====================================================================
// fp16 tensor-core GEMM, TMA loads (SW64), mbarrier 7-stage pipeline,
// TWO K-blocks per __syncthreads.
//   C[M,N](fp32) = A[M,K] @ B[N,K]^T
// CTA tile 128x256, warp tile 64x64 (8 warps 2x4), BK=32.
// EPI: 0 C fp32; 2 add aux fp32 -> C fp32;
//      3 multiply by auxh (fp16) -> OH fp16; 4 gelu -> OH fp16.
// =====================================================================
constexpr int GT_NSTG  = 7;
constexpr int GT_TA    = 128 * 64;              // 8192 B A tile
constexpr int GT_TB    = 256 * 64;              // 16384 B B tile
constexpr int GT_STAGE = GT_TA + GT_TB;         // 24576 B
constexpr int GT_HDR   = 1024;
constexpr int GT_SMEM  = GT_HDR + GT_NSTG * GT_STAGE;   // 173056 B

template<int EPI>
__global__ void __launch_bounds__(256, 1)
gemm_tma(const __grid_constant__ CUtensorMap mA,
         const __grid_constant__ CUtensorMap mB,
         float* __restrict__ C, const float* __restrict__ aux,
         const __half* __restrict__ auxh, __half* __restrict__ OH,
         int N, int K)
{
    extern __shared__ __align__(1024) char smem[];
    const uint32_t sb    = s2u(smem);
    const uint32_t tiles = sb + GT_HDR;

    const int tid  = threadIdx.x;
    const int lane = tid & 31;
    const int wid  = tid >> 5;
    const int wm   = wid >> 2;
    const int wn   = wid & 3;
    const int row0 = blockIdx.y * 128;
    const int col0 = blockIdx.x * 256;
    const int KB   = K >> 5;

    if (tid == 0) {
        #pragma unroll
        for (int s = 0; s < GT_NSTG; s++) mbar_init(sb + s * 8, 1);
    }
    __syncthreads();

    uint32_t arow[4], axm[4], brow[4], bxm[4];
    #pragma unroll
    for (int im = 0; im < 4; im++) {
        int r = wm * 64 + im * 16 + (lane & 15);
        arow[im] = (uint32_t)(r * 64);
        axm[im]  = (uint32_t)((r & 6) << 3);
    }
    #pragma unroll
    for (int ip = 0; ip < 4; ip++) {
        int r = wn * 64 + ip * 16 + (lane & 7) + ((lane >> 4) & 1) * 8;
        brow[ip] = (uint32_t)(r * 64);
        bxm[ip]  = (uint32_t)((r & 6) << 3);
    }
    const uint32_t acol = (uint32_t)((lane >> 4) * 16);
    const uint32_t bcol = (uint32_t)(((lane >> 3) & 1) * 16);

    float acc[4][8][4];
    #pragma unroll
    for (int im = 0; im < 4; im++)
        #pragma unroll
        for (int in = 0; in < 8; in++)
            #pragma unroll
            for (int q = 0; q < 4; q++) acc[im][in][q] = 0.0f;

    auto issue = [&](int kb) {
        int slot = kb % GT_NSTG;
        uint32_t bar = sb + slot * 8;
        uint32_t st  = tiles + (uint32_t)slot * GT_STAGE;
        mbar_expect_tx(bar, (uint32_t)GT_STAGE);
        tma2d(st,         &mA, kb * 32, row0, bar);
        tma2d(st + GT_TA, &mB, kb * 32, col0, bar);
    };

    auto compute = [&](int kb) {
        const uint32_t sA = tiles + (uint32_t)(kb % GT_NSTG) * GT_STAGE;
        const uint32_t sB = sA + GT_TA;
        #pragma unroll
        for (int kk = 0; kk < 2; kk++) {
            uint32_t af[4][4], bf[8][2];
            #pragma unroll
            for (int im = 0; im < 4; im++) {
                uint32_t rest = (acol + (uint32_t)(kk * 32)) ^ axm[im];
                ldmx4(af[im], sA + arow[im] + rest);
            }
            #pragma unroll
            for (int ip = 0; ip < 4; ip++) {
                uint32_t rest = (bcol + (uint32_t)(kk * 32)) ^ bxm[ip];
                uint32_t r4[4];
                ldmx4(r4, sB + brow[ip] + rest);
                bf[2 * ip + 0][0] = r4[0]; bf[2 * ip + 0][1] = r4[1];
                bf[2 * ip + 1][0] = r4[2]; bf[2 * ip + 1][1] = r4[3];
            }
            #pragma unroll
            for (int im = 0; im < 4; im++)
                #pragma unroll
                for (int in = 0; in < 8; in++)
                    mma16816(acc[im][in], af[im], bf[in]);
        }
    };

    if (tid == 0) {
        #pragma unroll
        for (int s = 0; s < GT_NSTG - 1; s++) issue(s);
    }

    // two K-blocks per barrier; KB is even for all shapes used here
    for (int kb = 0; kb < KB; kb += 2) {
        mbar_wait(sb + (kb % GT_NSTG) * 8, (uint32_t)((kb / GT_NSTG) & 1));
        compute(kb);
        mbar_wait(sb + ((kb + 1) % GT_NSTG) * 8, (uint32_t)(((kb + 1) / GT_NSTG) & 1));
        compute(kb + 1);
        __syncthreads();
        if (tid == 0) {
            if (kb + GT_NSTG - 1 < KB) issue(kb + GT_NSTG - 1);
            if (kb + GT_NSTG     < KB) issue(kb + GT_NSTG);
        }
    }

    // ---- epilogue ----
    const int gid = lane >> 2, t4 = lane & 3;
    #pragma unroll
    for (int im = 0; im < 4; im++) {
        #pragma unroll
        for (int in = 0; in < 8; in++) {
            int r = row0 + wm * 64 + im * 16 + gid;
            int c = col0 + wn * 64 + in * 8 + t4 * 2;
            #pragma unroll
            for (int half = 0; half < 2; half++) {
                int rr = r + half * 8;
                float v0 = acc[im][in][half * 2 + 0];
                float v1 = acc[im][in][half * 2 + 1];
                if (EPI == 2) {
                    float2 a2 = *reinterpret_cast<const float2*>(aux + (size_t)rr * N + c);
                    v0 += a2.x; v1 += a2.y;
                    float2 o; o.x = v0; o.y = v1;
                    *reinterpret_cast<float2*>(C + (size_t)rr * N + c) = o;
                } else if (EPI == 3) {
                    __half2 a2 = *reinterpret_cast<const __half2*>(auxh + (size_t)rr * N + c);
                    v0 *= __half2float(a2.x); v1 *= __half2float(a2.y);
                    __half2 hp; hp.x = __float2half_rn(v0); hp.y = __float2half_rn(v1);
                    *reinterpret_cast<__half2*>(OH + (size_t)rr * N + c) = hp;
                } else if (EPI == 4) {
                    v0 = gelu_tanh(v0); v1 = gelu_tanh(v1);
                    __half2 hp; hp.x = __float2half_rn(v0); hp.y = __float2half_rn(v1);
                    *reinterpret_cast<__half2*>(OH + (size_t)rr * N + c) = hp;
                } else {
                    float2 o; o.x = v0; o.y = v1;
                    *reinterpret_cast<float2*>(C + (size_t)rr * N + c) = o;
                }
            }
        }
    }
}

// =====================================================================
// gate_mma: per (128-row block, head) r/i pre-activations with split xc
// and split gate weights; gate math fused; ALSO computes chunk-end scan
// summaries (hend, aend) in-block (block rows == one scan chunk).
// Outputs: ga fp32, gb fp16, hend, aend.
// =====================================================================
constexpr int GG_CH   = 8192;
constexpr int GG_MAT  = 4 * GG_CH;            // 32768 B per matrix (K=128)
constexpr int GG_HDR  = 1024;
constexpr int GG_SMEM = GG_HDR + 6 * GG_MAT;  // 197632 B

__global__ void __launch_bounds__(256, 1)
gate_mma(const __grid_constant__ CUtensorMap mXh,
         const __grid_constant__ CUtensorMap mXl,
         const __grid_constant__ CUtensorMap mWaH,
         const __grid_constant__ CUtensorMap mWaL,
         const __grid_constant__ CUtensorMap mWiH,
         const __grid_constant__ CUtensorMap mWiL,
         const float* __restrict__ ab, const float* __restrict__ ib,
         const float* __restrict__ apar,
         float* __restrict__ ga, __half* __restrict__ gbh,
         float* __restrict__ hend, float* __restrict__ aend)
{
    using namespace hk;
    extern __shared__ __align__(1024) char smem[];
    const uint32_t sb    = s2u(smem);
    const uint32_t tiles = sb + GG_HDR;

    const int tid  = threadIdx.x;
    const int lane = tid & 31;
    const int wid  = tid >> 5;
    const int wm   = wid >> 2;
    const int wn   = wid & 3;
    const int row0 = blockIdx.x * 128;
    const int h    = blockIdx.y;

    // smem staging for in-block scan (reuses weight-tile region after mainloop)
    float* asp = reinterpret_cast<float*>(smem + GG_HDR + 2 * GG_MAT);  // 64 KB
    float* bsp = reinterpret_cast<float*>(smem + GG_HDR + 4 * GG_MAT);  // 64 KB

    if (tid == 0) mbar_init(sb, 1);
    __syncthreads();

    if (tid == 0) {
        mbar_expect_tx(sb, (uint32_t)(6 * GG_MAT));
        #pragma unroll
        for (int c = 0; c < 4; c++) {
            int kx = c * 32;
            tma2d(tiles + 0 * GG_MAT + c * GG_CH, &mXh,  h * HD + kx, row0,   sb);
            tma2d(tiles + 1 * GG_MAT + c * GG_CH, &mXl,  h * HD + kx, row0,   sb);
            tma2d(tiles + 2 * GG_MAT + c * GG_CH, &mWaH, kx,          h * HD, sb);
            tma2d(tiles + 3 * GG_MAT + c * GG_CH, &mWaL, kx,          h * HD, sb);
            tma2d(tiles + 4 * GG_MAT + c * GG_CH, &mWiH, kx,          h * HD, sb);
            tma2d(tiles + 5 * GG_MAT + c * GG_CH, &mWiL, kx,          h * HD, sb);
        }
    }
    mbar_wait(sb, 0);
    __syncthreads();

    uint32_t arow[4], axm[4], brow[2], bxm[2];
    #pragma unroll
    for (int im = 0; im < 4; im++) {
        int r = wm * 64 + im * 16 + (lane & 15);
        arow[im] = (uint32_t)(r * 64);
        axm[im]  = (uint32_t)((r & 6) << 3);
    }
    #pragma unroll
    for (int ip = 0; ip < 2; ip++) {
        int r = wn * 32 + ip * 16 + (lane & 7) + ((lane >> 4) & 1) * 8;
        brow[ip] = (uint32_t)(r * 64);
        bxm[ip]  = (uint32_t)((r & 6) << 3);
    }
    const uint32_t acol = (uint32_t)((lane >> 4) * 16);
    const uint32_t bcol = (uint32_t)(((lane >> 3) & 1) * 16);

    float accR[4][4][4], accI[4][4][4];
    #pragma unroll
    for (int im = 0; im < 4; im++)
        #pragma unroll
        for (int in = 0; in < 4; in++)
            #pragma unroll
            for (int q = 0; q < 4; q++) { accR[im][in][q] = 0.0f; accI[im][in][q] = 0.0f; }

    #pragma unroll
    for (int c = 0; c < 4; c++) {
        const uint32_t sAh = tiles + 0 * GG_MAT + c * GG_CH;
        const uint32_t sAl = tiles + 1 * GG_MAT + c * GG_CH;
        const uint32_t sWa = tiles + 2 * GG_MAT + c * GG_CH;
        const uint32_t sWal= tiles + 3 * GG_MAT + c * GG_CH;
        const uint32_t sWi = tiles + 4 * GG_MAT + c * GG_CH;
        const uint32_t sWil= tiles + 5 * GG_MAT + c * GG_CH;
        #pragma unroll
        for (int kk = 0; kk < 2; kk++) {
            uint32_t ahf[4][4], alf[4][4];
            uint32_t waH[4][2], waL[4][2], wiH[4][2], wiL[4][2];
            #pragma unroll
            for (int im = 0; im < 4; im++) {
                uint32_t rest = (acol + (uint32_t)(kk * 32)) ^ axm[im];
                ldmx4(ahf[im], sAh + arow[im] + rest);
                ldmx4(alf[im], sAl + arow[im] + rest);
            }
            #pragma unroll
            for (int ip = 0; ip < 2; ip++) {
                uint32_t rest = (bcol + (uint32_t)(kk * 32)) ^ bxm[ip];
                uint32_t r4[4];
                ldmx4(r4, sWa + brow[ip] + rest);
                waH[2*ip][0]=r4[0]; waH[2*ip][1]=r4[1]; waH[2*ip+1][0]=r4[2]; waH[2*ip+1][1]=r4[3];
                ldmx4(r4, sWal + brow[ip] + rest);
                waL[2*ip][0]=r4[0]; waL[2*ip][1]=r4[1]; waL[2*ip+1][0]=r4[2]; waL[2*ip+1][1]=r4[3];
                ldmx4(r4, sWi + brow[ip] + rest);
                wiH[2*ip][0]=r4[0]; wiH[2*ip][1]=r4[1]; wiH[2*ip+1][0]=r4[2]; wiH[2*ip+1][1]=r4[3];
                ldmx4(r4, sWil + brow[ip] + rest);
                wiL[2*ip][0]=r4[0]; wiL[2*ip][1]=r4[1]; wiL[2*ip+1][0]=r4[2]; wiL[2*ip+1][1]=r4[3];
            }
            #pragma unroll
            for (int im = 0; im < 4; im++)
                #pragma unroll
                for (int in = 0; in < 4; in++) {
                    mma16816(accR[im][in], ahf[im], waH[in]);
                    mma16816(accR[im][in], alf[im], waH[in]);
                    mma16816(accR[im][in], ahf[im], waL[in]);
                    mma16816(accI[im][in], ahf[im], wiH[in]);
                    mma16816(accI[im][in], alf[im], wiH[in]);
                    mma16816(accI[im][in], ahf[im], wiL[in]);
                }
        }
    }
    // weight tiles (slots 2..5) are dead after this point; xc tiles still live.
    __syncthreads();

    // ---- gate epilogue: write ga/gb to gmem AND stage a,b into smem ----
    const int gid = lane >> 2, t4 = lane & 3;
    #pragma unroll
    for (int in = 0; in < 4; in++) {
        int c0 = wn * 32 + in * 8 + t4 * 2;
        #pragma unroll
        for (int q = 0; q < 2; q++) {
            int col = c0 + q;
            int dd  = h * HD + col;
            float ab_ = ab[dd], ib_ = ib[dd];
            float sp  = log1pf(expf(-apar[dd]));
            int cch = col >> 5;
            uint32_t cb = (uint32_t)((col & 31) * 2);
            uint32_t cbase = (uint32_t)(cch * GG_CH);
            #pragma unroll
            for (int im = 0; im < 4; im++) {
                #pragma unroll
                for (int half = 0; half < 2; half++) {
                    int row = wm * 64 + im * 16 + gid + half * 8;
                    float rv = accR[im][in][half * 2 + q] + ab_;
                    float iv = accI[im][in][half * 2 + q] + ib_;
                    float r  = 1.0f / (1.0f + expf(-rv));
                    float ii = 1.0f / (1.0f + expf(-iv));
                    float la = -8.0f * r * sp;
                    float a  = expf(la);
                    float mult = sqrtf(fmaxf(1.0f - expf(2.0f * la), 0.0f));
                    uint32_t off = cbase + (uint32_t)(row * 64)
                                 + ((cb & 48u) ^ (uint32_t)((row & 6) << 3)) + (cb & 15u);
                    float xcv = __half2float(*reinterpret_cast<const __half*>(
                                    smem + GG_HDR + off))
                              + __half2float(*reinterpret_cast<const __half*>(
                                    smem + GG_HDR + GG_MAT + off));
                    float bt = mult * ii * xcv;
                    size_t g = (size_t)(row0 + row) * D + dd;
                    ga[g]  = a;
                    gbh[g] = __float2half_rn(bt);
                    int sidx = row * 128 + (col ^ (row & 31));   // XOR-swizzled
                    asp[sidx] = a;
                    bsp[sidx] = bt;
                }
            }
        }
    }
    __syncthreads();

    // ---- in-block chunk scan: one thread per column (d within head) ----
    if (tid < 128) {
        int col = tid;
        float hh = 0.0f, A = 1.0f;
        #pragma unroll 4
        for (int row = 0; row < 128; row++) {
            int sidx = row * 128 + (col ^ (row & 31));
            float a = asp[sidx];
            hh = fmaf(a, hh, bsp[sidx]);
            A *= a;
        }
        int bb = row0 / S;
        int cc = (row0 % S) / SC_L;
        size_t o = ((size_t)bb * SC_NC + cc) * D + (size_t)h * HD + col;
        hend[o] = hh;
        aend[o] = A;
    }
}

// =====================================================================
// vectorized transpose to fp16: W[K,N] fp32 -> Wt[N,K] fp16 (64x64 tiles)
// =====================================================================
__global__ void __launch_bounds__(256)
trans_half2(const float* __restrict__ W, __half* __restrict__ Wt, int K, int N)
{
    __shared__ float t[64][65];
    int n0 = blockIdx.x * 64, k0 = blockIdx.y * 64;
    int tid = threadIdx.x;
    int lr = tid >> 4;
    int lc = (tid & 15) * 4;
    #pragma unroll
    for (int i = 0; i < 4; i++) {
        int r = lr + i * 16;
        float4 v = *reinterpret_cast<const float4*>(&W[(size_t)(k0 + r) * N + n0 + lc]);
        t[r][lc] = v.x; t[r][lc + 1] = v.y; t[r][lc + 2] = v.z; t[r][lc + 3] = v.w;
    }
    __syncthreads();
    #pragma unroll
    for (int i = 0; i < 2; i++) {
        int task = tid + i * 256;
        int n  = task >> 3;
        int kg = (task & 7) * 8;
        __half h8[8];
        #pragma unroll
        for (int j = 0; j < 8; j++) h8[j] = __float2half_rn(t[kg + j][n]);
        *reinterpret_cast<uint4*>(&Wt[(size_t)(n0 + n) * K + k0 + kg]) =
            *reinterpret_cast<uint4*>(h8);
    }
}

// gate-weight transpose + hi/lo split: W[H][d][e] -> hi/lo [H][e][d]
__global__ void trans_gate(const float* __restrict__ W,
                           __half* __restrict__ hi, __half* __restrict__ lo)
{
    using namespace hk;
    __shared__ float t[32][33];
    int e0 = blockIdx.x * 32, d0 = blockIdx.y * 32, hh = blockIdx.z;
    int tx = threadIdx.x, ty = threadIdx.y;
    const float* Wh = W + (size_t)hh * HD * HD;
    #pragma unroll
    for (int i = 0; i < 32; i += 8)
        t[ty + i][tx] = Wh[(size_t)(d0 + ty + i) * HD + (e0 + tx)];
    __syncthreads();
    #pragma unroll
    for (int i = 0; i < 32; i += 8) {
        float v = t[tx][ty + i];
        size_t o = ((size_t)hh * HD + (e0 + ty + i)) * HD + (d0 + tx);
        __half a, b; split2h(v, a, b);
        hi[o] = a; lo[o] = b;
    }
}

// ---------------- rmsnorm with fp16 output ----------------
__global__ void rmsnorm_h(const float* __restrict__ x, const float* __restrict__ w,
                          __half* __restrict__ o)
{
    using namespace hk;
    const int row = blockIdx.x;
    const float* xr = x + (size_t)row * D;
    float ss = 0.0f;
    for (int d = threadIdx.x; d < D; d += 256) { float v = xr[d]; ss += v * v; }
    __shared__ float red[8];
    #pragma unroll
    for (int off = 16; off > 0; off >>= 1) ss += __shfl_down_sync(0xffffffffu, ss, off);
    if ((threadIdx.x & 31) == 0) red[threadIdx.x >> 5] = ss;
    __syncthreads();
    if (threadIdx.x < 8) {
        float v = red[threadIdx.x];
        #pragma unroll
        for (int off = 4; off > 0; off >>= 1) v += __shfl_down_sync(0xffu, v, off);
        if (threadIdx.x == 0) red[0] = v;
    }
    __syncthreads();
    const float scale = rsqrtf(red[0] / (float)D + 1e-6f);
    size_t base = (size_t)row * D;
    for (int d = threadIdx.x; d < D; d += 256)
        o[base + d] = __float2half_rn(xr[d] * scale * w[d]);
}

// ---------------- causal depthwise conv, kernel 4; split fp16 output ----------------
__global__ void conv_split(const float* __restrict__ xb, const float* __restrict__ cw,
                           const float* __restrict__ cb,
                           __half* __restrict__ xcH, __half* __restrict__ xcL)
{
    using namespace hk;
    size_t idx = (size_t)blockIdx.x * blockDim.x + threadIdx.x;
    if (idx >= NBSD) return;
    int d = (int)(idx % D);
    int s = (int)((idx / D) % S);
    float acc = cb[d];
    #pragma unroll
    for (int k = 0; k < 4; k++) {
        int ss = s + k - 3;
        if (ss >= 0) acc = fmaf(cw[k * D + d], xb[idx + (size_t)(k - 3) * D], acc);
    }
    __half h, l; split2h(acc, h, l);
    xcH[idx] = h; xcL[idx] = l;
}

// ---------------- scan pass2: combine chunk summaries -> carries + h_last ----
__global__ void scan_pass2(const float* __restrict__ hend, const float* __restrict__ aend,
                           const float* __restrict__ h0, float* __restrict__ carry,
                           float* __restrict__ hlast)
{
    using namespace hk;
    int ch = blockIdx.x * blockDim.x + threadIdx.x;
    if (ch >= B * D) return;
    int b = ch / D, d = ch % D;
    float cur = h0[ch];
    for (int c = 0; c < SC_NC; c++) {
        size_t o = ((size_t)b * SC_NC + c) * D + d;
        carry[o] = cur;
        cur = fmaf(aend[o], cur, hend[o]);
    }
    if (hlast) hlast[ch] = cur;
}

// ---------------- scan pass3: rescan from carry, write z = y*h fp16 ----
__global__ void scan_pass3(const float* __restrict__ ga, const __half* __restrict__ gbh,
                           const float* __restrict__ carry, const __half* __restrict__ yA,
                           __half* __restrict__ zA)
{
    using namespace hk;
    int t = blockIdx.x * blockDim.x + threadIdx.x;
    if (t >= B * SC_NC * D) return;
    int d = t % D;
    int c = (t / D) % SC_NC;
    int b = t / (D * SC_NC);
    float h = carry[((size_t)b * SC_NC + c) * D + d];
    size_t g = ((size_t)b * S + (size_t)c * SC_L) * D + d;
    for (int i = 0; i < SC_L; i++, g += D) {
        h = fmaf(ga[g], h, __half2float(gbh[g]));
        zA[g] = __float2half_rn(__half2float(yA[g]) * h);
    }
}

// =====================================================================
// host-side tensormap encoding (driver symbol via dlsym)
// =====================================================================
typedef CUresult (*EncodeFn)(CUtensorMap*, CUtensorMapDataType, cuuint32_t, void*,
                             const cuuint64_t*, const cuuint64_t*, const cuuint32_t*,
                             const cuuint32_t*, CUtensorMapInterleave, CUtensorMapSwizzle,
                             CUtensorMapL2promotion, CUtensorMapFloatOOBfill);

static EncodeFn get_encode() {
    static EncodeFn fn = nullptr;
    if (!fn) {
        fn = (EncodeFn)dlsym(RTLD_DEFAULT, "cuTensorMapEncodeTiled");
        if (!fn) {
            void* h = dlopen("libcuda.so.1", RTLD_LAZY | RTLD_GLOBAL);
            if (h) fn = (EncodeFn)dlsym(h, "cuTensorMapEncodeTiled");
        }
    }
    return fn;
}

static void enc_map(CUtensorMap* m, void* ptr, uint64_t K, uint64_t ROWS, uint32_t boxRows) {
    cuuint64_t dims[2]    = {K, ROWS};
    cuuint64_t strides[1] = {K * 2};
    cuuint32_t box[2]     = {32, boxRows};
    cuuint32_t es[2]      = {1, 1};
    get_encode()(m, CU_TENSOR_MAP_DATA_TYPE_FLOAT16, 2, ptr, dims, strides, box, es,
                 CU_TENSOR_MAP_INTERLEAVE_NONE, CU_TENSOR_MAP_SWIZZLE_64B,
                 CU_TENSOR_MAP_L2_PROMOTION_L2_128B, CU_TENSOR_MAP_FLOAT_OOB_FILL_NONE);
}

// ---------------- launch ----------------
extern "C" void kernel_launch(void* const* d_in, const int* in_sizes, int n_in,
                              void* d_out, int out_size)
{
    using namespace hk;
    const float* x    = (const float*)d_in[0];
    const float* h0   = (const float*)d_in[1];
    const float* r1w  = (const float*)d_in[2];
    const float* r2w  = (const float*)d_in[3];
    const float* Wx   = (const float*)d_in[4];
    const float* Wy   = (const float*)d_in[5];
    const float* cw   = (const float*)d_in[6];
    const float* cb   = (const float*)d_in[7];
    const float* apar = (const float*)d_in[8];
    const float* igw  = (const float*)d_in[9];
    const float* igb  = (const float*)d_in[10];
    const float* agw  = (const float*)d_in[11];
    const float* agb  = (const float*)d_in[12];
    const float* Wout = (const float*)d_in[13];
    const float* Wg   = (const float*)d_in[14];
    const float* Wu   = (const float*)d_in[15];
    const float* Wd   = (const float*)d_in[16];
    float* out = (float*)d_out;

    float *xb, *ga, *resid, *hend, *aend, *carry;
    cudaGetSymbolAddress((void**)&xb,    g_xb);
    cudaGetSymbolAddress((void**)&ga,    g_ga);
    cudaGetSymbolAddress((void**)&resid, g_resid);
    cudaGetSymbolAddress((void**)&hend,  g_hend);
    cudaGetSymbolAddress((void**)&aend,  g_aend);
    cudaGetSymbolAddress((void**)&carry, g_carry);

    __half *gbh,*nA,*yA,*xcH,*xcL,*zA,*n2A,*GA,*guA;
    __half *tWy,*tWx,*tWo,*tWg,*tWu,*tWd,*aWH,*aWL,*iWH,*iWL;
    cudaGetSymbolAddress((void**)&gbh, g_gbh);
    cudaGetSymbolAddress((void**)&nA,  g_nA);
    cudaGetSymbolAddress((void**)&yA,  g_yA);
    cudaGetSymbolAddress((void**)&xcH, g_xcH); cudaGetSymbolAddress((void**)&xcL, g_xcL);
    cudaGetSymbolAddress((void**)&zA,  g_zA);
    cudaGetSymbolAddress((void**)&n2A, g_n2A);
    cudaGetSymbolAddress((void**)&GA,  g_GA);
    cudaGetSymbolAddress((void**)&guA, g_guA);
    cudaGetSymbolAddress((void**)&tWy, g_Wy);  cudaGetSymbolAddress((void**)&tWx, g_Wx);
    cudaGetSymbolAddress((void**)&tWo, g_Wo);  cudaGetSymbolAddress((void**)&tWg, g_Wg);
    cudaGetSymbolAddress((void**)&tWu, g_Wu);  cudaGetSymbolAddress((void**)&tWd, g_Wd);
    cudaGetSymbolAddress((void**)&aWH, g_aWH); cudaGetSymbolAddress((void**)&aWL, g_aWL);
    cudaGetSymbolAddress((void**)&iWH, g_iWH); cudaGetSymbolAddress((void**)&iWL, g_iWL);

    // ---- tensormaps ----
    static CUtensorMap mnA, mzA, mn2A, mguA;
    static CUtensorMap mWy, mWx, mWo, mWg, mWu, mWd;
    static CUtensorMap mXh, mXl, mWaH, mWaL, mWiH, mWiL;
    enc_map(&mnA,  nA,  D, BS, 128);
    enc_map(&mzA,  zA,  D, BS, 128);
    enc_map(&mn2A, n2A, D, BS, 128);
    enc_map(&mguA, guA, F, BS, 128);
    enc_map(&mWy,  tWy, D, D, 256);   enc_map(&mWx,  tWx, D, D, 256);
    enc_map(&mWo,  tWo, D, D, 256);   enc_map(&mWg,  tWg, D, F, 256);
    enc_map(&mWu,  tWu, D, F, 256);   enc_map(&mWd,  tWd, F, D, 256);
    enc_map(&mXh,  xcH, D, BS, 128);  enc_map(&mXl,  xcL, D, BS, 128);
    enc_map(&mWaH, aWH, HD, (uint64_t)H * HD, 128);
    enc_map(&mWaL, aWL, HD, (uint64_t)H * HD, 128);
    enc_map(&mWiH, iWH, HD, (uint64_t)H * HD, 128);
    enc_map(&mWiL, iWL, HD, (uint64_t)H * HD, 128);

    cudaFuncSetAttribute(gemm_tma<0>, cudaFuncAttributeMaxDynamicSharedMemorySize, GT_SMEM);
    cudaFuncSetAttribute(gemm_tma<2>, cudaFuncAttributeMaxDynamicSharedMemorySize, GT_SMEM);
    cudaFuncSetAttribute(gemm_tma<3>, cudaFuncAttributeMaxDynamicSharedMemorySize, GT_SMEM);
    cudaFuncSetAttribute(gemm_tma<4>, cudaFuncAttributeMaxDynamicSharedMemorySize, GT_SMEM);
    cudaFuncSetAttribute(gate_mma,    cudaFuncAttributeMaxDynamicSharedMemorySize, GG_SMEM);

    const int EW = 256;
    const size_t nbsd_blocks = (NBSD + EW - 1) / EW;
    float* hlast = (out_size >= (int)(NBSD + (size_t)B * D)) ? (out + NBSD) : nullptr;

    // ---- weight transpose to fp16 ----
    trans_half2<<<dim3(D / 64, D / 64), 256>>>(Wy,   tWy, D, D);
    trans_half2<<<dim3(D / 64, D / 64), 256>>>(Wx,   tWx, D, D);
    trans_half2<<<dim3(D / 64, D / 64), 256>>>(Wout, tWo, D, D);
    trans_half2<<<dim3(F / 64, D / 64), 256>>>(Wg,   tWg, D, F);
    trans_half2<<<dim3(F / 64, D / 64), 256>>>(Wu,   tWu, D, F);
    trans_half2<<<dim3(D / 64, F / 64), 256>>>(Wd,   tWd, F, D);
    dim3 tg(HD / 32, HD / 32, H);
    trans_gate<<<tg, dim3(32, 8)>>>(agw, aWH, aWL);
    trans_gate<<<tg, dim3(32, 8)>>>(igw, iWH, iWL);

    // ---- temporal pre-norm ----
    rmsnorm_h<<<BS, 256>>>(x, r1w, nA);

    // ---- y = gelu(normed @ W_y) fp16; xb = normed @ W_x fp32 ----
    dim3 gDD(D / 256, BS / 128);
    gemm_tma<4><<<gDD, 256, GT_SMEM>>>(mnA, mWy, nullptr, nullptr, nullptr, yA, D, D);
    gemm_tma<0><<<gDD, 256, GT_SMEM>>>(mnA, mWx, xb, nullptr, nullptr, nullptr, D, D);

    // ---- causal conv (split fp16 out for gate path) ----
    conv_split<<<(unsigned)nbsd_blocks, EW>>>(xb, cw, cb, xcH, xcL);

    // ---- fused gate GEMM + gate math + chunk-end scan -> ga, gb, hend, aend ----
    gate_mma<<<dim3(BS / 128, H), 256, GG_SMEM>>>(mXh, mXl, mWaH, mWaL, mWiH, mWiL,
                                                  agb, igb, apar, ga, gbh, hend, aend);

    // ---- carries + final rescan fused with y-mul ----
    scan_pass2<<<(B * D + 255) / 256, 256>>>(hend, aend, h0, carry, hlast);
    scan_pass3<<<(B * SC_NC * D + 255) / 256, 256>>>(ga, gbh, carry, yA, zA);

    // ---- residual = z @ W_out + x ----
    gemm_tma<2><<<gDD, 256, GT_SMEM>>>(mzA, mWo, resid, x, nullptr, nullptr, D, D);

    // ---- second norm ----
    rmsnorm_h<<<BS, 256>>>(resid, r2w, n2A);

    // ---- MLP: G = gelu(n2 @ Wg) fp16; gu = (n2 @ Wu) * G fp16 ----
    dim3 gDF(F / 256, BS / 128);
    gemm_tma<4><<<gDF, 256, GT_SMEM>>>(mn2A, mWg, nullptr, nullptr, nullptr, GA, F, D);
    gemm_tma<3><<<gDF, 256, GT_SMEM>>>(mn2A, mWu, nullptr, nullptr, GA, guA, F, D);

    // ---- out = gu @ W_down + residual ----
    gemm_tma<2><<<gDD, 256, GT_SMEM>>>(mguA, mWd, out, resid, nullptr, nullptr, D, F);
}

// round 11
// speedup vs baseline: 8.5331x; 1.0261x over previous
#include <cuda_runtime.h>
#include <cuda.h>
#include <cuda_fp16.h>
#include <math.h>
#include <stdint.h>
#include <dlfcn.h>

// ---------------- problem constants ----------------
namespace hk {
constexpr int B  = 2;
constexpr int S  = 2048;
constexpr int D  = 2048;
constexpr int H  = 16;
constexpr int HD = 128;
constexpr int F  = 8192;
constexpr int BS = B * S;                     // 4096 rows
constexpr size_t NBSD = (size_t)BS * D;       // 8,388,608
constexpr size_t NBSF = (size_t)BS * F;       // 33,554,432
constexpr size_t NDD  = (size_t)D * D;
constexpr size_t NDF  = (size_t)D * F;
constexpr size_t NGW  = (size_t)H * HD * HD;  // 262,144
}

constexpr int SC_NC = 16;                      // scan chunks
constexpr int SC_L  = hk::S / SC_NC;           // 128 steps per chunk

// ---------------- scratch: fp32 intermediates ----------------
__device__ float g_resid [hk::NBSD];
__device__ float g_hend  [hk::B * hk::D * SC_NC];
__device__ float g_aend  [hk::B * hk::D * SC_NC];
__device__ float g_carry [hk::B * hk::D * SC_NC];

// ---------------- scratch: fp16 activations ----------------
__device__ __half g_omah[hk::NBSD];            // 1 - a
__device__ __half g_gbh [hk::NBSD];            // b
__device__ __half g_nA  [hk::NBSD];
__device__ __half g_yA  [hk::NBSD];
__device__ __half g_xbh [hk::NBSD];
__device__ __half g_xcH [hk::NBSD];
__device__ __half g_zA  [hk::NBSD];
__device__ __half g_n2A [hk::NBSD];
__device__ __half g_GA  [hk::NBSF];
__device__ __half g_guA [hk::NBSF];

// ---------------- scratch: fp16 transposed weights [N,K] ----------------
__device__ __half g_Wy[hk::NDD];
__device__ __half g_Wx[hk::NDD];
__device__ __half g_Wo[hk::NDD];
__device__ __half g_Wg[hk::NDF];
__device__ __half g_Wu[hk::NDF];
__device__ __half g_Wd[hk::NDF];
// gate weights, transposed per head [H][e][d], single fp16
__device__ __half g_aWH[hk::NGW];
__device__ __half g_iWH[hk::NGW];

// ---------------- helpers ----------------
__device__ __forceinline__ float gelu_tanh(float x) {
    float x3 = x * x * x;
    return 0.5f * x * (1.0f + tanhf(0.7978845608028654f * (x + 0.044715f * x3)));
}

__device__ __forceinline__ uint32_t s2u(const void* p) {
    uint32_t a;
    asm("{ .reg .u64 t; cvta.to.shared.u64 t, %1; cvt.u32.u64 %0, t; }" : "=r"(a) : "l"(p));
    return a;
}

__device__ __forceinline__ void ldmx4(uint32_t* r, uint32_t a) {
    asm volatile("ldmatrix.sync.aligned.m8n8.x4.shared.b16 {%0,%1,%2,%3}, [%4];"
                 : "=r"(r[0]), "=r"(r[1]), "=r"(r[2]), "=r"(r[3]) : "r"(a));
}

__device__ __forceinline__ void mma16816(float* c, const uint32_t* a, const uint32_t* b) {
    asm volatile(
        "mma.sync.aligned.m16n8k16.row.col.f32.f16.f16.f32 "
        "{%0,%1,%2,%3}, {%4,%5,%6,%7}, {%8,%9}, {%0,%1,%2,%3};"
        : "+f"(c[0]), "+f"(c[1]), "+f"(c[2]), "+f"(c[3])
        : "r"(a[0]), "r"(a[1]), "r"(a[2]), "r"(a[3]), "r"(b[0]), "r"(b[1]));
}

__device__ __forceinline__ void mbar_init(uint32_t mbar, uint32_t cnt) {
    asm volatile("mbarrier.init.shared.b64 [%0], %1;" :: "r"(mbar), "r"(cnt) : "memory");
}

__device__ __forceinline__ void mbar_expect_tx(uint32_t mbar, uint32_t bytes) {
    asm volatile("mbarrier.arrive.expect_tx.shared.b64 _, [%0], %1;"
                 :: "r"(mbar), "r"(bytes) : "memory");
}

__device__ __forceinline__ void mbar_wait(uint32_t mbar, uint32_t phase) {
    asm volatile(
        "{\n\t.reg .pred P;\n\t"
        "WAIT_%=:\n\t"
        "mbarrier.try_wait.parity.shared.b64 P, [%0], %1, 10000000;\n\t"
        "@P bra.uni DONE_%=;\n\t"
        "bra.uni WAIT_%=;\n\t"
        "DONE_%=:\n\t}"
        :: "r"(mbar), "r"(phase) : "memory");
}

__device__ __forceinline__ void tma2d(uint32_t dst, const CUtensorMap* map,
                                      int cx, int cy, uint32_t mbar) {
    asm volatile(
        "cp.async.bulk.tensor.2d.shared::cluster.global.tile.mbarrier::complete_tx::bytes "
        "[%0], [%1, {%2, %3}], [%4];"
        :: "r"(dst), "l"(map), "r"(cx), "r"(cy), "r"(mbar) : "memory");
}

// =====================================================================
// fp16 tensor-core GEMM, TMA loads (SW64), mbarrier 7-stage pipeline,
// TWO K-blocks per __syncthreads.
//   C[M,N](fp32) = A[M,K] @ B[N,K]^T
// CTA tile 128x256, warp tile 64x64 (8 warps 2x4), BK=32.
// EPI: 2 add aux fp32 -> C fp32; 3 multiply by auxh (fp16) -> OH fp16;
//      4 gelu -> OH fp16; 5 plain fp16 -> OH.
// =====================================================================
constexpr int GT_NSTG  = 7;
constexpr int GT_TA    = 128 * 64;              // 8192 B A tile
constexpr int GT_TB    = 256 * 64;              // 16384 B B tile
constexpr int GT_STAGE = GT_TA + GT_TB;         // 24576 B
constexpr int GT_HDR   = 1024;
constexpr int GT_SMEM  = GT_HDR + GT_NSTG * GT_STAGE;   // 173056 B

template<int EPI>
__global__ void __launch_bounds__(256, 1)
gemm_tma(const __grid_constant__ CUtensorMap mA,
         const __grid_constant__ CUtensorMap mB,
         float* __restrict__ C, const float* __restrict__ aux,
         const __half* __restrict__ auxh, __half* __restrict__ OH,
         int N, int K)
{
    extern __shared__ __align__(1024) char smem[];
    const uint32_t sb    = s2u(smem);
    const uint32_t tiles = sb + GT_HDR;

    const int tid  = threadIdx.x;
    const int lane = tid & 31;
    const int wid  = tid >> 5;
    const int wm   = wid >> 2;
    const int wn   = wid & 3;
    const int row0 = blockIdx.y * 128;
    const int col0 = blockIdx.x * 256;
    const int KB   = K >> 5;

    if (tid == 0) {
        #pragma unroll
        for (int s = 0; s < GT_NSTG; s++) mbar_init(sb + s * 8, 1);
    }
    __syncthreads();

    uint32_t arow[4], axm[4], brow[4], bxm[4];
    #pragma unroll
    for (int im = 0; im < 4; im++) {
        int r = wm * 64 + im * 16 + (lane & 15);
        arow[im] = (uint32_t)(r * 64);
        axm[im]  = (uint32_t)((r & 6) << 3);
    }
    #pragma unroll
    for (int ip = 0; ip < 4; ip++) {
        int r = wn * 64 + ip * 16 + (lane & 7) + ((lane >> 4) & 1) * 8;
        brow[ip] = (uint32_t)(r * 64);
        bxm[ip]  = (uint32_t)((r & 6) << 3);
    }
    const uint32_t acol = (uint32_t)((lane >> 4) * 16);
    const uint32_t bcol = (uint32_t)(((lane >> 3) & 1) * 16);

    float acc[4][8][4];
    #pragma unroll
    for (int im = 0; im < 4; im++)
        #pragma unroll
        for (int in = 0; in < 8; in++)
            #pragma unroll
            for (int q = 0; q < 4; q++) acc[im][in][q] = 0.0f;

    auto issue = [&](int kb) {
        int slot = kb % GT_NSTG;
        uint32_t bar = sb + slot * 8;
        uint32_t st  = tiles + (uint32_t)slot * GT_STAGE;
        mbar_expect_tx(bar, (uint32_t)GT_STAGE);
        tma2d(st,         &mA, kb * 32, row0, bar);
        tma2d(st + GT_TA, &mB, kb * 32, col0, bar);
    };

    auto compute = [&](int kb) {
        const uint32_t sA = tiles + (uint32_t)(kb % GT_NSTG) * GT_STAGE;
        const uint32_t sB = sA + GT_TA;
        #pragma unroll
        for (int kk = 0; kk < 2; kk++) {
            uint32_t af[4][4], bf[8][2];
            #pragma unroll
            for (int im = 0; im < 4; im++) {
                uint32_t rest = (acol + (uint32_t)(kk * 32)) ^ axm[im];
                ldmx4(af[im], sA + arow[im] + rest);
            }
            #pragma unroll
            for (int ip = 0; ip < 4; ip++) {
                uint32_t rest = (bcol + (uint32_t)(kk * 32)) ^ bxm[ip];
                uint32_t r4[4];
                ldmx4(r4, sB + brow[ip] + rest);
                bf[2 * ip + 0][0] = r4[0]; bf[2 * ip + 0][1] = r4[1];
                bf[2 * ip + 1][0] = r4[2]; bf[2 * ip + 1][1] = r4[3];
            }
            #pragma unroll
            for (int im = 0; im < 4; im++)
                #pragma unroll
                for (int in = 0; in < 8; in++)
                    mma16816(acc[im][in], af[im], bf[in]);
        }
    };

    if (tid == 0) {
        #pragma unroll
        for (int s = 0; s < GT_NSTG - 1; s++) issue(s);
    }

    for (int kb = 0; kb < KB; kb += 2) {
        mbar_wait(sb + (kb % GT_NSTG) * 8, (uint32_t)((kb / GT_NSTG) & 1));
        compute(kb);
        mbar_wait(sb + ((kb + 1) % GT_NSTG) * 8, (uint32_t)(((kb + 1) / GT_NSTG) & 1));
        compute(kb + 1);
        __syncthreads();
        if (tid == 0) {
            if (kb + GT_NSTG - 1 < KB) issue(kb + GT_NSTG - 1);
            if (kb + GT_NSTG     < KB) issue(kb + GT_NSTG);
        }
    }

    // ---- epilogue ----
    const int gid = lane >> 2, t4 = lane & 3;
    #pragma unroll
    for (int im = 0; im < 4; im++) {
        #pragma unroll
        for (int in = 0; in < 8; in++) {
            int r = row0 + wm * 64 + im * 16 + gid;
            int c = col0 + wn * 64 + in * 8 + t4 * 2;
            #pragma unroll
            for (int half = 0; half < 2; half++) {
                int rr = r + half * 8;
                float v0 = acc[im][in][half * 2 + 0];
                float v1 = acc[im][in][half * 2 + 1];
                if (EPI == 2) {
                    float2 a2 = *reinterpret_cast<const float2*>(aux + (size_t)rr * N + c);
                    v0 += a2.x; v1 += a2.y;
                    float2 o; o.x = v0; o.y = v1;
                    *reinterpret_cast<float2*>(C + (size_t)rr * N + c) = o;
                } else if (EPI == 3) {
                    __half2 a2 = *reinterpret_cast<const __half2*>(auxh + (size_t)rr * N + c);
                    v0 *= __half2float(a2.x); v1 *= __half2float(a2.y);
                    __half2 hp; hp.x = __float2half_rn(v0); hp.y = __float2half_rn(v1);
                    *reinterpret_cast<__half2*>(OH + (size_t)rr * N + c) = hp;
                } else if (EPI == 4) {
                    v0 = gelu_tanh(v0); v1 = gelu_tanh(v1);
                    __half2 hp; hp.x = __float2half_rn(v0); hp.y = __float2half_rn(v1);
                    *reinterpret_cast<__half2*>(OH + (size_t)rr * N + c) = hp;
                } else {   // EPI == 5: plain fp16
                    __half2 hp; hp.x = __float2half_rn(v0); hp.y = __float2half_rn(v1);
                    *reinterpret_cast<__half2*>(OH + (size_t)rr * N + c) = hp;
                }
            }
        }
    }
}

// =====================================================================
// gate_mma: per (128-row block, head) r/i pre-activations with SINGLE
// fp16 xc and gate weights (error analysis: gate pre-acts tiny, sigmoid
// sensitivity gives delta_h/h ~ 5e-5 — safe). Gate math fused; chunk-end
// scan summaries (hend, aend) computed in-block using the SAME quantized
// (1-a, b) values pass3 will use. Outputs: omah fp16, gbh fp16, hend, aend.
// =====================================================================
constexpr int GG_CH   = 8192;
constexpr int GG_MAT  = 4 * GG_CH;            // 32768 B per matrix (K=128)
constexpr int GG_HDR  = 1024;
constexpr int GG_ASP  = GG_HDR + GG_MAT;      // fp32 a-stage, aliases Wa+Wi (64KB)
constexpr int GG_BSP  = GG_HDR + 3 * GG_MAT;  // fp16 b-stage (32KB)
constexpr int GG_SMEM = GG_BSP + 32768;       // 132096 B

__global__ void __launch_bounds__(256, 1)
gate_mma(const __grid_constant__ CUtensorMap mXh,
         const __grid_constant__ CUtensorMap mWaH,
         const __grid_constant__ CUtensorMap mWiH,
         const float* __restrict__ ab, const float* __restrict__ ib,
         const float* __restrict__ apar,
         __half* __restrict__ omah, __half* __restrict__ gbh,
         float* __restrict__ hend, float* __restrict__ aend)
{
    using namespace hk;
    extern __shared__ __align__(1024) char smem[];
    const uint32_t sb    = s2u(smem);
    const uint32_t tiles = sb + GG_HDR;

    const int tid  = threadIdx.x;
    const int lane = tid & 31;
    const int wid  = tid >> 5;
    const int wm   = wid >> 2;
    const int wn   = wid & 3;
    const int row0 = blockIdx.x * 128;
    const int h    = blockIdx.y;

    float* asp = reinterpret_cast<float*>(smem + GG_ASP);
    __half* bsp = reinterpret_cast<__half*>(smem + GG_BSP);

    if (tid == 0) mbar_init(sb, 1);
    __syncthreads();

    if (tid == 0) {
        mbar_expect_tx(sb, (uint32_t)(3 * GG_MAT));
        #pragma unroll
        for (int c = 0; c < 4; c++) {
            int kx = c * 32;
            tma2d(tiles + 0 * GG_MAT + c * GG_CH, &mXh,  h * HD + kx, row0,   sb);
            tma2d(tiles + 1 * GG_MAT + c * GG_CH, &mWaH, kx,          h * HD, sb);
            tma2d(tiles + 2 * GG_MAT + c * GG_CH, &mWiH, kx,          h * HD, sb);
        }
    }
    mbar_wait(sb, 0);
    __syncthreads();

    uint32_t arow[4], axm[4], brow[2], bxm[2];
    #pragma unroll
    for (int im = 0; im < 4; im++) {
        int r = wm * 64 + im * 16 + (lane & 15);
        arow[im] = (uint32_t)(r * 64);
        axm[im]  = (uint32_t)((r & 6) << 3);
    }
    #pragma unroll
    for (int ip = 0; ip < 2; ip++) {
        int r = wn * 32 + ip * 16 + (lane & 7) + ((lane >> 4) & 1) * 8;
        brow[ip] = (uint32_t)(r * 64);
        bxm[ip]  = (uint32_t)((r & 6) << 3);
    }
    const uint32_t acol = (uint32_t)((lane >> 4) * 16);
    const uint32_t bcol = (uint32_t)(((lane >> 3) & 1) * 16);

    float accR[4][4][4], accI[4][4][4];
    #pragma unroll
    for (int im = 0; im < 4; im++)
        #pragma unroll
        for (int in = 0; in < 4; in++)
            #pragma unroll
            for (int q = 0; q < 4; q++) { accR[im][in][q] = 0.0f; accI[im][in][q] = 0.0f; }

    #pragma unroll
    for (int c = 0; c < 4; c++) {
        const uint32_t sAh = tiles + 0 * GG_MAT + c * GG_CH;
        const uint32_t sWa = tiles + 1 * GG_MAT + c * GG_CH;
        const uint32_t sWi = tiles + 2 * GG_MAT + c * GG_CH;
        #pragma unroll
        for (int kk = 0; kk < 2; kk++) {
            uint32_t af[4][4], wa[4][2], wi[4][2];
            #pragma unroll
            for (int im = 0; im < 4; im++) {
                uint32_t rest = (acol + (uint32_t)(kk * 32)) ^ axm[im];
                ldmx4(af[im], sAh + arow[im] + rest);
            }
            #pragma unroll
            for (int ip = 0; ip < 2; ip++) {
                uint32_t rest = (bcol + (uint32_t)(kk * 32)) ^ bxm[ip];
                uint32_t r4[4];
                ldmx4(r4, sWa + brow[ip] + rest);
                wa[2*ip][0]=r4[0]; wa[2*ip][1]=r4[1]; wa[2*ip+1][0]=r4[2]; wa[2*ip+1][1]=r4[3];
                ldmx4(r4, sWi + brow[ip] + rest);
                wi[2*ip][0]=r4[0]; wi[2*ip][1]=r4[1]; wi[2*ip+1][0]=r4[2]; wi[2*ip+1][1]=r4[3];
            }
            #pragma unroll
            for (int im = 0; im < 4; im++)
                #pragma unroll
                for (int in = 0; in < 4; in++) {
                    mma16816(accR[im][in], af[im], wa[in]);
                    mma16816(accI[im][in], af[im], wi[in]);
                }
        }
    }
    // Wa/Wi tiles dead after this; X tile still live (read in epilogue).
    __syncthreads();

    // ---- gate epilogue ----
    const int gid = lane >> 2, t4 = lane & 3;
    #pragma unroll
    for (int in = 0; in < 4; in++) {
        int c0 = wn * 32 + in * 8 + t4 * 2;
        #pragma unroll
        for (int q = 0; q < 2; q++) {
            int col = c0 + q;
            int dd  = h * HD + col;
            float ab_ = ab[dd], ib_ = ib[dd];
            float sp  = log1pf(expf(-apar[dd]));
            int cch = col >> 5;
            uint32_t cb = (uint32_t)((col & 31) * 2);
            uint32_t cbase = (uint32_t)(cch * GG_CH);
            #pragma unroll
            for (int im = 0; im < 4; im++) {
                #pragma unroll
                for (int half = 0; half < 2; half++) {
                    int row = wm * 64 + im * 16 + gid + half * 8;
                    float rv = accR[im][in][half * 2 + q] + ab_;
                    float iv = accI[im][in][half * 2 + q] + ib_;
                    float r  = 1.0f / (1.0f + expf(-rv));
                    float ii = 1.0f / (1.0f + expf(-iv));
                    float la = -8.0f * r * sp;
                    float a  = expf(la);
                    __half omh = __float2half_rn(1.0f - a);
                    float aq = 1.0f - __half2float(omh);     // quantized a (pass3-consistent)
                    float mult = sqrtf(fmaxf(1.0f - expf(2.0f * la), 0.0f));
                    uint32_t off = cbase + (uint32_t)(row * 64)
                                 + ((cb & 48u) ^ (uint32_t)((row & 6) << 3)) + (cb & 15u);
                    float xcv = __half2float(*reinterpret_cast<const __half*>(
                                    smem + GG_HDR + off));
                    __half bh = __float2half_rn(mult * ii * xcv);
                    size_t g = (size_t)(row0 + row) * D + dd;
                    omah[g] = omh;
                    gbh[g]  = bh;
                    int sidx = row * 128 + (col ^ (row & 31));
                    asp[sidx] = aq;
                    bsp[sidx] = bh;
                }
            }
        }
    }
    __syncthreads();

    // ---- in-block chunk scan: one thread per column ----
    if (tid < 128) {
        int col = tid;
        float hh = 0.0f, A = 1.0f;
        #pragma unroll 4
        for (int row = 0; row < 128; row++) {
            int sidx = row * 128 + (col ^ (row & 31));
            float a = asp[sidx];
            hh = fmaf(a, hh, __half2float(bsp[sidx]));
            A *= a;
        }
        int bb = row0 / S;
        int cc = (row0 % S) / SC_L;
        size_t o = ((size_t)bb * SC_NC + cc) * D + (size_t)h * HD + col;
        hend[o] = hh;
        aend[o] = A;
    }
}

// =====================================================================
// combined weight transpose/convert: all 6 weights in ONE launch.
// W[K,N] fp32 -> Wt[N,K] fp16, 64x64 tiles.
// Block ranges: Wy[0,1024) Wx[1024,2048) Wo[2048,3072)
//               Wg[3072,7168) Wu[7168,11264) Wd[11264,15360)
// =====================================================================
__global__ void __launch_bounds__(256)
trans_all(const float* __restrict__ W0, __half* __restrict__ T0,
          const float* __restrict__ W1, __half* __restrict__ T1,
          const float* __restrict__ W2, __half* __restrict__ T2,
          const float* __restrict__ W3, __half* __restrict__ T3,
          const float* __restrict__ W4, __half* __restrict__ T4,
          const float* __restrict__ W5, __half* __restrict__ T5)
{
    using namespace hk;
    __shared__ float t[64][65];
    int b = blockIdx.x;
    const float* W; __half* Wt; int K, N, lb;
    if      (b < 1024)  { W = W0; Wt = T0; K = D; N = D; lb = b; }
    else if (b < 2048)  { W = W1; Wt = T1; K = D; N = D; lb = b - 1024; }
    else if (b < 3072)  { W = W2; Wt = T2; K = D; N = D; lb = b - 2048; }
    else if (b < 7168)  { W = W3; Wt = T3; K = D; N = F; lb = b - 3072; }
    else if (b < 11264) { W = W4; Wt = T4; K = D; N = F; lb = b - 7168; }
    else                { W = W5; Wt = T5; K = F; N = D; lb = b - 11264; }
    int nbx = N >> 6;
    int n0 = (lb % nbx) * 64, k0 = (lb / nbx) * 64;

    int tid = threadIdx.x;
    int lr = tid >> 4;
    int lc = (tid & 15) * 4;
    #pragma unroll
    for (int i = 0; i < 4; i++) {
        int r = lr + i * 16;
        float4 v = *reinterpret_cast<const float4*>(&W[(size_t)(k0 + r) * N + n0 + lc]);
        t[r][lc] = v.x; t[r][lc + 1] = v.y; t[r][lc + 2] = v.z; t[r][lc + 3] = v.w;
    }
    __syncthreads();
    #pragma unroll
    for (int i = 0; i < 2; i++) {
        int task = tid + i * 256;
        int n  = task >> 3;
        int kg = (task & 7) * 8;
        __half h8[8];
        #pragma unroll
        for (int j = 0; j < 8; j++) h8[j] = __float2half_rn(t[kg + j][n]);
        *reinterpret_cast<uint4*>(&Wt[(size_t)(n0 + n) * K + k0 + kg]) =
            *reinterpret_cast<uint4*>(h8);
    }
}

// gate-weight transpose: W[H][d][e] fp32 -> [H][e][d] fp16 (single)
__global__ void trans_gateH(const float* __restrict__ W, __half* __restrict__ hi)
{
    using namespace hk;
    __shared__ float t[32][33];
    int e0 = blockIdx.x * 32, d0 = blockIdx.y * 32, hh = blockIdx.z;
    int tx = threadIdx.x, ty = threadIdx.y;
    const float* Wh = W + (size_t)hh * HD * HD;
    #pragma unroll
    for (int i = 0; i < 32; i += 8)
        t[ty + i][tx] = Wh[(size_t)(d0 + ty + i) * HD + (e0 + tx)];
    __syncthreads();
    #pragma unroll
    for (int i = 0; i < 32; i += 8) {
        size_t o = ((size_t)hh * HD + (e0 + ty + i)) * HD + (d0 + tx);
        hi[o] = __float2half_rn(t[tx][ty + i]);
    }
}

// ---------------- rmsnorm with fp16 output ----------------
__global__ void rmsnorm_h(const float* __restrict__ x, const float* __restrict__ w,
                          __half* __restrict__ o)
{
    using namespace hk;
    const int row = blockIdx.x;
    const float* xr = x + (size_t)row * D;
    float ss = 0.0f;
    for (int d = threadIdx.x; d < D; d += 256) { float v = xr[d]; ss += v * v; }
    __shared__ float red[8];
    #pragma unroll
    for (int off = 16; off > 0; off >>= 1) ss += __shfl_down_sync(0xffffffffu, ss, off);
    if ((threadIdx.x & 31) == 0) red[threadIdx.x >> 5] = ss;
    __syncthreads();
    if (threadIdx.x < 8) {
        float v = red[threadIdx.x];
        #pragma unroll
        for (int off = 4; off > 0; off >>= 1) v += __shfl_down_sync(0xffu, v, off);
        if (threadIdx.x == 0) red[0] = v;
    }
    __syncthreads();
    const float scale = rsqrtf(red[0] / (float)D + 1e-6f);
    size_t base = (size_t)row * D;
    for (int d = threadIdx.x; d < D; d += 256)
        o[base + d] = __float2half_rn(xr[d] * scale * w[d]);
}

// ---------------- causal depthwise conv, kernel 4; fp16 in, fp16 out ----------------
__global__ void conv_h(const __half* __restrict__ xbh, const float* __restrict__ cw,
                       const float* __restrict__ cb, __half* __restrict__ xcH)
{
    using namespace hk;
    size_t idx = (size_t)blockIdx.x * blockDim.x + threadIdx.x;
    if (idx >= NBSD) return;
    int d = (int)(idx % D);
    int s = (int)((idx / D) % S);
    float acc = cb[d];
    #pragma unroll
    for (int k = 0; k < 4; k++) {
        int ss = s + k - 3;
        if (ss >= 0)
            acc = fmaf(cw[k * D + d], __half2float(xbh[idx + (size_t)(k - 3) * D]), acc);
    }
    xcH[idx] = __float2half_rn(acc);
}

// ---------------- scan pass2: combine chunk summaries -> carries + h_last ----
__global__ void scan_pass2(const float* __restrict__ hend, const float* __restrict__ aend,
                           const float* __restrict__ h0, float* __restrict__ carry,
                           float* __restrict__ hlast)
{
    using namespace hk;
    int ch = blockIdx.x * blockDim.x + threadIdx.x;
    if (ch >= B * D) return;
    int b = ch / D, d = ch % D;
    float cur = h0[ch];
    for (int c = 0; c < SC_NC; c++) {
        size_t o = ((size_t)b * SC_NC + c) * D + d;
        carry[o] = cur;
        cur = fmaf(aend[o], cur, hend[o]);
    }
    if (hlast) hlast[ch] = cur;
}

// ---------------- scan pass3: rescan from carry, write z = y*h fp16 ----
__global__ void scan_pass3(const __half* __restrict__ omah, const __half* __restrict__ gbh,
                           const float* __restrict__ carry, const __half* __restrict__ yA,
                           __half* __restrict__ zA)
{
    using namespace hk;
    int t = blockIdx.x * blockDim.x + threadIdx.x;
    if (t >= B * SC_NC * D) return;
    int d = t % D;
    int c = (t / D) % SC_NC;
    int b = t / (D * SC_NC);
    float h = carry[((size_t)b * SC_NC + c) * D + d];
    size_t g = ((size_t)b * S + (size_t)c * SC_L) * D + d;
    for (int i = 0; i < SC_L; i++, g += D) {
        float a = 1.0f - __half2float(omah[g]);
        h = fmaf(a, h, __half2float(gbh[g]));
        zA[g] = __float2half_rn(__half2float(yA[g]) * h);
    }
}

// =====================================================================
// host-side tensormap encoding (driver symbol via dlsym)
// =====================================================================
typedef CUresult (*EncodeFn)(CUtensorMap*, CUtensorMapDataType, cuuint32_t, void*,
                             const cuuint64_t*, const cuuint64_t*, const cuuint32_t*,
                             const cuuint32_t*, CUtensorMapInterleave, CUtensorMapSwizzle,
                             CUtensorMapL2promotion, CUtensorMapFloatOOBfill);

static EncodeFn get_encode() {
    static EncodeFn fn = nullptr;
    if (!fn) {
        fn = (EncodeFn)dlsym(RTLD_DEFAULT, "cuTensorMapEncodeTiled");
        if (!fn) {
            void* h = dlopen("libcuda.so.1", RTLD_LAZY | RTLD_GLOBAL);
            if (h) fn = (EncodeFn)dlsym(h, "cuTensorMapEncodeTiled");
        }
    }
    return fn;
}

static void enc_map(CUtensorMap* m, void* ptr, uint64_t K, uint64_t ROWS, uint32_t boxRows) {
    cuuint64_t dims[2]    = {K, ROWS};
    cuuint64_t strides[1] = {K * 2};
    cuuint32_t box[2]     = {32, boxRows};
    cuuint32_t es[2]      = {1, 1};
    get_encode()(m, CU_TENSOR_MAP_DATA_TYPE_FLOAT16, 2, ptr, dims, strides, box, es,
                 CU_TENSOR_MAP_INTERLEAVE_NONE, CU_TENSOR_MAP_SWIZZLE_64B,
                 CU_TENSOR_MAP_L2_PROMOTION_L2_128B, CU_TENSOR_MAP_FLOAT_OOB_FILL_NONE);
}

// ---------------- launch ----------------
extern "C" void kernel_launch(void* const* d_in, const int* in_sizes, int n_in,
                              void* d_out, int out_size)
{
    using namespace hk;
    const float* x    = (const float*)d_in[0];
    const float* h0   = (const float*)d_in[1];
    const float* r1w  = (const float*)d_in[2];
    const float* r2w  = (const float*)d_in[3];
    const float* Wx   = (const float*)d_in[4];
    const float* Wy   = (const float*)d_in[5];
    const float* cw   = (const float*)d_in[6];
    const float* cb   = (const float*)d_in[7];
    const float* apar = (const float*)d_in[8];
    const float* igw  = (const float*)d_in[9];
    const float* igb  = (const float*)d_in[10];
    const float* agw  = (const float*)d_in[11];
    const float* agb  = (const float*)d_in[12];
    const float* Wout = (const float*)d_in[13];
    const float* Wg   = (const float*)d_in[14];
    const float* Wu   = (const float*)d_in[15];
    const float* Wd   = (const float*)d_in[16];
    float* out = (float*)d_out;

    float *resid, *hend, *aend, *carry;
    cudaGetSymbolAddress((void**)&resid, g_resid);
    cudaGetSymbolAddress((void**)&hend,  g_hend);
    cudaGetSymbolAddress((void**)&aend,  g_aend);
    cudaGetSymbolAddress((void**)&carry, g_carry);

    __half *omah,*gbh,*nA,*yA,*xbh,*xcH,*zA,*n2A,*GA,*guA;
    __half *tWy,*tWx,*tWo,*tWg,*tWu,*tWd,*aWH,*iWH;
    cudaGetSymbolAddress((void**)&omah, g_omah);
    cudaGetSymbolAddress((void**)&gbh, g_gbh);
    cudaGetSymbolAddress((void**)&nA,  g_nA);
    cudaGetSymbolAddress((void**)&yA,  g_yA);
    cudaGetSymbolAddress((void**)&xbh, g_xbh);
    cudaGetSymbolAddress((void**)&xcH, g_xcH);
    cudaGetSymbolAddress((void**)&zA,  g_zA);
    cudaGetSymbolAddress((void**)&n2A, g_n2A);
    cudaGetSymbolAddress((void**)&GA,  g_GA);
    cudaGetSymbolAddress((void**)&guA, g_guA);
    cudaGetSymbolAddress((void**)&tWy, g_Wy);  cudaGetSymbolAddress((void**)&tWx, g_Wx);
    cudaGetSymbolAddress((void**)&tWo, g_Wo);  cudaGetSymbolAddress((void**)&tWg, g_Wg);
    cudaGetSymbolAddress((void**)&tWu, g_Wu);  cudaGetSymbolAddress((void**)&tWd, g_Wd);
    cudaGetSymbolAddress((void**)&aWH, g_aWH); cudaGetSymbolAddress((void**)&iWH, g_iWH);

    // ---- tensormaps ----
    static CUtensorMap mnA, mzA, mn2A, mguA;
    static CUtensorMap mWy, mWx, mWo, mWg, mWu, mWd;
    static CUtensorMap mXh, mWaH, mWiH;
    enc_map(&mnA,  nA,  D, BS, 128);
    enc_map(&mzA,  zA,  D, BS, 128);
    enc_map(&mn2A, n2A, D, BS, 128);
    enc_map(&mguA, guA, F, BS, 128);
    enc_map(&mWy,  tWy, D, D, 256);   enc_map(&mWx,  tWx, D, D, 256);
    enc_map(&mWo,  tWo, D, D, 256);   enc_map(&mWg,  tWg, D, F, 256);
    enc_map(&mWu,  tWu, D, F, 256);   enc_map(&mWd,  tWd, F, D, 256);
    enc_map(&mXh,  xcH, D, BS, 128);
    enc_map(&mWaH, aWH, HD, (uint64_t)H * HD, 128);
    enc_map(&mWiH, iWH, HD, (uint64_t)H * HD, 128);

    cudaFuncSetAttribute(gemm_tma<2>, cudaFuncAttributeMaxDynamicSharedMemorySize, GT_SMEM);
    cudaFuncSetAttribute(gemm_tma<3>, cudaFuncAttributeMaxDynamicSharedMemorySize, GT_SMEM);
    cudaFuncSetAttribute(gemm_tma<4>, cudaFuncAttributeMaxDynamicSharedMemorySize, GT_SMEM);
    cudaFuncSetAttribute(gemm_tma<5>, cudaFuncAttributeMaxDynamicSharedMemorySize, GT_SMEM);
    cudaFuncSetAttribute(gate_mma,    cudaFuncAttributeMaxDynamicSharedMemorySize, GG_SMEM);

    const int EW = 256;
    const size_t nbsd_blocks = (NBSD + EW - 1) / EW;
    float* hlast = (out_size >= (int)(NBSD + (size_t)B * D)) ? (out + NBSD) : nullptr;

    // ---- combined weight transpose/convert (1 launch) ----
    trans_all<<<15360, 256>>>(Wy, tWy, Wx, tWx, Wout, tWo, Wg, tWg, Wu, tWu, Wd, tWd);
    dim3 tg(HD / 32, HD / 32, H);
    trans_gateH<<<tg, dim3(32, 8)>>>(agw, aWH);
    trans_gateH<<<tg, dim3(32, 8)>>>(igw, iWH);

    // ---- temporal pre-norm ----
    rmsnorm_h<<<BS, 256>>>(x, r1w, nA);

    // ---- y = gelu(normed @ W_y) fp16; xb = normed @ W_x fp16 ----
    dim3 gDD(D / 256, BS / 128);
    gemm_tma<4><<<gDD, 256, GT_SMEM>>>(mnA, mWy, nullptr, nullptr, nullptr, yA, D, D);
    gemm_tma<5><<<gDD, 256, GT_SMEM>>>(mnA, mWx, nullptr, nullptr, nullptr, xbh, D, D);

    // ---- causal conv (fp16 in/out) ----
    conv_h<<<(unsigned)nbsd_blocks, EW>>>(xbh, cw, cb, xcH);

    // ---- fused gate GEMM + gate math + chunk-end scan ----
    gate_mma<<<dim3(BS / 128, H), 256, GG_SMEM>>>(mXh, mWaH, mWiH,
                                                  agb, igb, apar, omah, gbh, hend, aend);

    // ---- carries + final rescan fused with y-mul ----
    scan_pass2<<<(B * D + 255) / 256, 256>>>(hend, aend, h0, carry, hlast);
    scan_pass3<<<(B * SC_NC * D + 255) / 256, 256>>>(omah, gbh, carry, yA, zA);

    // ---- residual = z @ W_out + x ----
    gemm_tma<2><<<gDD, 256, GT_SMEM>>>(mzA, mWo, resid, x, nullptr, nullptr, D, D);

    // ---- second norm ----
    rmsnorm_h<<<BS, 256>>>(resid, r2w, n2A);

    // ---- MLP: G = gelu(n2 @ Wg) fp16; gu = (n2 @ Wu) * G fp16 ----
    dim3 gDF(F / 256, BS / 128);
    gemm_tma<4><<<gDF, 256, GT_SMEM>>>(mn2A, mWg, nullptr, nullptr, nullptr, GA, F, D);
    gemm_tma<3><<<gDF, 256, GT_SMEM>>>(mn2A, mWu, nullptr, nullptr, GA, guA, F, D);

    // ---- out = gu @ W_down + residual ----
    gemm_tma<2><<<gDD, 256, GT_SMEM>>>(mguA, mWd, out, resid, nullptr, nullptr, D, F);
}

// round 12
// speedup vs baseline: 8.7537x; 1.0259x over previous
#include <cuda_runtime.h>
#include <cuda.h>
#include <cuda_fp16.h>
#include <math.h>
#include <stdint.h>
#include <dlfcn.h>

// ---------------- problem constants ----------------
namespace hk {
constexpr int B  = 2;
constexpr int S  = 2048;
constexpr int D  = 2048;
constexpr int H  = 16;
constexpr int HD = 128;
constexpr int F  = 8192;
constexpr int BS = B * S;                     // 4096 rows
constexpr size_t NBSD = (size_t)BS * D;       // 8,388,608
constexpr size_t NBSF = (size_t)BS * F;       // 33,554,432
constexpr size_t NDD  = (size_t)D * D;
constexpr size_t NDF  = (size_t)D * F;
constexpr size_t NGW  = (size_t)H * HD * HD;  // 262,144
}

constexpr int SC_NC = 16;                      // scan chunks
constexpr int SC_L  = hk::S / SC_NC;           // 128 steps per chunk

// ---------------- scratch: fp32 intermediates ----------------
__device__ float g_resid [hk::NBSD];
__device__ float g_hend  [hk::B * hk::D * SC_NC];
__device__ float g_aend  [hk::B * hk::D * SC_NC];
__device__ float g_carry [hk::B * hk::D * SC_NC];

// ---------------- scratch: fp16 activations ----------------
__device__ __half g_omah[hk::NBSD];            // 1 - a
__device__ __half g_gbh [hk::NBSD];            // b
__device__ __half g_nA  [hk::NBSD];
__device__ __half g_yA  [hk::NBSD];
__device__ __half g_xbh [hk::NBSD];
__device__ __half g_xcH [hk::NBSD];
__device__ __half g_zA  [hk::NBSD];
__device__ __half g_n2A [hk::NBSD];
__device__ __half g_GA  [hk::NBSF];
__device__ __half g_guA [hk::NBSF];

// ---------------- scratch: fp16 transposed weights [N,K] ----------------
__device__ __half g_Wyx[2 * hk::NDD];          // [Wy ; Wx] concatenated on N
__device__ __half g_Wo[hk::NDD];
__device__ __half g_Wg[hk::NDF];
__device__ __half g_Wu[hk::NDF];
__device__ __half g_Wd[hk::NDF];
// gate weights, transposed per head [H][e][d], single fp16
__device__ __half g_aWH[hk::NGW];
__device__ __half g_iWH[hk::NGW];

// ---------------- helpers ----------------
__device__ __forceinline__ float gelu_tanh(float x) {
    float x3 = x * x * x;
    return 0.5f * x * (1.0f + tanhf(0.7978845608028654f * (x + 0.044715f * x3)));
}

__device__ __forceinline__ uint32_t s2u(const void* p) {
    uint32_t a;
    asm("{ .reg .u64 t; cvta.to.shared.u64 t, %1; cvt.u32.u64 %0, t; }" : "=r"(a) : "l"(p));
    return a;
}

__device__ __forceinline__ void ldmx4(uint32_t* r, uint32_t a) {
    asm volatile("ldmatrix.sync.aligned.m8n8.x4.shared.b16 {%0,%1,%2,%3}, [%4];"
                 : "=r"(r[0]), "=r"(r[1]), "=r"(r[2]), "=r"(r[3]) : "r"(a));
}

__device__ __forceinline__ void mma16816(float* c, const uint32_t* a, const uint32_t* b) {
    asm volatile(
        "mma.sync.aligned.m16n8k16.row.col.f32.f16.f16.f32 "
        "{%0,%1,%2,%3}, {%4,%5,%6,%7}, {%8,%9}, {%0,%1,%2,%3};"
        : "+f"(c[0]), "+f"(c[1]), "+f"(c[2]), "+f"(c[3])
        : "r"(a[0]), "r"(a[1]), "r"(a[2]), "r"(a[3]), "r"(b[0]), "r"(b[1]));
}

__device__ __forceinline__ void mbar_init(uint32_t mbar, uint32_t cnt) {
    asm volatile("mbarrier.init.shared.b64 [%0], %1;" :: "r"(mbar), "r"(cnt) : "memory");
}

__device__ __forceinline__ void mbar_expect_tx(uint32_t mbar, uint32_t bytes) {
    asm volatile("mbarrier.arrive.expect_tx.shared.b64 _, [%0], %1;"
                 :: "r"(mbar), "r"(bytes) : "memory");
}

__device__ __forceinline__ void mbar_wait(uint32_t mbar, uint32_t phase) {
    asm volatile(
        "{\n\t.reg .pred P;\n\t"
        "WAIT_%=:\n\t"
        "mbarrier.try_wait.parity.shared.b64 P, [%0], %1, 10000000;\n\t"
        "@P bra.uni DONE_%=;\n\t"
        "bra.uni WAIT_%=;\n\t"
        "DONE_%=:\n\t}"
        :: "r"(mbar), "r"(phase) : "memory");
}

__device__ __forceinline__ void tma2d(uint32_t dst, const CUtensorMap* map,
                                      int cx, int cy, uint32_t mbar) {
    asm volatile(
        "cp.async.bulk.tensor.2d.shared::cluster.global.tile.mbarrier::complete_tx::bytes "
        "[%0], [%1, {%2, %3}], [%4];"
        :: "r"(dst), "l"(map), "r"(cx), "r"(cy), "r"(mbar) : "memory");
}

// =====================================================================
// GEMM core shared constants
// =====================================================================
constexpr int GT_NSTG  = 7;
constexpr int GT_TA    = 128 * 64;              // 8192 B A tile
constexpr int GT_TB    = 256 * 64;              // 16384 B B tile
constexpr int GT_STAGE = GT_TA + GT_TB;         // 24576 B
constexpr int GT_HDR   = 1024;
constexpr int GT_SMEM  = GT_HDR + GT_NSTG * GT_STAGE;   // 173056 B

// mainloop macro body shared by both GEMM kernels (identical numerics)
#define GEMM_MAINLOOP(mA_, mB_)                                                   \
    const uint32_t sb    = s2u(smem);                                             \
    const uint32_t tiles = sb + GT_HDR;                                           \
    const int tid  = threadIdx.x;                                                 \
    const int lane = tid & 31;                                                    \
    const int wid  = tid >> 5;                                                    \
    const int wm   = wid >> 2;                                                    \
    const int wn   = wid & 3;                                                     \
    const int row0 = blockIdx.y * 128;                                            \
    const int col0 = blockIdx.x * 256;                                            \
    const int KB   = K >> 5;                                                      \
    if (tid == 0) {                                                               \
        _Pragma("unroll")                                                         \
        for (int s = 0; s < GT_NSTG; s++) mbar_init(sb + s * 8, 1);               \
    }                                                                             \
    __syncthreads();                                                              \
    uint32_t arow[4], axm[4], brow[4], bxm[4];                                    \
    _Pragma("unroll")                                                             \
    for (int im = 0; im < 4; im++) {                                              \
        int r = wm * 64 + im * 16 + (lane & 15);                                  \
        arow[im] = (uint32_t)(r * 64);                                            \
        axm[im]  = (uint32_t)((r & 6) << 3);                                      \
    }                                                                             \
    _Pragma("unroll")                                                             \
    for (int ip = 0; ip < 4; ip++) {                                              \
        int r = wn * 64 + ip * 16 + (lane & 7) + ((lane >> 4) & 1) * 8;           \
        brow[ip] = (uint32_t)(r * 64);                                            \
        bxm[ip]  = (uint32_t)((r & 6) << 3);                                      \
    }                                                                             \
    const uint32_t acol = (uint32_t)((lane >> 4) * 16);                           \
    const uint32_t bcol = (uint32_t)(((lane >> 3) & 1) * 16);                     \
    float acc[4][8][4];                                                           \
    _Pragma("unroll")                                                             \
    for (int im = 0; im < 4; im++)                                                \
        _Pragma("unroll")                                                         \
        for (int in = 0; in < 8; in++)                                            \
            _Pragma("unroll")                                                     \
            for (int q = 0; q < 4; q++) acc[im][in][q] = 0.0f;                    \
    auto issue = [&](int kb) {                                                    \
        int slot = kb % GT_NSTG;                                                  \
        uint32_t bar = sb + slot * 8;                                             \
        uint32_t st  = tiles + (uint32_t)slot * GT_STAGE;                         \
        mbar_expect_tx(bar, (uint32_t)GT_STAGE);                                  \
        tma2d(st,         &mA_, kb * 32, row0, bar);                              \
        tma2d(st + GT_TA, &mB_, kb * 32, col0, bar);                              \
    };                                                                            \
    auto compute = [&](int kb) {                                                  \
        const uint32_t sA = tiles + (uint32_t)(kb % GT_NSTG) * GT_STAGE;          \
        const uint32_t sB = sA + GT_TA;                                           \
        _Pragma("unroll")                                                         \
        for (int kk = 0; kk < 2; kk++) {                                          \
            uint32_t af[4][4], bf[8][2];                                          \
            _Pragma("unroll")                                                     \
            for (int im = 0; im < 4; im++) {                                      \
                uint32_t rest = (acol + (uint32_t)(kk * 32)) ^ axm[im];           \
                ldmx4(af[im], sA + arow[im] + rest);                              \
            }                                                                     \
            _Pragma("unroll")                                                     \
            for (int ip = 0; ip < 4; ip++) {                                      \
                uint32_t rest = (bcol + (uint32_t)(kk * 32)) ^ bxm[ip];           \
                uint32_t r4[4];                                                   \
                ldmx4(r4, sB + brow[ip] + rest);                                  \
                bf[2 * ip + 0][0] = r4[0]; bf[2 * ip + 0][1] = r4[1];             \
                bf[2 * ip + 1][0] = r4[2]; bf[2 * ip + 1][1] = r4[3];             \
            }                                                                     \
            _Pragma("unroll")                                                     \
            for (int im = 0; im < 4; im++)                                        \
                _Pragma("unroll")                                                 \
                for (int in = 0; in < 8; in++)                                    \
                    mma16816(acc[im][in], af[im], bf[in]);                        \
        }                                                                         \
    };                                                                            \
    if (tid == 0) {                                                               \
        _Pragma("unroll")                                                         \
        for (int s = 0; s < GT_NSTG - 1; s++) issue(s);                           \
    }                                                                             \
    for (int kb = 0; kb < KB; kb += 2) {                                          \
        mbar_wait(sb + (kb % GT_NSTG) * 8, (uint32_t)((kb / GT_NSTG) & 1));       \
        compute(kb);                                                              \
        mbar_wait(sb + ((kb + 1) % GT_NSTG) * 8,                                  \
                  (uint32_t)(((kb + 1) / GT_NSTG) & 1));                          \
        compute(kb + 1);                                                          \
        __syncthreads();                                                          \
        if (tid == 0) {                                                           \
            if (kb + GT_NSTG - 1 < KB) issue(kb + GT_NSTG - 1);                   \
            if (kb + GT_NSTG     < KB) issue(kb + GT_NSTG);                       \
        }                                                                         \
    }

// =====================================================================
// gemm_tma: EPI 2 add aux fp32 -> C fp32; 3 mul auxh fp16 -> OH fp16;
//           4 gelu -> OH fp16.
// =====================================================================
template<int EPI>
__global__ void __launch_bounds__(256, 1)
gemm_tma(const __grid_constant__ CUtensorMap mA,
         const __grid_constant__ CUtensorMap mB,
         float* __restrict__ C, const float* __restrict__ aux,
         const __half* __restrict__ auxh, __half* __restrict__ OH,
         int N, int K)
{
    extern __shared__ __align__(1024) char smem[];
    GEMM_MAINLOOP(mA, mB)

    const int gid = lane >> 2, t4 = lane & 3;
    #pragma unroll
    for (int im = 0; im < 4; im++) {
        #pragma unroll
        for (int in = 0; in < 8; in++) {
            int r = row0 + wm * 64 + im * 16 + gid;
            int c = col0 + wn * 64 + in * 8 + t4 * 2;
            #pragma unroll
            for (int half = 0; half < 2; half++) {
                int rr = r + half * 8;
                float v0 = acc[im][in][half * 2 + 0];
                float v1 = acc[im][in][half * 2 + 1];
                if (EPI == 2) {
                    float2 a2 = *reinterpret_cast<const float2*>(aux + (size_t)rr * N + c);
                    v0 += a2.x; v1 += a2.y;
                    float2 o; o.x = v0; o.y = v1;
                    *reinterpret_cast<float2*>(C + (size_t)rr * N + c) = o;
                } else if (EPI == 3) {
                    __half2 a2 = *reinterpret_cast<const __half2*>(auxh + (size_t)rr * N + c);
                    v0 *= __half2float(a2.x); v1 *= __half2float(a2.y);
                    __half2 hp; hp.x = __float2half_rn(v0); hp.y = __float2half_rn(v1);
                    *reinterpret_cast<__half2*>(OH + (size_t)rr * N + c) = hp;
                } else {   // EPI == 4: gelu
                    v0 = gelu_tanh(v0); v1 = gelu_tanh(v1);
                    __half2 hp; hp.x = __float2half_rn(v0); hp.y = __float2half_rn(v1);
                    *reinterpret_cast<__half2*>(OH + (size_t)rr * N + c) = hp;
                }
            }
        }
    }
}

// =====================================================================
// gemm_dual: combined Wy+Wx GEMM over concatenated B [2*NOUT, K].
// Columns [0, NOUT): gelu -> O1; [NOUT, 2*NOUT): plain -> O2.
// Branch is CTA-uniform (NOUT % 256 == 0).
// =====================================================================
__global__ void __launch_bounds__(256, 1)
gemm_dual(const __grid_constant__ CUtensorMap mA,
          const __grid_constant__ CUtensorMap mB,
          __half* __restrict__ O1, __half* __restrict__ O2,
          int NOUT, int K)
{
    extern __shared__ __align__(1024) char smem[];
    GEMM_MAINLOOP(mA, mB)

    const bool side = (col0 >= NOUT);
    __half* dst = side ? O2 : O1;
    const int cb0 = side ? (col0 - NOUT) : col0;

    const int gid = lane >> 2, t4 = lane & 3;
    #pragma unroll
    for (int im = 0; im < 4; im++) {
        #pragma unroll
        for (int in = 0; in < 8; in++) {
            int r = row0 + wm * 64 + im * 16 + gid;
            int c = cb0 + wn * 64 + in * 8 + t4 * 2;
            #pragma unroll
            for (int half = 0; half < 2; half++) {
                int rr = r + half * 8;
                float v0 = acc[im][in][half * 2 + 0];
                float v1 = acc[im][in][half * 2 + 1];
                if (!side) { v0 = gelu_tanh(v0); v1 = gelu_tanh(v1); }
                __half2 hp; hp.x = __float2half_rn(v0); hp.y = __float2half_rn(v1);
                *reinterpret_cast<__half2*>(dst + (size_t)rr * NOUT + c) = hp;
            }
        }
    }
}

// =====================================================================
// gate_mma (unchanged from round 11)
// =====================================================================
constexpr int GG_CH   = 8192;
constexpr int GG_MAT  = 4 * GG_CH;
constexpr int GG_HDR  = 1024;
constexpr int GG_ASP  = GG_HDR + GG_MAT;
constexpr int GG_BSP  = GG_HDR + 3 * GG_MAT;
constexpr int GG_SMEM = GG_BSP + 32768;       // 132096 B

__global__ void __launch_bounds__(256, 1)
gate_mma(const __grid_constant__ CUtensorMap mXh,
         const __grid_constant__ CUtensorMap mWaH,
         const __grid_constant__ CUtensorMap mWiH,
         const float* __restrict__ ab, const float* __restrict__ ib,
         const float* __restrict__ apar,
         __half* __restrict__ omah, __half* __restrict__ gbh,
         float* __restrict__ hend, float* __restrict__ aend)
{
    using namespace hk;
    extern __shared__ __align__(1024) char smem[];
    const uint32_t sb    = s2u(smem);
    const uint32_t tiles = sb + GG_HDR;

    const int tid  = threadIdx.x;
    const int lane = tid & 31;
    const int wid  = tid >> 5;
    const int wm   = wid >> 2;
    const int wn   = wid & 3;
    const int row0 = blockIdx.x * 128;
    const int h    = blockIdx.y;

    float* asp = reinterpret_cast<float*>(smem + GG_ASP);
    __half* bsp = reinterpret_cast<__half*>(smem + GG_BSP);

    if (tid == 0) mbar_init(sb, 1);
    __syncthreads();

    if (tid == 0) {
        mbar_expect_tx(sb, (uint32_t)(3 * GG_MAT));
        #pragma unroll
        for (int c = 0; c < 4; c++) {
            int kx = c * 32;
            tma2d(tiles + 0 * GG_MAT + c * GG_CH, &mXh,  h * HD + kx, row0,   sb);
            tma2d(tiles + 1 * GG_MAT + c * GG_CH, &mWaH, kx,          h * HD, sb);
            tma2d(tiles + 2 * GG_MAT + c * GG_CH, &mWiH, kx,          h * HD, sb);
        }
    }
    mbar_wait(sb, 0);
    __syncthreads();

    uint32_t arow[4], axm[4], brow[2], bxm[2];
    #pragma unroll
    for (int im = 0; im < 4; im++) {
        int r = wm * 64 + im * 16 + (lane & 15);
        arow[im] = (uint32_t)(r * 64);
        axm[im]  = (uint32_t)((r & 6) << 3);
    }
    #pragma unroll
    for (int ip = 0; ip < 2; ip++) {
        int r = wn * 32 + ip * 16 + (lane & 7) + ((lane >> 4) & 1) * 8;
        brow[ip] = (uint32_t)(r * 64);
        bxm[ip]  = (uint32_t)((r & 6) << 3);
    }
    const uint32_t acol = (uint32_t)((lane >> 4) * 16);
    const uint32_t bcol = (uint32_t)(((lane >> 3) & 1) * 16);

    float accR[4][4][4], accI[4][4][4];
    #pragma unroll
    for (int im = 0; im < 4; im++)
        #pragma unroll
        for (int in = 0; in < 4; in++)
            #pragma unroll
            for (int q = 0; q < 4; q++) { accR[im][in][q] = 0.0f; accI[im][in][q] = 0.0f; }

    #pragma unroll
    for (int c = 0; c < 4; c++) {
        const uint32_t sAh = tiles + 0 * GG_MAT + c * GG_CH;
        const uint32_t sWa = tiles + 1 * GG_MAT + c * GG_CH;
        const uint32_t sWi = tiles + 2 * GG_MAT + c * GG_CH;
        #pragma unroll
        for (int kk = 0; kk < 2; kk++) {
            uint32_t af[4][4], wa[4][2], wi[4][2];
            #pragma unroll
            for (int im = 0; im < 4; im++) {
                uint32_t rest = (acol + (uint32_t)(kk * 32)) ^ axm[im];
                ldmx4(af[im], sAh + arow[im] + rest);
            }
            #pragma unroll
            for (int ip = 0; ip < 2; ip++) {
                uint32_t rest = (bcol + (uint32_t)(kk * 32)) ^ bxm[ip];
                uint32_t r4[4];
                ldmx4(r4, sWa + brow[ip] + rest);
                wa[2*ip][0]=r4[0]; wa[2*ip][1]=r4[1]; wa[2*ip+1][0]=r4[2]; wa[2*ip+1][1]=r4[3];
                ldmx4(r4, sWi + brow[ip] + rest);
                wi[2*ip][0]=r4[0]; wi[2*ip][1]=r4[1]; wi[2*ip+1][0]=r4[2]; wi[2*ip+1][1]=r4[3];
            }
            #pragma unroll
            for (int im = 0; im < 4; im++)
                #pragma unroll
                for (int in = 0; in < 4; in++) {
                    mma16816(accR[im][in], af[im], wa[in]);
                    mma16816(accI[im][in], af[im], wi[in]);
                }
        }
    }
    __syncthreads();

    const int gid = lane >> 2, t4 = lane & 3;
    #pragma unroll
    for (int in = 0; in < 4; in++) {
        int c0 = wn * 32 + in * 8 + t4 * 2;
        #pragma unroll
        for (int q = 0; q < 2; q++) {
            int col = c0 + q;
            int dd  = h * HD + col;
            float ab_ = ab[dd], ib_ = ib[dd];
            float sp  = log1pf(expf(-apar[dd]));
            int cch = col >> 5;
            uint32_t cb = (uint32_t)((col & 31) * 2);
            uint32_t cbase = (uint32_t)(cch * GG_CH);
            #pragma unroll
            for (int im = 0; im < 4; im++) {
                #pragma unroll
                for (int half = 0; half < 2; half++) {
                    int row = wm * 64 + im * 16 + gid + half * 8;
                    float rv = accR[im][in][half * 2 + q] + ab_;
                    float iv = accI[im][in][half * 2 + q] + ib_;
                    float r  = 1.0f / (1.0f + expf(-rv));
                    float ii = 1.0f / (1.0f + expf(-iv));
                    float la = -8.0f * r * sp;
                    float a  = expf(la);
                    __half omh = __float2half_rn(1.0f - a);
                    float aq = 1.0f - __half2float(omh);
                    float mult = sqrtf(fmaxf(1.0f - expf(2.0f * la), 0.0f));
                    uint32_t off = cbase + (uint32_t)(row * 64)
                                 + ((cb & 48u) ^ (uint32_t)((row & 6) << 3)) + (cb & 15u);
                    float xcv = __half2float(*reinterpret_cast<const __half*>(
                                    smem + GG_HDR + off));
                    __half bh = __float2half_rn(mult * ii * xcv);
                    size_t g = (size_t)(row0 + row) * D + dd;
                    omah[g] = omh;
                    gbh[g]  = bh;
                    int sidx = row * 128 + (col ^ (row & 31));
                    asp[sidx] = aq;
                    bsp[sidx] = bh;
                }
            }
        }
    }
    __syncthreads();

    if (tid < 128) {
        int col = tid;
        float hh = 0.0f, A = 1.0f;
        #pragma unroll 4
        for (int row = 0; row < 128; row++) {
            int sidx = row * 128 + (col ^ (row & 31));
            float a = asp[sidx];
            hh = fmaf(a, hh, __half2float(bsp[sidx]));
            A *= a;
        }
        int bb = row0 / S;
        int cc = (row0 % S) / SC_L;
        size_t o = ((size_t)bb * SC_NC + cc) * D + (size_t)h * HD + col;
        hend[o] = hh;
        aend[o] = A;
    }
}

// =====================================================================
// combined weight transpose/convert (Wy,Wx -> concatenated Wyx)
// =====================================================================
__global__ void __launch_bounds__(256)
trans_all(const float* __restrict__ W0, __half* __restrict__ T0,
          const float* __restrict__ W1, __half* __restrict__ T1,
          const float* __restrict__ W2, __half* __restrict__ T2,
          const float* __restrict__ W3, __half* __restrict__ T3,
          const float* __restrict__ W4, __half* __restrict__ T4,
          const float* __restrict__ W5, __half* __restrict__ T5)
{
    using namespace hk;
    __shared__ float t[64][65];
    int b = blockIdx.x;
    const float* W; __half* Wt; int K, N, lb;
    if      (b < 1024)  { W = W0; Wt = T0; K = D; N = D; lb = b; }
    else if (b < 2048)  { W = W1; Wt = T1; K = D; N = D; lb = b - 1024; }
    else if (b < 3072)  { W = W2; Wt = T2; K = D; N = D; lb = b - 2048; }
    else if (b < 7168)  { W = W3; Wt = T3; K = D; N = F; lb = b - 3072; }
    else if (b < 11264) { W = W4; Wt = T4; K = D; N = F; lb = b - 7168; }
    else                { W = W5; Wt = T5; K = F; N = D; lb = b - 11264; }
    int nbx = N >> 6;
    int n0 = (lb % nbx) * 64, k0 = (lb / nbx) * 64;

    int tid = threadIdx.x;
    int lr = tid >> 4;
    int lc = (tid & 15) * 4;
    #pragma unroll
    for (int i = 0; i < 4; i++) {
        int r = lr + i * 16;
        float4 v = *reinterpret_cast<const float4*>(&W[(size_t)(k0 + r) * N + n0 + lc]);
        t[r][lc] = v.x; t[r][lc + 1] = v.y; t[r][lc + 2] = v.z; t[r][lc + 3] = v.w;
    }
    __syncthreads();
    #pragma unroll
    for (int i = 0; i < 2; i++) {
        int task = tid + i * 256;
        int n  = task >> 3;
        int kg = (task & 7) * 8;
        __half h8[8];
        #pragma unroll
        for (int j = 0; j < 8; j++) h8[j] = __float2half_rn(t[kg + j][n]);
        *reinterpret_cast<uint4*>(&Wt[(size_t)(n0 + n) * K + k0 + kg]) =
            *reinterpret_cast<uint4*>(h8);
    }
}

// gate-weight transpose: both weights in one launch (z in [0, 2H))
__global__ void trans_gate2(const float* __restrict__ Wa, __half* __restrict__ Ta,
                            const float* __restrict__ Wi, __half* __restrict__ Ti)
{
    using namespace hk;
    __shared__ float t[32][33];
    int e0 = blockIdx.x * 32, d0 = blockIdx.y * 32;
    int z = blockIdx.z;
    int hh = z & (H - 1);
    const float* W = (z < H) ? Wa : Wi;
    __half* T = (z < H) ? Ta : Ti;
    int tx = threadIdx.x, ty = threadIdx.y;
    const float* Wh = W + (size_t)hh * HD * HD;
    #pragma unroll
    for (int i = 0; i < 32; i += 8)
        t[ty + i][tx] = Wh[(size_t)(d0 + ty + i) * HD + (e0 + tx)];
    __syncthreads();
    #pragma unroll
    for (int i = 0; i < 32; i += 8) {
        size_t o = ((size_t)hh * HD + (e0 + ty + i)) * HD + (d0 + tx);
        T[o] = __float2half_rn(t[tx][ty + i]);
    }
}

// ---------------- vectorized rmsnorm: float4 in, uint4 fp16 out ----------------
__global__ void __launch_bounds__(256)
rmsnorm_v(const float* __restrict__ x, const float* __restrict__ w,
          __half* __restrict__ o)
{
    using namespace hk;
    const int row = blockIdx.x;
    const int tid = threadIdx.x;
    const float4* xr = reinterpret_cast<const float4*>(x + (size_t)row * D);
    float4 v0 = xr[tid * 2];
    float4 v1 = xr[tid * 2 + 1];
    float ss = v0.x*v0.x + v0.y*v0.y + v0.z*v0.z + v0.w*v0.w
             + v1.x*v1.x + v1.y*v1.y + v1.z*v1.z + v1.w*v1.w;
    __shared__ float red[8];
    #pragma unroll
    for (int off = 16; off > 0; off >>= 1) ss += __shfl_down_sync(0xffffffffu, ss, off);
    if ((tid & 31) == 0) red[tid >> 5] = ss;
    __syncthreads();
    if (tid < 8) {
        float v = red[tid];
        #pragma unroll
        for (int off = 4; off > 0; off >>= 1) v += __shfl_down_sync(0xffu, v, off);
        if (tid == 0) red[0] = v;
    }
    __syncthreads();
    const float scale = rsqrtf(red[0] / (float)D + 1e-6f);
    const float4* wr = reinterpret_cast<const float4*>(w);
    float4 w0 = wr[tid * 2];
    float4 w1 = wr[tid * 2 + 1];
    __half h8[8];
    h8[0] = __float2half_rn(v0.x * scale * w0.x);
    h8[1] = __float2half_rn(v0.y * scale * w0.y);
    h8[2] = __float2half_rn(v0.z * scale * w0.z);
    h8[3] = __float2half_rn(v0.w * scale * w0.w);
    h8[4] = __float2half_rn(v1.x * scale * w1.x);
    h8[5] = __float2half_rn(v1.y * scale * w1.y);
    h8[6] = __float2half_rn(v1.z * scale * w1.z);
    h8[7] = __float2half_rn(v1.w * scale * w1.w);
    *reinterpret_cast<uint4*>(o + (size_t)row * D + tid * 8) =
        *reinterpret_cast<uint4*>(h8);
}

// ---------------- vectorized causal conv: 8 channels per thread ----------------
__global__ void __launch_bounds__(256)
conv_v(const __half* __restrict__ xbh, const float* __restrict__ cw,
       const float* __restrict__ cb, __half* __restrict__ xcH)
{
    using namespace hk;
    size_t t = (size_t)blockIdx.x * blockDim.x + threadIdx.x;
    size_t base = t * 8;
    if (base >= NBSD) return;
    int d = (int)(base % D);
    int s = (int)((base / D) % S);
    float acc[8];
    {
        float4 c0 = *reinterpret_cast<const float4*>(cb + d);
        float4 c1 = *reinterpret_cast<const float4*>(cb + d + 4);
        acc[0]=c0.x; acc[1]=c0.y; acc[2]=c0.z; acc[3]=c0.w;
        acc[4]=c1.x; acc[5]=c1.y; acc[6]=c1.z; acc[7]=c1.w;
    }
    #pragma unroll
    for (int k = 0; k < 4; k++) {
        int ss = s + k - 3;
        if (ss >= 0) {
            uint4 xv = *reinterpret_cast<const uint4*>(xbh + base + (ptrdiff_t)(k - 3) * D);
            const __half2* xp = reinterpret_cast<const __half2*>(&xv);
            float4 w0 = *reinterpret_cast<const float4*>(cw + k * D + d);
            float4 w1 = *reinterpret_cast<const float4*>(cw + k * D + d + 4);
            float2 p0 = __half22float2(xp[0]);
            float2 p1 = __half22float2(xp[1]);
            float2 p2 = __half22float2(xp[2]);
            float2 p3 = __half22float2(xp[3]);
            acc[0] = fmaf(w0.x, p0.x, acc[0]);
            acc[1] = fmaf(w0.y, p0.y, acc[1]);
            acc[2] = fmaf(w0.z, p1.x, acc[2]);
            acc[3] = fmaf(w0.w, p1.y, acc[3]);
            acc[4] = fmaf(w1.x, p2.x, acc[4]);
            acc[5] = fmaf(w1.y, p2.y, acc[5]);
            acc[6] = fmaf(w1.z, p3.x, acc[6]);
            acc[7] = fmaf(w1.w, p3.y, acc[7]);
        }
    }
    __half h8[8];
    #pragma unroll
    for (int j = 0; j < 8; j++) h8[j] = __float2half_rn(acc[j]);
    *reinterpret_cast<uint4*>(xcH + base) = *reinterpret_cast<uint4*>(h8);
}

// ---------------- scan pass2 ----------------
__global__ void scan_pass2(const float* __restrict__ hend, const float* __restrict__ aend,
                           const float* __restrict__ h0, float* __restrict__ carry,
                           float* __restrict__ hlast)
{
    using namespace hk;
    int ch = blockIdx.x * blockDim.x + threadIdx.x;
    if (ch >= B * D) return;
    int b = ch / D, d = ch % D;
    float cur = h0[ch];
    for (int c = 0; c < SC_NC; c++) {
        size_t o = ((size_t)b * SC_NC + c) * D + d;
        carry[o] = cur;
        cur = fmaf(aend[o], cur, hend[o]);
    }
    if (hlast) hlast[ch] = cur;
}

// ---------------- scan pass3 ----------------
__global__ void scan_pass3(const __half* __restrict__ omah, const __half* __restrict__ gbh,
                           const float* __restrict__ carry, const __half* __restrict__ yA,
                           __half* __restrict__ zA)
{
    using namespace hk;
    int t = blockIdx.x * blockDim.x + threadIdx.x;
    if (t >= B * SC_NC * D) return;
    int d = t % D;
    int c = (t / D) % SC_NC;
    int b = t / (D * SC_NC);
    float h = carry[((size_t)b * SC_NC + c) * D + d];
    size_t g = ((size_t)b * S + (size_t)c * SC_L) * D + d;
    for (int i = 0; i < SC_L; i++, g += D) {
        float a = 1.0f - __half2float(omah[g]);
        h = fmaf(a, h, __half2float(gbh[g]));
        zA[g] = __float2half_rn(__half2float(yA[g]) * h);
    }
}

// =====================================================================
// host-side tensormap encoding (driver symbol via dlsym)
// =====================================================================
typedef CUresult (*EncodeFn)(CUtensorMap*, CUtensorMapDataType, cuuint32_t, void*,
                             const cuuint64_t*, const cuuint64_t*, const cuuint32_t*,
                             const cuuint32_t*, CUtensorMapInterleave, CUtensorMapSwizzle,
                             CUtensorMapL2promotion, CUtensorMapFloatOOBfill);

static EncodeFn get_encode() {
    static EncodeFn fn = nullptr;
    if (!fn) {
        fn = (EncodeFn)dlsym(RTLD_DEFAULT, "cuTensorMapEncodeTiled");
        if (!fn) {
            void* h = dlopen("libcuda.so.1", RTLD_LAZY | RTLD_GLOBAL);
            if (h) fn = (EncodeFn)dlsym(h, "cuTensorMapEncodeTiled");
        }
    }
    return fn;
}

static void enc_map(CUtensorMap* m, void* ptr, uint64_t K, uint64_t ROWS, uint32_t boxRows) {
    cuuint64_t dims[2]    = {K, ROWS};
    cuuint64_t strides[1] = {K * 2};
    cuuint32_t box[2]     = {32, boxRows};
    cuuint32_t es[2]      = {1, 1};
    get_encode()(m, CU_TENSOR_MAP_DATA_TYPE_FLOAT16, 2, ptr, dims, strides, box, es,
                 CU_TENSOR_MAP_INTERLEAVE_NONE, CU_TENSOR_MAP_SWIZZLE_64B,
                 CU_TENSOR_MAP_L2_PROMOTION_L2_128B, CU_TENSOR_MAP_FLOAT_OOB_FILL_NONE);
}

// ---------------- launch ----------------
extern "C" void kernel_launch(void* const* d_in, const int* in_sizes, int n_in,
                              void* d_out, int out_size)
{
    using namespace hk;
    const float* x    = (const float*)d_in[0];
    const float* h0   = (const float*)d_in[1];
    const float* r1w  = (const float*)d_in[2];
    const float* r2w  = (const float*)d_in[3];
    const float* Wx   = (const float*)d_in[4];
    const float* Wy   = (const float*)d_in[5];
    const float* cw   = (const float*)d_in[6];
    const float* cb   = (const float*)d_in[7];
    const float* apar = (const float*)d_in[8];
    const float* igw  = (const float*)d_in[9];
    const float* igb  = (const float*)d_in[10];
    const float* agw  = (const float*)d_in[11];
    const float* agb  = (const float*)d_in[12];
    const float* Wout = (const float*)d_in[13];
    const float* Wg   = (const float*)d_in[14];
    const float* Wu   = (const float*)d_in[15];
    const float* Wd   = (const float*)d_in[16];
    float* out = (float*)d_out;

    float *resid, *hend, *aend, *carry;
    cudaGetSymbolAddress((void**)&resid, g_resid);
    cudaGetSymbolAddress((void**)&hend,  g_hend);
    cudaGetSymbolAddress((void**)&aend,  g_aend);
    cudaGetSymbolAddress((void**)&carry, g_carry);

    __half *omah,*gbh,*nA,*yA,*xbh,*xcH,*zA,*n2A,*GA,*guA;
    __half *tWyx,*tWo,*tWg,*tWu,*tWd,*aWH,*iWH;
    cudaGetSymbolAddress((void**)&omah, g_omah);
    cudaGetSymbolAddress((void**)&gbh, g_gbh);
    cudaGetSymbolAddress((void**)&nA,  g_nA);
    cudaGetSymbolAddress((void**)&yA,  g_yA);
    cudaGetSymbolAddress((void**)&xbh, g_xbh);
    cudaGetSymbolAddress((void**)&xcH, g_xcH);
    cudaGetSymbolAddress((void**)&zA,  g_zA);
    cudaGetSymbolAddress((void**)&n2A, g_n2A);
    cudaGetSymbolAddress((void**)&GA,  g_GA);
    cudaGetSymbolAddress((void**)&guA, g_guA);
    cudaGetSymbolAddress((void**)&tWyx, g_Wyx);
    cudaGetSymbolAddress((void**)&tWo, g_Wo);  cudaGetSymbolAddress((void**)&tWg, g_Wg);
    cudaGetSymbolAddress((void**)&tWu, g_Wu);  cudaGetSymbolAddress((void**)&tWd, g_Wd);
    cudaGetSymbolAddress((void**)&aWH, g_aWH); cudaGetSymbolAddress((void**)&iWH, g_iWH);

    // ---- tensormaps ----
    static CUtensorMap mnA, mzA, mn2A, mguA;
    static CUtensorMap mWyx, mWo, mWg, mWu, mWd;
    static CUtensorMap mXh, mWaH, mWiH;
    enc_map(&mnA,  nA,  D, BS, 128);
    enc_map(&mzA,  zA,  D, BS, 128);
    enc_map(&mn2A, n2A, D, BS, 128);
    enc_map(&mguA, guA, F, BS, 128);
    enc_map(&mWyx, tWyx, D, 2 * (uint64_t)D, 256);
    enc_map(&mWo,  tWo, D, D, 256);   enc_map(&mWg,  tWg, D, F, 256);
    enc_map(&mWu,  tWu, D, F, 256);   enc_map(&mWd,  tWd, F, D, 256);
    enc_map(&mXh,  xcH, D, BS, 128);
    enc_map(&mWaH, aWH, HD, (uint64_t)H * HD, 128);
    enc_map(&mWiH, iWH, HD, (uint64_t)H * HD, 128);

    cudaFuncSetAttribute(gemm_tma<2>, cudaFuncAttributeMaxDynamicSharedMemorySize, GT_SMEM);
    cudaFuncSetAttribute(gemm_tma<3>, cudaFuncAttributeMaxDynamicSharedMemorySize, GT_SMEM);
    cudaFuncSetAttribute(gemm_tma<4>, cudaFuncAttributeMaxDynamicSharedMemorySize, GT_SMEM);
    cudaFuncSetAttribute(gemm_dual,   cudaFuncAttributeMaxDynamicSharedMemorySize, GT_SMEM);
    cudaFuncSetAttribute(gate_mma,    cudaFuncAttributeMaxDynamicSharedMemorySize, GG_SMEM);

    float* hlast = (out_size >= (int)(NBSD + (size_t)B * D)) ? (out + NBSD) : nullptr;

    // ---- weight transpose/convert ----
    trans_all<<<15360, 256>>>(Wy, tWyx, Wx, tWyx + NDD, Wout, tWo,
                              Wg, tWg, Wu, tWu, Wd, tWd);
    trans_gate2<<<dim3(HD / 32, HD / 32, 2 * H), dim3(32, 8)>>>(agw, aWH, igw, iWH);

    // ---- temporal pre-norm (vectorized) ----
    rmsnorm_v<<<BS, 256>>>(x, r1w, nA);

    // ---- combined: y = gelu(nA @ Wy) fp16 AND xb = nA @ Wx fp16, one launch ----
    dim3 gDual(2 * D / 256, BS / 128);
    gemm_dual<<<gDual, 256, GT_SMEM>>>(mnA, mWyx, yA, xbh, D, D);

    // ---- causal conv (vectorized) ----
    conv_v<<<(unsigned)(NBSD / 8 / 256), 256>>>(xbh, cw, cb, xcH);

    // ---- fused gate GEMM + gate math + chunk-end scan ----
    gate_mma<<<dim3(BS / 128, H), 256, GG_SMEM>>>(mXh, mWaH, mWiH,
                                                  agb, igb, apar, omah, gbh, hend, aend);

    // ---- carries + final rescan fused with y-mul ----
    scan_pass2<<<(B * D + 255) / 256, 256>>>(hend, aend, h0, carry, hlast);
    scan_pass3<<<(B * SC_NC * D + 255) / 256, 256>>>(omah, gbh, carry, yA, zA);

    // ---- residual = z @ W_out + x ----
    dim3 gDD(D / 256, BS / 128);
    gemm_tma<2><<<gDD, 256, GT_SMEM>>>(mzA, mWo, resid, x, nullptr, nullptr, D, D);

    // ---- second norm (vectorized) ----
    rmsnorm_v<<<BS, 256>>>(resid, r2w, n2A);

    // ---- MLP: G = gelu(n2 @ Wg) fp16; gu = (n2 @ Wu) * G fp16 ----
    dim3 gDF(F / 256, BS / 128);
    gemm_tma<4><<<gDF, 256, GT_SMEM>>>(mn2A, mWg, nullptr, nullptr, nullptr, GA, F, D);
    gemm_tma<3><<<gDF, 256, GT_SMEM>>>(mn2A, mWu, nullptr, nullptr, GA, guA, F, D);

    // ---- out = gu @ W_down + residual ----
    gemm_tma<2><<<gDD, 256, GT_SMEM>>>(mguA, mWd, out, resid, nullptr, nullptr, D, F);
}